// round 3
// baseline (speedup 1.0000x reference)
#include <cuda_runtime.h>
#include <math.h>

// Problem constants: L=1024, N=4, E=1024, F=4096, H=16, d=64
#define LL 1024
#define NN 4
#define EE 1024
#define FF 4096
#define HH 16
#define HD 64
#define MM (LL*NN)   // 4096 rows

// ---------------- scratch (static device allocations) ----------------
__device__ float g_h[MM*EE];     // layernorm output
__device__ float g_q[MM*EE];
__device__ float g_k[MM*EE];
__device__ float g_v[MM*EE];
__device__ float g_attn[MM*EE];
__device__ float g_ff[MM*FF];

// ---------------- layernorm: one block per row, E=1024 ----------------
__global__ void ln_kernel(const float* __restrict__ x, const float* __restrict__ g,
                          const float* __restrict__ b, float* __restrict__ y) {
    int row = blockIdx.x;
    int tid = threadIdx.x;               // 256 threads
    const float4* xr = (const float4*)(x + (size_t)row * EE);
    float4 v = xr[tid];
    float s  = v.x + v.y + v.z + v.w;
    float sq = v.x*v.x + v.y*v.y + v.z*v.z + v.w*v.w;
    #pragma unroll
    for (int off = 16; off > 0; off >>= 1) {
        s  += __shfl_down_sync(0xffffffffu, s,  off);
        sq += __shfl_down_sync(0xffffffffu, sq, off);
    }
    __shared__ float rs[8], rq[8];
    __shared__ float s_mean, s_rstd;
    int lane = tid & 31, wid = tid >> 5;
    if (lane == 0) { rs[wid] = s; rq[wid] = sq; }
    __syncthreads();
    if (tid == 0) {
        float ts = 0.f, tq = 0.f;
        #pragma unroll
        for (int i = 0; i < 8; i++) { ts += rs[i]; tq += rq[i]; }
        float mean = ts * (1.0f / EE);
        float var  = tq * (1.0f / EE) - mean * mean;
        s_mean = mean;
        s_rstd = rsqrtf(var + 1e-5f);
    }
    __syncthreads();
    float mean = s_mean, rstd = s_rstd;
    const float4* gr = (const float4*)g;
    const float4* br = (const float4*)b;
    float4 gv = gr[tid], bv = br[tid];
    float4 o;
    o.x = (v.x - mean) * rstd * gv.x + bv.x;
    o.y = (v.y - mean) * rstd * gv.y + bv.y;
    o.z = (v.z - mean) * rstd * gv.z + bv.z;
    o.w = (v.w - mean) * rstd * gv.w + bv.w;
    ((float4*)(y + (size_t)row * EE))[tid] = o;
}

// ---------------- SGEMM: C = A(MxK) @ W(NxK)^T + bias [+epilogue] -------
// EPI: 0 = bias only, 1 = bias + residual, 2 = bias + gelu(erf)
#define BM 128
#define BN 128
#define BK 8

template<int EPI>
__global__ void __launch_bounds__(256, 2)
sgemm_kernel(const float* __restrict__ A, const float* __restrict__ W,
             const float* __restrict__ bias, const float* __restrict__ R,
             float* __restrict__ C, int M, int N, int K) {
    __shared__ float As[2][BK][BM];
    __shared__ float Bs[2][BK][BN];
    int tid = threadIdx.x;
    int bm = blockIdx.y * BM;
    int bn = blockIdx.x * BN;

    int lrow = tid >> 1;               // 0..127
    int lcol = (tid & 1) << 2;         // 0 or 4
    const float* Aptr = A + (size_t)(bm + lrow) * K + lcol;
    const float* Wptr = W + (size_t)(bn + lrow) * K + lcol;

    int tx = tid & 15, ty = tid >> 4;  // 16x16 threads, 8x8 each

    float acc[8][8];
    #pragma unroll
    for (int i = 0; i < 8; i++)
        #pragma unroll
        for (int j = 0; j < 8; j++) acc[i][j] = 0.f;

    float4 ar = *(const float4*)Aptr;
    float4 br = *(const float4*)Wptr;
    As[0][lcol+0][lrow] = ar.x; As[0][lcol+1][lrow] = ar.y;
    As[0][lcol+2][lrow] = ar.z; As[0][lcol+3][lrow] = ar.w;
    Bs[0][lcol+0][lrow] = br.x; Bs[0][lcol+1][lrow] = br.y;
    Bs[0][lcol+2][lrow] = br.z; Bs[0][lcol+3][lrow] = br.w;
    __syncthreads();

    int nk = K / BK;
    int buf = 0;
    for (int kt = 0; kt < nk; kt++) {
        if (kt + 1 < nk) {
            ar = *(const float4*)(Aptr + (size_t)(kt + 1) * BK);
            br = *(const float4*)(Wptr + (size_t)(kt + 1) * BK);
        }
        #pragma unroll
        for (int kk = 0; kk < BK; kk++) {
            float a[8], b[8];
            *(float4*)&a[0] = *(const float4*)&As[buf][kk][ty*8];
            *(float4*)&a[4] = *(const float4*)&As[buf][kk][ty*8+4];
            *(float4*)&b[0] = *(const float4*)&Bs[buf][kk][tx*8];
            *(float4*)&b[4] = *(const float4*)&Bs[buf][kk][tx*8+4];
            #pragma unroll
            for (int i = 0; i < 8; i++)
                #pragma unroll
                for (int j = 0; j < 8; j++)
                    acc[i][j] += a[i] * b[j];
        }
        if (kt + 1 < nk) {
            As[buf^1][lcol+0][lrow] = ar.x; As[buf^1][lcol+1][lrow] = ar.y;
            As[buf^1][lcol+2][lrow] = ar.z; As[buf^1][lcol+3][lrow] = ar.w;
            Bs[buf^1][lcol+0][lrow] = br.x; Bs[buf^1][lcol+1][lrow] = br.y;
            Bs[buf^1][lcol+2][lrow] = br.z; Bs[buf^1][lcol+3][lrow] = br.w;
        }
        __syncthreads();
        buf ^= 1;
    }

    #pragma unroll
    for (int i = 0; i < 8; i++) {
        int row = bm + ty*8 + i;
        #pragma unroll
        for (int j = 0; j < 8; j++) {
            int col = bn + tx*8 + j;
            float c = acc[i][j] + bias[col];
            if (EPI == 1) c += R[(size_t)row * N + col];
            if (EPI == 2) c = 0.5f * c * (1.0f + erff(c * 0.70710678118654752f));
            C[(size_t)row * N + col] = c;
        }
    }
}

// ---------------- flash attention (static smem <= 48KB) ----------------
// NOTE: the reference applies the causal mask in BOTH self- and cross-attention
// (its _attn() always applies tril), so 'causal' is always 1 here.
// Q tile: 32 rows; KV tile: 64 rows; d = 64. 256 threads.
// Smem: Qs 32x64 (8KB) + Kt 64x68 (17KB, P-tile overlaid after S) + Vs 64x64 (16KB)
#define ABM 32
#define KP 68

__global__ void __launch_bounds__(256)
attn_kernel(const float* __restrict__ Q, const float* __restrict__ Kp,
            const float* __restrict__ Vp, float* __restrict__ O, int causal) {
    __shared__ float Qs[ABM * 64];
    __shared__ float Kt[64 * KP];      // K^T during S; P-tile (Ss) during PV
    __shared__ float Vs[64 * 64];

    int b  = blockIdx.y;               // 0..63 (batch-head), b = n*16 + hh
    int qi = blockIdx.x;               // 0..31 (q tile of 32 rows)
    int n  = b >> 4, hh = b & 15;
    int tid = threadIdx.x;
    int rg = tid >> 4, cg = tid & 15;  // 16 row-groups x 16 col-groups
    int r0 = rg * 2, c0 = cg * 4;
    int qbase = qi * ABM;

    // load Q tile (32 x 64)
    for (int i = tid; i < ABM * 16; i += 256) {
        int rr = i >> 4, seg = (i & 15) * 4;
        *(float4*)&Qs[rr*64 + seg] =
            *(const float4*)(Q + (size_t)(((qbase + rr)*NN + n) << 10) + hh*HD + seg);
    }

    float m[2], l[2], o[2][4];
    #pragma unroll
    for (int i = 0; i < 2; i++) {
        m[i] = -1e30f; l[i] = 0.f;
        #pragma unroll
        for (int j = 0; j < 4; j++) o[i][j] = 0.f;
    }

    int jmax = causal ? ((qbase + ABM - 1) >> 6) : (LL/64 - 1);
    for (int j = 0; j <= jmax; j++) {
        __syncthreads();   // previous tile's PV done with Kt(=Ss)/Vs
        for (int i = tid; i < 64 * 16; i += 256) {
            int rr = i >> 4, seg = (i & 15) * 4;
            size_t base = (size_t)(((j*64 + rr)*NN + n) << 10) + hh*HD;
            float4 kv = *(const float4*)(Kp + base + seg);
            Kt[(seg+0)*KP + rr] = kv.x;
            Kt[(seg+1)*KP + rr] = kv.y;
            Kt[(seg+2)*KP + rr] = kv.z;
            Kt[(seg+3)*KP + rr] = kv.w;
            *(float4*)&Vs[rr*64 + seg] = *(const float4*)(Vp + base + seg);
        }
        __syncthreads();

        // S = Q K^T (2 rows x 4 cols per thread)
        float s[2][4];
        #pragma unroll
        for (int i = 0; i < 2; i++)
            #pragma unroll
            for (int jj = 0; jj < 4; jj++) s[i][jj] = 0.f;

        for (int d4 = 0; d4 < 64; d4 += 4) {
            float qv[8], kv[16];
            *(float4*)&qv[0] = *(const float4*)&Qs[(r0+0)*64 + d4];
            *(float4*)&qv[4] = *(const float4*)&Qs[(r0+1)*64 + d4];
            #pragma unroll
            for (int t = 0; t < 4; t++)
                *(float4*)&kv[t*4] = *(const float4*)&Kt[(d4+t)*KP + c0];
            #pragma unroll
            for (int i = 0; i < 2; i++)
                #pragma unroll
                for (int t = 0; t < 4; t++) {
                    float qq = qv[i*4 + t];
                    s[i][0] += qq * kv[t*4+0];
                    s[i][1] += qq * kv[t*4+1];
                    s[i][2] += qq * kv[t*4+2];
                    s[i][3] += qq * kv[t*4+3];
                }
        }
        const float scale = 0.125f;  // 64^-0.5
        #pragma unroll
        for (int i = 0; i < 2; i++)
            #pragma unroll
            for (int jj = 0; jj < 4; jj++) s[i][jj] *= scale;

        if (causal && j == jmax) {
            #pragma unroll
            for (int i = 0; i < 2; i++)
                #pragma unroll
                for (int jj = 0; jj < 4; jj++)
                    if (j*64 + c0 + jj > qbase + r0 + i) s[i][jj] = -10000.0f;
        }

        __syncthreads();   // all Kt reads complete before P-tile overlays it

        // online softmax; write P into Kt (Ss overlay)
        #pragma unroll
        for (int i = 0; i < 2; i++) {
            float mx = fmaxf(fmaxf(s[i][0], s[i][1]), fmaxf(s[i][2], s[i][3]));
            #pragma unroll
            for (int off = 8; off > 0; off >>= 1)
                mx = fmaxf(mx, __shfl_xor_sync(0xffffffffu, mx, off, 16));
            float mn = fmaxf(m[i], mx);
            float alpha = __expf(m[i] - mn);
            float ls = 0.f;
            #pragma unroll
            for (int jj = 0; jj < 4; jj++) {
                float p = __expf(s[i][jj] - mn);
                s[i][jj] = p;
                ls += p;
            }
            #pragma unroll
            for (int off = 8; off > 0; off >>= 1)
                ls += __shfl_xor_sync(0xffffffffu, ls, off, 16);
            l[i] = l[i] * alpha + ls;
            m[i] = mn;
            #pragma unroll
            for (int jj = 0; jj < 4; jj++) o[i][jj] *= alpha;
            *(float4*)&Kt[(r0+i)*KP + c0] = make_float4(s[i][0], s[i][1], s[i][2], s[i][3]);
        }
        __syncthreads();

        // O += P V
        for (int c4 = 0; c4 < 64; c4 += 4) {
            float pv[8], vv[16];
            *(float4*)&pv[0] = *(const float4*)&Kt[(r0+0)*KP + c4];
            *(float4*)&pv[4] = *(const float4*)&Kt[(r0+1)*KP + c4];
            #pragma unroll
            for (int t = 0; t < 4; t++)
                *(float4*)&vv[t*4] = *(const float4*)&Vs[(c4+t)*64 + c0];
            #pragma unroll
            for (int i = 0; i < 2; i++)
                #pragma unroll
                for (int t = 0; t < 4; t++) {
                    float pp = pv[i*4 + t];
                    o[i][0] += pp * vv[t*4+0];
                    o[i][1] += pp * vv[t*4+1];
                    o[i][2] += pp * vv[t*4+2];
                    o[i][3] += pp * vv[t*4+3];
                }
        }
    }

    // write normalized output
    #pragma unroll
    for (int i = 0; i < 2; i++) {
        float inv = 1.0f / l[i];
        int row = qbase + r0 + i;
        float4 ov = make_float4(o[i][0]*inv, o[i][1]*inv, o[i][2]*inv, o[i][3]*inv);
        *(float4*)(O + (size_t)((row*NN + n) << 10) + hh*HD + c0) = ov;
    }
}

// ---------------- orchestration ----------------
static void run_gemm(int epi, const float* A, const float* W, const float* bias,
                     const float* R, float* C, int M, int N, int K) {
    dim3 grid(N / BN, M / BM);
    if (epi == 0)      sgemm_kernel<0><<<grid, 256>>>(A, W, bias, R, C, M, N, K);
    else if (epi == 1) sgemm_kernel<1><<<grid, 256>>>(A, W, bias, R, C, M, N, K);
    else               sgemm_kernel<2><<<grid, 256>>>(A, W, bias, R, C, M, N, K);
}

extern "C" void kernel_launch(void* const* d_in, const int* in_sizes, int n_in,
                              void* d_out, int out_size) {
    const float* x    = (const float*)d_in[0];
    const float* enc  = (const float*)d_in[1];
    const float* wq_s = (const float*)d_in[2];
    const float* bq_s = (const float*)d_in[3];
    const float* wk_s = (const float*)d_in[4];
    const float* bk_s = (const float*)d_in[5];
    const float* wv_s = (const float*)d_in[6];
    const float* bv_s = (const float*)d_in[7];
    const float* wo_s = (const float*)d_in[8];
    const float* bo_s = (const float*)d_in[9];
    const float* wq_c = (const float*)d_in[10];
    const float* bq_c = (const float*)d_in[11];
    const float* wk_c = (const float*)d_in[12];
    const float* bk_c = (const float*)d_in[13];
    const float* wv_c = (const float*)d_in[14];
    const float* bv_c = (const float*)d_in[15];
    const float* wo_c = (const float*)d_in[16];
    const float* bo_c = (const float*)d_in[17];
    const float* ln1_g = (const float*)d_in[18];
    const float* ln1_b = (const float*)d_in[19];
    const float* ln2_g = (const float*)d_in[20];
    const float* ln2_b = (const float*)d_in[21];
    const float* ln3_g = (const float*)d_in[22];
    const float* ln3_b = (const float*)d_in[23];
    const float* fc1_w = (const float*)d_in[24];
    const float* fc1_b = (const float*)d_in[25];
    const float* fc2_w = (const float*)d_in[26];
    const float* fc2_b = (const float*)d_in[27];
    float* out = (float*)d_out;

    float *p_h, *p_q, *p_k, *p_v, *p_attn, *p_ff;
    cudaGetSymbolAddress((void**)&p_h,    g_h);
    cudaGetSymbolAddress((void**)&p_q,    g_q);
    cudaGetSymbolAddress((void**)&p_k,    g_k);
    cudaGetSymbolAddress((void**)&p_v,    g_v);
    cudaGetSymbolAddress((void**)&p_attn, g_attn);
    cudaGetSymbolAddress((void**)&p_ff,   g_ff);

    dim3 agrid(LL/ABM, NN*HH);   // 32 x 64

    // ---- block 1: self-attention (causal) ----
    ln_kernel<<<MM, 256>>>(x, ln1_g, ln1_b, p_h);
    run_gemm(0, p_h, wq_s, bq_s, nullptr, p_q, MM, EE, EE);
    run_gemm(0, p_h, wk_s, bk_s, nullptr, p_k, MM, EE, EE);
    run_gemm(0, p_h, wv_s, bv_s, nullptr, p_v, MM, EE, EE);
    attn_kernel<<<agrid, 256>>>(p_q, p_k, p_v, p_attn, 1);
    run_gemm(1, p_attn, wo_s, bo_s, x, out, MM, EE, EE);

    // ---- block 2: cross-attention (reference's _attn ALWAYS applies causal mask) ----
    ln_kernel<<<MM, 256>>>(out, ln2_g, ln2_b, p_h);
    run_gemm(0, p_h, wq_c, bq_c, nullptr, p_q, MM, EE, EE);
    run_gemm(0, enc, wk_c, bk_c, nullptr, p_k, MM, EE, EE);
    run_gemm(0, enc, wv_c, bv_c, nullptr, p_v, MM, EE, EE);
    attn_kernel<<<agrid, 256>>>(p_q, p_k, p_v, p_attn, 1);
    run_gemm(1, p_attn, wo_c, bo_c, out, out, MM, EE, EE);

    // ---- block 3: FFN ----
    ln_kernel<<<MM, 256>>>(out, ln3_g, ln3_b, p_h);
    run_gemm(2, p_h, fc1_w, fc1_b, nullptr, p_ff, MM, FF, EE);
    run_gemm(1, p_ff, fc2_w, fc2_b, out, out, MM, EE, FF);
}

// round 5
// speedup vs baseline: 1.9695x; 1.9695x over previous
#include <cuda_runtime.h>
#include <cuda_bf16.h>
#include <math.h>
#include <stdint.h>

// Problem constants: L=1024, N=4, E=1024, F=4096, H=16, d=64
#define LL 1024
#define NN 4
#define EE 1024
#define FF 4096
#define HH 16
#define HD 64
#define MM (LL*NN)   // 4096 rows

// ---------------- scratch (static device allocations) ----------------
__device__ float g_h[MM*EE];
__device__ float g_q[MM*EE];
__device__ float g_k[MM*EE];
__device__ float g_v[MM*EE];
__device__ float g_attn[MM*EE];
__device__ float g_ff[(size_t)MM*FF];
__device__ __nv_bfloat16 g_a3[(size_t)MM * 3 * FF];   // split-A, up to 4096 x 12288
__device__ __nv_bfloat16 g_w3[(size_t)FF * 3 * EE];   // split-W, up to 4096 x 3072 / 1024 x 12288

// ---------------- portable PTX helpers (no sm_103a-only features) -------
__device__ __forceinline__ uint32_t smem_u32(const void* p) {
    uint32_t a;
    asm("{ .reg .u64 t; cvta.to.shared.u64 t, %1; cvt.u32.u64 %0, t; }" : "=r"(a) : "l"(p));
    return a;
}

#define SWZ(x) ((x) ^ (((x) >> 3) & 0x70))

#define CP_ASYNC16(dst_u32, src_ptr) \
    asm volatile("cp.async.cg.shared.global [%0], [%1], 16;" \
        :: "r"(dst_u32), "l"(src_ptr) : "memory")
#define CP_COMMIT() asm volatile("cp.async.commit_group;" ::: "memory")
#define CP_WAIT1()  asm volatile("cp.async.wait_group 1;" ::: "memory")
#define CP_WAIT0()  asm volatile("cp.async.wait_group 0;" ::: "memory")

__device__ __forceinline__ void ldsm_x4(uint32_t& r0, uint32_t& r1, uint32_t& r2, uint32_t& r3,
                                        uint32_t addr) {
    asm volatile("ldmatrix.sync.aligned.m8n8.x4.shared.b16 {%0,%1,%2,%3}, [%4];"
        : "=r"(r0), "=r"(r1), "=r"(r2), "=r"(r3) : "r"(addr));
}
__device__ __forceinline__ void ldsm_x2(uint32_t& r0, uint32_t& r1, uint32_t addr) {
    asm volatile("ldmatrix.sync.aligned.m8n8.x2.shared.b16 {%0,%1}, [%2];"
        : "=r"(r0), "=r"(r1) : "r"(addr));
}
__device__ __forceinline__ void mma_bf16(float* d, const uint32_t* a, const uint32_t* b) {
    asm volatile("mma.sync.aligned.m16n8k16.row.col.f32.bf16.bf16.f32 "
        "{%0,%1,%2,%3}, {%4,%5,%6,%7}, {%8,%9}, {%0,%1,%2,%3};"
        : "+f"(d[0]), "+f"(d[1]), "+f"(d[2]), "+f"(d[3])
        : "r"(a[0]), "r"(a[1]), "r"(a[2]), "r"(a[3]), "r"(b[0]), "r"(b[1]));
}

// ---------------- layernorm: one block per row, E=1024 ----------------
__global__ void ln_kernel(const float* __restrict__ x, const float* __restrict__ g,
                          const float* __restrict__ b, float* __restrict__ y) {
    int row = blockIdx.x;
    int tid = threadIdx.x;               // 256 threads
    const float4* xr = (const float4*)(x + (size_t)row * EE);
    float4 v = xr[tid];
    float s  = v.x + v.y + v.z + v.w;
    float sq = v.x*v.x + v.y*v.y + v.z*v.z + v.w*v.w;
    #pragma unroll
    for (int off = 16; off > 0; off >>= 1) {
        s  += __shfl_down_sync(0xffffffffu, s,  off);
        sq += __shfl_down_sync(0xffffffffu, sq, off);
    }
    __shared__ float rs[8], rq[8];
    __shared__ float s_mean, s_rstd;
    int lane = tid & 31, wid = tid >> 5;
    if (lane == 0) { rs[wid] = s; rq[wid] = sq; }
    __syncthreads();
    if (tid == 0) {
        float ts = 0.f, tq = 0.f;
        #pragma unroll
        for (int i = 0; i < 8; i++) { ts += rs[i]; tq += rq[i]; }
        float mean = ts * (1.0f / EE);
        float var  = tq * (1.0f / EE) - mean * mean;
        s_mean = mean;
        s_rstd = rsqrtf(var + 1e-5f);
    }
    __syncthreads();
    float mean = s_mean, rstd = s_rstd;
    const float4* gr = (const float4*)g;
    const float4* br = (const float4*)b;
    float4 gv = gr[tid], bv = br[tid];
    float4 o;
    o.x = (v.x - mean) * rstd * gv.x + bv.x;
    o.y = (v.y - mean) * rstd * gv.y + bv.y;
    o.z = (v.z - mean) * rstd * gv.z + bv.z;
    o.w = (v.w - mean) * rstd * gv.w + bv.w;
    ((float4*)(y + (size_t)row * EE))[tid] = o;
}

// ---------------- fp32 -> 3-segment bf16 split ----------------
// border=0 (A):  segs [hi, lo, hi];  border=1 (W): segs [hi, hi, lo]
// => dot over 3K gives hi*hi + lo*hi + hi*lo  (lo*lo ~ 2^-18 dropped)
__global__ void split3_kernel(const float* __restrict__ X, __nv_bfloat16* __restrict__ Y,
                              int K, int total4, int border) {
    int idx = blockIdx.x * blockDim.x + threadIdx.x;
    if (idx >= total4) return;
    int kq = K >> 2;
    int r  = idx / kq;
    int k  = (idx - r * kq) << 2;
    float4 v = *(const float4*)(X + (size_t)r * K + k);
    float f[4] = {v.x, v.y, v.z, v.w};
    union { __nv_bfloat16 b[4]; uint2 u; } H, L;
    #pragma unroll
    for (int i = 0; i < 4; i++) {
        H.b[i] = __float2bfloat16(f[i]);
        L.b[i] = __float2bfloat16(f[i] - __bfloat162float(H.b[i]));
    }
    size_t base = (size_t)r * 3 * K + k;
    *(uint2*)(Y + base)         = H.u;
    *(uint2*)(Y + base + K)     = border ? H.u : L.u;
    *(uint2*)(Y + base + 2*K)   = border ? L.u : H.u;
}

// ---------------- HMMA bf16 GEMM: C = A(M x K3) @ B(N x K3)^T + epilogue ----
// EPI: 0 = bias, 1 = bias + residual, 2 = bias + gelu(erf)
// 128x128 CTA tile, 256 threads (2x4 warps, 64x32 warp tile), BK=64 bf16.
#define GBM 128
#define GBN 128
#define GBK 64                      // bf16 per K-chunk => 128B SW128 rows
#define AST (GBM*128)               // A stage bytes = 16384
#define GSTAGE (AST + GBN*128)      // 32768
#define GSMEM (2*GSTAGE + 1024)

template<int EPI>
__global__ void __launch_bounds__(256, 1)
gemm_mma(const __nv_bfloat16* __restrict__ A, const __nv_bfloat16* __restrict__ B,
         const float* __restrict__ bias, const float* __restrict__ R,
         float* __restrict__ C, int M, int N, int K3) {
    extern __shared__ char dyn_smem[];
    const int tid  = threadIdx.x;
    const int lane = tid & 31;
    const int wid  = tid >> 5;
    const int wm   = wid & 1;          // 2 warp rows
    const int wn   = wid >> 1;         // 4 warp cols
    const int bm = blockIdx.y * GBM;
    const int bn = blockIdx.x * GBN;

    uint32_t raw = smem_u32(dyn_smem);
    uint32_t sb  = (raw + 1023u) & ~1023u;

    const size_t ldb = (size_t)K3 * 2;   // row stride in bytes
    const char* Abase = (const char*)(A + (size_t)bm * K3);
    const char* Bbase = (const char*)(B + (size_t)bn * K3);

    auto issue_stage = [&](int kt, int s) {
        uint32_t dst = sb + s * GSTAGE;
        const char* Ab = Abase + (size_t)kt * (GBK * 2);
        const char* Bb = Bbase + (size_t)kt * (GBK * 2);
        #pragma unroll
        for (int p = 0; p < 4; p++) {
            int g   = (p << 8) + tid;          // 0..1023
            int row = g >> 3;
            int seg = (g & 7) << 4;
            uint32_t off = SWZ(row * 128 + seg);
            CP_ASYNC16(dst + off,       Ab + (size_t)row * ldb + seg);
            CP_ASYNC16(dst + AST + off, Bb + (size_t)row * ldb + seg);
        }
        CP_COMMIT();
    };

    float acc[4][4][4];
    #pragma unroll
    for (int i = 0; i < 4; i++)
        #pragma unroll
        for (int j = 0; j < 4; j++)
            #pragma unroll
            for (int t = 0; t < 4; t++) acc[i][j][t] = 0.f;

    const int nk = K3 / GBK;
    issue_stage(0, 0);

    // precomputed ldmatrix lane address components
    const int a_row = wm * 64 + (lane & 15);       // + i*16
    const int a_kb  = (lane >> 4) << 4;            // 0 or 16 bytes
    const int b_row = wn * 32 + (lane & 7);        // + j*8
    const int b_kb  = ((lane >> 3) & 1) << 4;      // 0 or 16 bytes

    for (int kt = 0; kt < nk; kt++) {
        int s = kt & 1;
        if (kt + 1 < nk) {
            issue_stage(kt + 1, s ^ 1);
            CP_WAIT1();
        } else {
            CP_WAIT0();
        }
        __syncthreads();

        uint32_t ab = sb + s * GSTAGE;
        uint32_t bb = ab + AST;
        #pragma unroll
        for (int kk = 0; kk < 4; kk++) {
            uint32_t af[4][4], bfr[4][2];
            #pragma unroll
            for (int i = 0; i < 4; i++)
                ldsm_x4(af[i][0], af[i][1], af[i][2], af[i][3],
                        ab + SWZ((a_row + i*16) * 128 + kk*32 + a_kb));
            #pragma unroll
            for (int j = 0; j < 4; j++)
                ldsm_x2(bfr[j][0], bfr[j][1],
                        bb + SWZ((b_row + j*8) * 128 + kk*32 + b_kb));
            #pragma unroll
            for (int i = 0; i < 4; i++)
                #pragma unroll
                for (int j = 0; j < 4; j++)
                    mma_bf16(acc[i][j], af[i], bfr[j]);
        }
        __syncthreads();
    }

    // ---- epilogue: registers -> global, fused bias/residual/gelu ----
    const int er = (lane >> 2);          // 0..7
    const int ec = (lane & 3) << 1;      // 0,2,4,6
    #pragma unroll
    for (int i = 0; i < 4; i++) {
        #pragma unroll
        for (int j = 0; j < 4; j++) {
            int col = bn + wn*32 + j*8 + ec;
            float bx = bias[col], by = bias[col + 1];
            #pragma unroll
            for (int h = 0; h < 2; h++) {
                int row = bm + wm*64 + i*16 + er + h*8;
                float vx = acc[i][j][h*2 + 0] + bx;
                float vy = acc[i][j][h*2 + 1] + by;
                if (EPI == 1) {
                    const float2 rr = *(const float2*)(R + (size_t)row * N + col);
                    vx += rr.x; vy += rr.y;
                }
                if (EPI == 2) {
                    vx = 0.5f * vx * (1.0f + erff(vx * 0.70710678118654752f));
                    vy = 0.5f * vy * (1.0f + erff(vy * 0.70710678118654752f));
                }
                *(float2*)(C + (size_t)row * N + col) = make_float2(vx, vy);
            }
        }
    }
}

// ---------------- flash attention (causal always per reference) ----------
#define ABM 32
#define KP 68

__global__ void __launch_bounds__(256)
attn_kernel(const float* __restrict__ Q, const float* __restrict__ Kp,
            const float* __restrict__ Vp, float* __restrict__ O, int causal) {
    __shared__ float Qs[ABM * 64];
    __shared__ float Kt[64 * KP];
    __shared__ float Vs[64 * 64];

    int b  = blockIdx.y;
    int qi = blockIdx.x;
    int n  = b >> 4, hh = b & 15;
    int tid = threadIdx.x;
    int rg = tid >> 4, cg = tid & 15;
    int r0 = rg * 2, c0 = cg * 4;
    int qbase = qi * ABM;

    for (int i = tid; i < ABM * 16; i += 256) {
        int rr = i >> 4, seg = (i & 15) * 4;
        *(float4*)&Qs[rr*64 + seg] =
            *(const float4*)(Q + (size_t)(((qbase + rr)*NN + n) << 10) + hh*HD + seg);
    }

    float m[2], l[2], o[2][4];
    #pragma unroll
    for (int i = 0; i < 2; i++) {
        m[i] = -1e30f; l[i] = 0.f;
        #pragma unroll
        for (int j = 0; j < 4; j++) o[i][j] = 0.f;
    }

    int jmax = causal ? ((qbase + ABM - 1) >> 6) : (LL/64 - 1);
    for (int j = 0; j <= jmax; j++) {
        __syncthreads();
        for (int i = tid; i < 64 * 16; i += 256) {
            int rr = i >> 4, seg = (i & 15) * 4;
            size_t base = (size_t)(((j*64 + rr)*NN + n) << 10) + hh*HD;
            float4 kv = *(const float4*)(Kp + base + seg);
            Kt[(seg+0)*KP + rr] = kv.x;
            Kt[(seg+1)*KP + rr] = kv.y;
            Kt[(seg+2)*KP + rr] = kv.z;
            Kt[(seg+3)*KP + rr] = kv.w;
            *(float4*)&Vs[rr*64 + seg] = *(const float4*)(Vp + base + seg);
        }
        __syncthreads();

        float s[2][4];
        #pragma unroll
        for (int i = 0; i < 2; i++)
            #pragma unroll
            for (int jj = 0; jj < 4; jj++) s[i][jj] = 0.f;

        for (int d4 = 0; d4 < 64; d4 += 4) {
            float qv[8], kv[16];
            *(float4*)&qv[0] = *(const float4*)&Qs[(r0+0)*64 + d4];
            *(float4*)&qv[4] = *(const float4*)&Qs[(r0+1)*64 + d4];
            #pragma unroll
            for (int t = 0; t < 4; t++)
                *(float4*)&kv[t*4] = *(const float4*)&Kt[(d4+t)*KP + c0];
            #pragma unroll
            for (int i = 0; i < 2; i++)
                #pragma unroll
                for (int t = 0; t < 4; t++) {
                    float qq = qv[i*4 + t];
                    s[i][0] += qq * kv[t*4+0];
                    s[i][1] += qq * kv[t*4+1];
                    s[i][2] += qq * kv[t*4+2];
                    s[i][3] += qq * kv[t*4+3];
                }
        }
        const float scale = 0.125f;
        #pragma unroll
        for (int i = 0; i < 2; i++)
            #pragma unroll
            for (int jj = 0; jj < 4; jj++) s[i][jj] *= scale;

        if (causal && j == jmax) {
            #pragma unroll
            for (int i = 0; i < 2; i++)
                #pragma unroll
                for (int jj = 0; jj < 4; jj++)
                    if (j*64 + c0 + jj > qbase + r0 + i) s[i][jj] = -10000.0f;
        }

        __syncthreads();

        #pragma unroll
        for (int i = 0; i < 2; i++) {
            float mx = fmaxf(fmaxf(s[i][0], s[i][1]), fmaxf(s[i][2], s[i][3]));
            #pragma unroll
            for (int off = 8; off > 0; off >>= 1)
                mx = fmaxf(mx, __shfl_xor_sync(0xffffffffu, mx, off, 16));
            float mn = fmaxf(m[i], mx);
            float alpha = __expf(m[i] - mn);
            float ls = 0.f;
            #pragma unroll
            for (int jj = 0; jj < 4; jj++) {
                float p = __expf(s[i][jj] - mn);
                s[i][jj] = p;
                ls += p;
            }
            #pragma unroll
            for (int off = 8; off > 0; off >>= 1)
                ls += __shfl_xor_sync(0xffffffffu, ls, off, 16);
            l[i] = l[i] * alpha + ls;
            m[i] = mn;
            #pragma unroll
            for (int jj = 0; jj < 4; jj++) o[i][jj] *= alpha;
            *(float4*)&Kt[(r0+i)*KP + c0] = make_float4(s[i][0], s[i][1], s[i][2], s[i][3]);
        }
        __syncthreads();

        for (int c4 = 0; c4 < 64; c4 += 4) {
            float pv[8], vv[16];
            *(float4*)&pv[0] = *(const float4*)&Kt[(r0+0)*KP + c4];
            *(float4*)&pv[4] = *(const float4*)&Kt[(r0+1)*KP + c4];
            #pragma unroll
            for (int t = 0; t < 4; t++)
                *(float4*)&vv[t*4] = *(const float4*)&Vs[(c4+t)*64 + c0];
            #pragma unroll
            for (int i = 0; i < 2; i++)
                #pragma unroll
                for (int t = 0; t < 4; t++) {
                    float pp = pv[i*4 + t];
                    o[i][0] += pp * vv[t*4+0];
                    o[i][1] += pp * vv[t*4+1];
                    o[i][2] += pp * vv[t*4+2];
                    o[i][3] += pp * vv[t*4+3];
                }
        }
    }

    #pragma unroll
    for (int i = 0; i < 2; i++) {
        float inv = 1.0f / l[i];
        int row = qbase + r0 + i;
        float4 ov = make_float4(o[i][0]*inv, o[i][1]*inv, o[i][2]*inv, o[i][3]*inv);
        *(float4*)(O + (size_t)((row*NN + n) << 10) + hh*HD + c0) = ov;
    }
}

// ---------------- orchestration ----------------
static void split_a(const float* X, __nv_bfloat16* Y, int rows, int K) {
    int t4 = rows * K / 4;
    split3_kernel<<<(t4 + 255) / 256, 256>>>(X, Y, K, t4, 0);
}

static void tc_gemm(int epi, int M_, int N_, int K_,
                    const __nv_bfloat16* a3, const float* W,
                    const float* bias, const float* R, float* Cc,
                    __nv_bfloat16* w3) {
    int t4 = N_ * K_ / 4;
    split3_kernel<<<(t4 + 255) / 256, 256>>>(W, w3, K_, t4, 1);
    dim3 grid(N_ / GBN, M_ / GBM);
    int K3 = 3 * K_;
    if (epi == 0)      gemm_mma<0><<<grid, 256, GSMEM>>>(a3, w3, bias, R, Cc, M_, N_, K3);
    else if (epi == 1) gemm_mma<1><<<grid, 256, GSMEM>>>(a3, w3, bias, R, Cc, M_, N_, K3);
    else               gemm_mma<2><<<grid, 256, GSMEM>>>(a3, w3, bias, R, Cc, M_, N_, K3);
}

extern "C" void kernel_launch(void* const* d_in, const int* in_sizes, int n_in,
                              void* d_out, int out_size) {
    const float* x    = (const float*)d_in[0];
    const float* enc  = (const float*)d_in[1];
    const float* wq_s = (const float*)d_in[2];
    const float* bq_s = (const float*)d_in[3];
    const float* wk_s = (const float*)d_in[4];
    const float* bk_s = (const float*)d_in[5];
    const float* wv_s = (const float*)d_in[6];
    const float* bv_s = (const float*)d_in[7];
    const float* wo_s = (const float*)d_in[8];
    const float* bo_s = (const float*)d_in[9];
    const float* wq_c = (const float*)d_in[10];
    const float* bq_c = (const float*)d_in[11];
    const float* wk_c = (const float*)d_in[12];
    const float* bk_c = (const float*)d_in[13];
    const float* wv_c = (const float*)d_in[14];
    const float* bv_c = (const float*)d_in[15];
    const float* wo_c = (const float*)d_in[16];
    const float* bo_c = (const float*)d_in[17];
    const float* ln1_g = (const float*)d_in[18];
    const float* ln1_b = (const float*)d_in[19];
    const float* ln2_g = (const float*)d_in[20];
    const float* ln2_b = (const float*)d_in[21];
    const float* ln3_g = (const float*)d_in[22];
    const float* ln3_b = (const float*)d_in[23];
    const float* fc1_w = (const float*)d_in[24];
    const float* fc1_b = (const float*)d_in[25];
    const float* fc2_w = (const float*)d_in[26];
    const float* fc2_b = (const float*)d_in[27];
    float* out = (float*)d_out;

    float *p_h, *p_q, *p_k, *p_v, *p_attn, *p_ff;
    __nv_bfloat16 *p_a3, *p_w3;
    cudaGetSymbolAddress((void**)&p_h,    g_h);
    cudaGetSymbolAddress((void**)&p_q,    g_q);
    cudaGetSymbolAddress((void**)&p_k,    g_k);
    cudaGetSymbolAddress((void**)&p_v,    g_v);
    cudaGetSymbolAddress((void**)&p_attn, g_attn);
    cudaGetSymbolAddress((void**)&p_ff,   g_ff);
    cudaGetSymbolAddress((void**)&p_a3,   g_a3);
    cudaGetSymbolAddress((void**)&p_w3,   g_w3);

    cudaFuncSetAttribute(gemm_mma<0>, cudaFuncAttributeMaxDynamicSharedMemorySize, GSMEM);
    cudaFuncSetAttribute(gemm_mma<1>, cudaFuncAttributeMaxDynamicSharedMemorySize, GSMEM);
    cudaFuncSetAttribute(gemm_mma<2>, cudaFuncAttributeMaxDynamicSharedMemorySize, GSMEM);

    dim3 agrid(LL / ABM, NN * HH);

    // ---- block 1: self-attention ----
    ln_kernel<<<MM, 256>>>(x, ln1_g, ln1_b, p_h);
    split_a(p_h, p_a3, MM, EE);
    tc_gemm(0, MM, EE, EE, p_a3, wq_s, bq_s, nullptr, p_q, p_w3);
    tc_gemm(0, MM, EE, EE, p_a3, wk_s, bk_s, nullptr, p_k, p_w3);
    tc_gemm(0, MM, EE, EE, p_a3, wv_s, bv_s, nullptr, p_v, p_w3);
    attn_kernel<<<agrid, 256>>>(p_q, p_k, p_v, p_attn, 1);
    split_a(p_attn, p_a3, MM, EE);
    tc_gemm(1, MM, EE, EE, p_a3, wo_s, bo_s, x, out, p_w3);

    // ---- block 2: cross-attention (reference applies causal mask here too) ----
    ln_kernel<<<MM, 256>>>(out, ln2_g, ln2_b, p_h);
    split_a(p_h, p_a3, MM, EE);
    tc_gemm(0, MM, EE, EE, p_a3, wq_c, bq_c, nullptr, p_q, p_w3);
    split_a(enc, p_a3, MM, EE);
    tc_gemm(0, MM, EE, EE, p_a3, wk_c, bk_c, nullptr, p_k, p_w3);
    tc_gemm(0, MM, EE, EE, p_a3, wv_c, bv_c, nullptr, p_v, p_w3);
    attn_kernel<<<agrid, 256>>>(p_q, p_k, p_v, p_attn, 1);
    split_a(p_attn, p_a3, MM, EE);
    tc_gemm(1, MM, EE, EE, p_a3, wo_c, bo_c, out, out, p_w3);

    // ---- block 3: FFN ----
    ln_kernel<<<MM, 256>>>(out, ln3_g, ln3_b, p_h);
    split_a(p_h, p_a3, MM, EE);
    tc_gemm(2, MM, FF, EE, p_a3, fc1_w, fc1_b, nullptr, p_ff, p_w3);
    split_a(p_ff, p_a3, MM, FF);
    tc_gemm(1, MM, EE, FF, p_a3, fc2_w, fc2_b, out, out, p_w3);
}

// round 6
// speedup vs baseline: 2.8399x; 1.4419x over previous
#include <cuda_runtime.h>
#include <cuda_bf16.h>
#include <math.h>
#include <stdint.h>

// Problem constants: L=1024, N=4, E=1024, F=4096, H=16, d=64
#define LL 1024
#define NN 4
#define EE 1024
#define FF 4096
#define HH 16
#define HD 64
#define MM (LL*NN)   // 4096 rows

// ---------------- scratch (static device allocations) ----------------
__device__ float g_h[MM*EE];
__device__ float g_q[MM*EE];
__device__ float g_k[MM*EE];
__device__ float g_v[MM*EE];
__device__ float g_attn[MM*EE];
__device__ float g_ff[(size_t)MM*FF];
__device__ __nv_bfloat16 g_a3[(size_t)MM * 3 * FF];
__device__ __nv_bfloat16 g_w3[(size_t)FF * 3 * EE];

// ---------------- portable PTX helpers -------
__device__ __forceinline__ uint32_t smem_u32(const void* p) {
    uint32_t a;
    asm("{ .reg .u64 t; cvta.to.shared.u64 t, %1; cvt.u32.u64 %0, t; }" : "=r"(a) : "l"(p));
    return a;
}

#define SWZ(x) ((x) ^ (((x) >> 3) & 0x70))

#define CP_ASYNC16(dst_u32, src_ptr) \
    asm volatile("cp.async.cg.shared.global [%0], [%1], 16;" \
        :: "r"(dst_u32), "l"(src_ptr) : "memory")
#define CP_COMMIT() asm volatile("cp.async.commit_group;" ::: "memory")
#define CP_WAIT1()  asm volatile("cp.async.wait_group 1;" ::: "memory")
#define CP_WAIT0()  asm volatile("cp.async.wait_group 0;" ::: "memory")

__device__ __forceinline__ void ldsm_x4(uint32_t& r0, uint32_t& r1, uint32_t& r2, uint32_t& r3,
                                        uint32_t addr) {
    asm volatile("ldmatrix.sync.aligned.m8n8.x4.shared.b16 {%0,%1,%2,%3}, [%4];"
        : "=r"(r0), "=r"(r1), "=r"(r2), "=r"(r3) : "r"(addr));
}
__device__ __forceinline__ void ldsm_x2(uint32_t& r0, uint32_t& r1, uint32_t addr) {
    asm volatile("ldmatrix.sync.aligned.m8n8.x2.shared.b16 {%0,%1}, [%2];"
        : "=r"(r0), "=r"(r1) : "r"(addr));
}
__device__ __forceinline__ void mma_bf16(float* d, const uint32_t* a, const uint32_t* b) {
    asm volatile("mma.sync.aligned.m16n8k16.row.col.f32.bf16.bf16.f32 "
        "{%0,%1,%2,%3}, {%4,%5,%6,%7}, {%8,%9}, {%0,%1,%2,%3};"
        : "+f"(d[0]), "+f"(d[1]), "+f"(d[2]), "+f"(d[3])
        : "r"(a[0]), "r"(a[1]), "r"(a[2]), "r"(a[3]), "r"(b[0]), "r"(b[1]));
}
__device__ __forceinline__ uint32_t pack_bf16x2(float x, float y) {
    __nv_bfloat162 h = __floats2bfloat162_rn(x, y);
    return *(uint32_t*)&h;
}

// ---------------- layernorm ----------------
__global__ void ln_kernel(const float* __restrict__ x, const float* __restrict__ g,
                          const float* __restrict__ b, float* __restrict__ y) {
    int row = blockIdx.x;
    int tid = threadIdx.x;
    const float4* xr = (const float4*)(x + (size_t)row * EE);
    float4 v = xr[tid];
    float s  = v.x + v.y + v.z + v.w;
    float sq = v.x*v.x + v.y*v.y + v.z*v.z + v.w*v.w;
    #pragma unroll
    for (int off = 16; off > 0; off >>= 1) {
        s  += __shfl_down_sync(0xffffffffu, s,  off);
        sq += __shfl_down_sync(0xffffffffu, sq, off);
    }
    __shared__ float rs[8], rq[8];
    __shared__ float s_mean, s_rstd;
    int lane = tid & 31, wid = tid >> 5;
    if (lane == 0) { rs[wid] = s; rq[wid] = sq; }
    __syncthreads();
    if (tid == 0) {
        float ts = 0.f, tq = 0.f;
        #pragma unroll
        for (int i = 0; i < 8; i++) { ts += rs[i]; tq += rq[i]; }
        float mean = ts * (1.0f / EE);
        float var  = tq * (1.0f / EE) - mean * mean;
        s_mean = mean;
        s_rstd = rsqrtf(var + 1e-5f);
    }
    __syncthreads();
    float mean = s_mean, rstd = s_rstd;
    const float4* gr = (const float4*)g;
    const float4* br = (const float4*)b;
    float4 gv = gr[tid], bv = br[tid];
    float4 o;
    o.x = (v.x - mean) * rstd * gv.x + bv.x;
    o.y = (v.y - mean) * rstd * gv.y + bv.y;
    o.z = (v.z - mean) * rstd * gv.z + bv.z;
    o.w = (v.w - mean) * rstd * gv.w + bv.w;
    ((float4*)(y + (size_t)row * EE))[tid] = o;
}

// ---------------- fp32 -> 3-segment bf16 split ----------------
__global__ void split3_kernel(const float* __restrict__ X, __nv_bfloat16* __restrict__ Y,
                              int K, int total4, int border) {
    int idx = blockIdx.x * blockDim.x + threadIdx.x;
    if (idx >= total4) return;
    int kq = K >> 2;
    int r  = idx / kq;
    int k  = (idx - r * kq) << 2;
    float4 v = *(const float4*)(X + (size_t)r * K + k);
    float f[4] = {v.x, v.y, v.z, v.w};
    union { __nv_bfloat16 b[4]; uint2 u; } H, L;
    #pragma unroll
    for (int i = 0; i < 4; i++) {
        H.b[i] = __float2bfloat16(f[i]);
        L.b[i] = __float2bfloat16(f[i] - __bfloat162float(H.b[i]));
    }
    size_t base = (size_t)r * 3 * K + k;
    *(uint2*)(Y + base)         = H.u;
    *(uint2*)(Y + base + K)     = border ? H.u : L.u;
    *(uint2*)(Y + base + 2*K)   = border ? L.u : H.u;
}

// ---------------- HMMA bf16 GEMM (3-stage cp.async pipeline) ----
#define GBM 128
#define GBN 128
#define GBK 64
#define AST (GBM*128)
#define GSTAGE (AST + GBN*128)      // 32768
#define GSMEM (3*GSTAGE + 1024)

template<int EPI>
__global__ void __launch_bounds__(256, 1)
gemm_mma(const __nv_bfloat16* __restrict__ A, const __nv_bfloat16* __restrict__ B,
         const float* __restrict__ bias, const float* __restrict__ R,
         float* __restrict__ C, int M, int N, int K3) {
    extern __shared__ char dyn_smem[];
    const int tid  = threadIdx.x;
    const int lane = tid & 31;
    const int wid  = tid >> 5;
    const int wm   = wid & 1;
    const int wn   = wid >> 1;
    const int bm = blockIdx.y * GBM;
    const int bn = blockIdx.x * GBN;

    uint32_t raw = smem_u32(dyn_smem);
    uint32_t sb  = (raw + 1023u) & ~1023u;

    const size_t ldb = (size_t)K3 * 2;
    const char* Abase = (const char*)(A + (size_t)bm * K3);
    const char* Bbase = (const char*)(B + (size_t)bn * K3);

    auto issue_stage = [&](int kt, int s) {
        uint32_t dst = sb + s * GSTAGE;
        const char* Ab = Abase + (size_t)kt * (GBK * 2);
        const char* Bb = Bbase + (size_t)kt * (GBK * 2);
        #pragma unroll
        for (int p = 0; p < 4; p++) {
            int g   = (p << 8) + tid;
            int row = g >> 3;
            int seg = (g & 7) << 4;
            uint32_t off = SWZ(row * 128 + seg);
            CP_ASYNC16(dst + off,       Ab + (size_t)row * ldb + seg);
            CP_ASYNC16(dst + AST + off, Bb + (size_t)row * ldb + seg);
        }
        CP_COMMIT();
    };

    float acc[4][4][4];
    #pragma unroll
    for (int i = 0; i < 4; i++)
        #pragma unroll
        for (int j = 0; j < 4; j++)
            #pragma unroll
            for (int t = 0; t < 4; t++) acc[i][j][t] = 0.f;

    const int nk = K3 / GBK;
    issue_stage(0, 0);
    issue_stage(1, 1);

    const int a_row = wm * 64 + (lane & 15);
    const int a_kb  = (lane >> 4) << 4;
    const int b_row = wn * 32 + (lane & 7);
    const int b_kb  = ((lane >> 3) & 1) << 4;

    for (int kt = 0; kt < nk; kt++) {
        if (kt + 1 < nk) { CP_WAIT1(); } else { CP_WAIT0(); }
        __syncthreads();
        if (kt + 2 < nk) issue_stage(kt + 2, (kt + 2) % 3);

        uint32_t ab = sb + (kt % 3) * GSTAGE;
        uint32_t bb = ab + AST;
        #pragma unroll
        for (int kk = 0; kk < 4; kk++) {
            uint32_t af[4][4], bfr[4][2];
            #pragma unroll
            for (int i = 0; i < 4; i++)
                ldsm_x4(af[i][0], af[i][1], af[i][2], af[i][3],
                        ab + SWZ((a_row + i*16) * 128 + kk*32 + a_kb));
            #pragma unroll
            for (int j = 0; j < 4; j++)
                ldsm_x2(bfr[j][0], bfr[j][1],
                        bb + SWZ((b_row + j*8) * 128 + kk*32 + b_kb));
            #pragma unroll
            for (int i = 0; i < 4; i++)
                #pragma unroll
                for (int j = 0; j < 4; j++)
                    mma_bf16(acc[i][j], af[i], bfr[j]);
        }
    }

    const int er = (lane >> 2);
    const int ec = (lane & 3) << 1;
    #pragma unroll
    for (int i = 0; i < 4; i++) {
        #pragma unroll
        for (int j = 0; j < 4; j++) {
            int col = bn + wn*32 + j*8 + ec;
            float bx = bias[col], by = bias[col + 1];
            #pragma unroll
            for (int h = 0; h < 2; h++) {
                int row = bm + wm*64 + i*16 + er + h*8;
                float vx = acc[i][j][h*2 + 0] + bx;
                float vy = acc[i][j][h*2 + 1] + by;
                if (EPI == 1) {
                    const float2 rr = *(const float2*)(R + (size_t)row * N + col);
                    vx += rr.x; vy += rr.y;
                }
                if (EPI == 2) {
                    vx = 0.5f * vx * (1.0f + erff(vx * 0.70710678118654752f));
                    vy = 0.5f * vy * (1.0f + erff(vy * 0.70710678118654752f));
                }
                *(float2*)(C + (size_t)row * N + col) = make_float2(vx, vy);
            }
        }
    }
}

// ---------------- HMMA flash attention (causal always per reference) ----
// 128 threads = 4 warps, q-tile 64 rows (16 per warp), kv-tile 64, d=64.
// Softmax on MMA fragments; P repacked in registers (FA2 trick); V transposed in smem.
__global__ void __launch_bounds__(128)
attn_mma(const float* __restrict__ Q, const float* __restrict__ Kp,
         const float* __restrict__ Vp, float* __restrict__ O) {
    __shared__ __nv_bfloat16 Qs[64*64];
    __shared__ __nv_bfloat16 Ks[64*64];
    __shared__ __nv_bfloat16 Vt[64*64];   // [d][kv]

    const int b = blockIdx.y, qi = blockIdx.x;
    const int n = b >> 4, hh = b & 15;
    const int tid = threadIdx.x, lane = tid & 31, w = tid >> 5;
    const int qbase = qi * 64;
    const uint32_t qs = smem_u32(Qs), ks = smem_u32(Ks), vt = smem_u32(Vt);

    // load + convert Q (fold 1/sqrt(d)=0.125, exact in bf16)
    for (int i = tid; i < 64*16; i += 128) {
        int rr = i >> 4, seg = (i & 15) << 2;
        float4 v = *(const float4*)(Q + ((size_t)((qbase+rr)*NN + n) << 10) + hh*HD + seg);
        uint2 pk;
        pk.x = pack_bf16x2(v.x*0.125f, v.y*0.125f);
        pk.y = pack_bf16x2(v.z*0.125f, v.w*0.125f);
        *(uint2*)((char*)Qs + SWZ(rr*128 + seg*2)) = pk;
    }

    const int r  = lane >> 2;          // fragment row 0..7
    const int cb = (lane & 3) << 1;    // fragment col base

    float m0 = -1e30f, m1 = -1e30f, l0 = 0.f, l1 = 0.f;
    float oac[8][4];
    #pragma unroll
    for (int t = 0; t < 8; t++)
        #pragma unroll
        for (int e = 0; e < 4; e++) oac[t][e] = 0.f;

    const uint32_t a_addr0 = SWZ((w*16 + (lane & 15))*128 + ((lane >> 4) << 4));

    for (int j = 0; j <= qi; j++) {
        __syncthreads();   // prev iteration done with Ks/Vt
        for (int i = tid; i < 64*16; i += 128) {
            int rr = i >> 4, seg = (i & 15) << 2;
            size_t base = ((size_t)((j*64 + rr)*NN + n) << 10) + hh*HD;
            float4 kv = *(const float4*)(Kp + base + seg);
            uint2 pk;
            pk.x = pack_bf16x2(kv.x, kv.y);
            pk.y = pack_bf16x2(kv.z, kv.w);
            *(uint2*)((char*)Ks + SWZ(rr*128 + seg*2)) = pk;
            float4 vv = *(const float4*)(Vp + base + seg);
            __nv_bfloat16 e0 = __float2bfloat16(vv.x), e1 = __float2bfloat16(vv.y);
            __nv_bfloat16 e2 = __float2bfloat16(vv.z), e3 = __float2bfloat16(vv.w);
            *(__nv_bfloat16*)((char*)Vt + SWZ((seg+0)*128 + rr*2)) = e0;
            *(__nv_bfloat16*)((char*)Vt + SWZ((seg+1)*128 + rr*2)) = e1;
            *(__nv_bfloat16*)((char*)Vt + SWZ((seg+2)*128 + rr*2)) = e2;
            *(__nv_bfloat16*)((char*)Vt + SWZ((seg+3)*128 + rr*2)) = e3;
        }
        __syncthreads();

        // ---- S = Q K^T (m16 x n64 per warp) ----
        uint32_t af[4][4];
        #pragma unroll
        for (int kk = 0; kk < 4; kk++)
            ldsm_x4(af[kk][0], af[kk][1], af[kk][2], af[kk][3], qs + a_addr0 + (kk*32 ^ 0));
        // NOTE: kk*32 offset must go through SWZ with the row term; recompute properly:
        #pragma unroll
        for (int kk = 0; kk < 4; kk++)
            ldsm_x4(af[kk][0], af[kk][1], af[kk][2], af[kk][3],
                    qs + SWZ((w*16 + (lane & 15))*128 + kk*32 + ((lane >> 4) << 4)));

        float sac[8][4];
        #pragma unroll
        for (int t = 0; t < 8; t++) {
            sac[t][0] = sac[t][1] = sac[t][2] = sac[t][3] = 0.f;
            #pragma unroll
            for (int kk = 0; kk < 4; kk++) {
                uint32_t bfr[2];
                ldsm_x2(bfr[0], bfr[1],
                        ks + SWZ((t*8 + (lane & 7))*128 + kk*32 + (((lane >> 3) & 1) << 4)));
                mma_bf16(sac[t], af[kk], bfr);
            }
        }

        // ---- causal mask on diagonal tile ----
        if (j == qi) {
            int grow0 = qbase + w*16 + r;
            int grow1 = grow0 + 8;
            #pragma unroll
            for (int t = 0; t < 8; t++) {
                int gc = j*64 + t*8 + cb;
                if (gc     > grow0) sac[t][0] = -10000.0f;
                if (gc + 1 > grow0) sac[t][1] = -10000.0f;
                if (gc     > grow1) sac[t][2] = -10000.0f;
                if (gc + 1 > grow1) sac[t][3] = -10000.0f;
            }
        }

        // ---- online softmax on fragments ----
        float mx0 = -1e30f, mx1 = -1e30f;
        #pragma unroll
        for (int t = 0; t < 8; t++) {
            mx0 = fmaxf(mx0, fmaxf(sac[t][0], sac[t][1]));
            mx1 = fmaxf(mx1, fmaxf(sac[t][2], sac[t][3]));
        }
        mx0 = fmaxf(mx0, __shfl_xor_sync(0xffffffffu, mx0, 1));
        mx0 = fmaxf(mx0, __shfl_xor_sync(0xffffffffu, mx0, 2));
        mx1 = fmaxf(mx1, __shfl_xor_sync(0xffffffffu, mx1, 1));
        mx1 = fmaxf(mx1, __shfl_xor_sync(0xffffffffu, mx1, 2));
        float mn0 = fmaxf(m0, mx0), mn1 = fmaxf(m1, mx1);
        float al0 = __expf(m0 - mn0), al1 = __expf(m1 - mn1);
        float ls0 = 0.f, ls1 = 0.f;
        #pragma unroll
        for (int t = 0; t < 8; t++) {
            sac[t][0] = __expf(sac[t][0] - mn0);
            sac[t][1] = __expf(sac[t][1] - mn0);
            sac[t][2] = __expf(sac[t][2] - mn1);
            sac[t][3] = __expf(sac[t][3] - mn1);
            ls0 += sac[t][0] + sac[t][1];
            ls1 += sac[t][2] + sac[t][3];
        }
        ls0 += __shfl_xor_sync(0xffffffffu, ls0, 1);
        ls0 += __shfl_xor_sync(0xffffffffu, ls0, 2);
        ls1 += __shfl_xor_sync(0xffffffffu, ls1, 1);
        ls1 += __shfl_xor_sync(0xffffffffu, ls1, 2);
        l0 = l0 * al0 + ls0;  m0 = mn0;
        l1 = l1 * al1 + ls1;  m1 = mn1;
        #pragma unroll
        for (int t = 0; t < 8; t++) {
            oac[t][0] *= al0; oac[t][1] *= al0;
            oac[t][2] *= al1; oac[t][3] *= al1;
        }

        // ---- repack P (C-frag) -> A-frag in registers ----
        uint32_t pf[4][4];
        #pragma unroll
        for (int kt = 0; kt < 4; kt++) {
            pf[kt][0] = pack_bf16x2(sac[2*kt][0],   sac[2*kt][1]);
            pf[kt][1] = pack_bf16x2(sac[2*kt][2],   sac[2*kt][3]);
            pf[kt][2] = pack_bf16x2(sac[2*kt+1][0], sac[2*kt+1][1]);
            pf[kt][3] = pack_bf16x2(sac[2*kt+1][2], sac[2*kt+1][3]);
        }

        // ---- O += P V  (B operand from Vt[d][kv]) ----
        #pragma unroll
        for (int td = 0; td < 8; td++) {
            #pragma unroll
            for (int kt = 0; kt < 4; kt++) {
                uint32_t bfr[2];
                ldsm_x2(bfr[0], bfr[1],
                        vt + SWZ((td*8 + (lane & 7))*128 + kt*32 + (((lane >> 3) & 1) << 4)));
                mma_bf16(oac[td], pf[kt], bfr);
            }
        }
    }

    // ---- finalize: normalize and store ----
    float inv0 = 1.0f / l0, inv1 = 1.0f / l1;
    int row0 = qbase + w*16 + r;
    int row1 = row0 + 8;
    #pragma unroll
    for (int td = 0; td < 8; td++) {
        int col = td*8 + cb;
        *(float2*)(O + ((size_t)(row0*NN + n) << 10) + hh*HD + col) =
            make_float2(oac[td][0]*inv0, oac[td][1]*inv0);
        *(float2*)(O + ((size_t)(row1*NN + n) << 10) + hh*HD + col) =
            make_float2(oac[td][2]*inv1, oac[td][3]*inv1);
    }
}

// ---------------- orchestration ----------------
static void split_a(const float* X, __nv_bfloat16* Y, int rows, int K) {
    int t4 = rows * K / 4;
    split3_kernel<<<(t4 + 255) / 256, 256>>>(X, Y, K, t4, 0);
}

static void tc_gemm(int epi, int M_, int N_, int K_,
                    const __nv_bfloat16* a3, const float* W,
                    const float* bias, const float* R, float* Cc,
                    __nv_bfloat16* w3) {
    int t4 = N_ * K_ / 4;
    split3_kernel<<<(t4 + 255) / 256, 256>>>(W, w3, K_, t4, 1);
    dim3 grid(N_ / GBN, M_ / GBM);
    int K3 = 3 * K_;
    if (epi == 0)      gemm_mma<0><<<grid, 256, GSMEM>>>(a3, w3, bias, R, Cc, M_, N_, K3);
    else if (epi == 1) gemm_mma<1><<<grid, 256, GSMEM>>>(a3, w3, bias, R, Cc, M_, N_, K3);
    else               gemm_mma<2><<<grid, 256, GSMEM>>>(a3, w3, bias, R, Cc, M_, N_, K3);
}

extern "C" void kernel_launch(void* const* d_in, const int* in_sizes, int n_in,
                              void* d_out, int out_size) {
    const float* x    = (const float*)d_in[0];
    const float* enc  = (const float*)d_in[1];
    const float* wq_s = (const float*)d_in[2];
    const float* bq_s = (const float*)d_in[3];
    const float* wk_s = (const float*)d_in[4];
    const float* bk_s = (const float*)d_in[5];
    const float* wv_s = (const float*)d_in[6];
    const float* bv_s = (const float*)d_in[7];
    const float* wo_s = (const float*)d_in[8];
    const float* bo_s = (const float*)d_in[9];
    const float* wq_c = (const float*)d_in[10];
    const float* bq_c = (const float*)d_in[11];
    const float* wk_c = (const float*)d_in[12];
    const float* bk_c = (const float*)d_in[13];
    const float* wv_c = (const float*)d_in[14];
    const float* bv_c = (const float*)d_in[15];
    const float* wo_c = (const float*)d_in[16];
    const float* bo_c = (const float*)d_in[17];
    const float* ln1_g = (const float*)d_in[18];
    const float* ln1_b = (const float*)d_in[19];
    const float* ln2_g = (const float*)d_in[20];
    const float* ln2_b = (const float*)d_in[21];
    const float* ln3_g = (const float*)d_in[22];
    const float* ln3_b = (const float*)d_in[23];
    const float* fc1_w = (const float*)d_in[24];
    const float* fc1_b = (const float*)d_in[25];
    const float* fc2_w = (const float*)d_in[26];
    const float* fc2_b = (const float*)d_in[27];
    float* out = (float*)d_out;

    float *p_h, *p_q, *p_k, *p_v, *p_attn, *p_ff;
    __nv_bfloat16 *p_a3, *p_w3;
    cudaGetSymbolAddress((void**)&p_h,    g_h);
    cudaGetSymbolAddress((void**)&p_q,    g_q);
    cudaGetSymbolAddress((void**)&p_k,    g_k);
    cudaGetSymbolAddress((void**)&p_v,    g_v);
    cudaGetSymbolAddress((void**)&p_attn, g_attn);
    cudaGetSymbolAddress((void**)&p_ff,   g_ff);
    cudaGetSymbolAddress((void**)&p_a3,   g_a3);
    cudaGetSymbolAddress((void**)&p_w3,   g_w3);

    cudaFuncSetAttribute(gemm_mma<0>, cudaFuncAttributeMaxDynamicSharedMemorySize, GSMEM);
    cudaFuncSetAttribute(gemm_mma<1>, cudaFuncAttributeMaxDynamicSharedMemorySize, GSMEM);
    cudaFuncSetAttribute(gemm_mma<2>, cudaFuncAttributeMaxDynamicSharedMemorySize, GSMEM);

    dim3 agrid(LL / 64, NN * HH);   // 16 x 64

    // ---- block 1: self-attention ----
    ln_kernel<<<MM, 256>>>(x, ln1_g, ln1_b, p_h);
    split_a(p_h, p_a3, MM, EE);
    tc_gemm(0, MM, EE, EE, p_a3, wq_s, bq_s, nullptr, p_q, p_w3);
    tc_gemm(0, MM, EE, EE, p_a3, wk_s, bk_s, nullptr, p_k, p_w3);
    tc_gemm(0, MM, EE, EE, p_a3, wv_s, bv_s, nullptr, p_v, p_w3);
    attn_mma<<<agrid, 128>>>(p_q, p_k, p_v, p_attn);
    split_a(p_attn, p_a3, MM, EE);
    tc_gemm(1, MM, EE, EE, p_a3, wo_s, bo_s, x, out, p_w3);

    // ---- block 2: cross-attention (reference applies causal mask here too) ----
    ln_kernel<<<MM, 256>>>(out, ln2_g, ln2_b, p_h);
    split_a(p_h, p_a3, MM, EE);
    tc_gemm(0, MM, EE, EE, p_a3, wq_c, bq_c, nullptr, p_q, p_w3);
    split_a(enc, p_a3, MM, EE);
    tc_gemm(0, MM, EE, EE, p_a3, wk_c, bk_c, nullptr, p_k, p_w3);
    tc_gemm(0, MM, EE, EE, p_a3, wv_c, bv_c, nullptr, p_v, p_w3);
    attn_mma<<<agrid, 128>>>(p_q, p_k, p_v, p_attn);
    split_a(p_attn, p_a3, MM, EE);
    tc_gemm(1, MM, EE, EE, p_a3, wo_c, bo_c, out, out, p_w3);

    // ---- block 3: FFN ----
    ln_kernel<<<MM, 256>>>(out, ln3_g, ln3_b, p_h);
    split_a(p_h, p_a3, MM, EE);
    tc_gemm(2, MM, FF, EE, p_a3, fc1_w, fc1_b, nullptr, p_ff, p_w3);
    split_a(p_ff, p_a3, MM, FF);
    tc_gemm(1, MM, EE, FF, p_a3, fc2_w, fc2_b, out, out, p_w3);
}

// round 7
// speedup vs baseline: 3.9451x; 1.3892x over previous
#include <cuda_runtime.h>
#include <cuda_bf16.h>
#include <math.h>
#include <stdint.h>

// Problem constants: L=1024, N=4, E=1024, F=4096, H=16, d=64
#define LL 1024
#define NN 4
#define EE 1024
#define FF 4096
#define HH 16
#define HD 64
#define MM (LL*NN)   // 4096 rows

// ---------------- scratch (static device allocations) ----------------
__device__ float g_h[MM*EE];                       // layernorm output
__device__ float g_q[MM*EE];                       // cross-attn q
__device__ float g_attn[MM*EE];                    // attention output
__device__ float g_ff[(size_t)MM*FF];              // fused qkv/kv out; fc1 out
__device__ __nv_bfloat16 g_a3[(size_t)MM * 3 * FF];   // A: bf16 1-term or 3-term split
__device__ __nv_bfloat16 g_w3[(size_t)FF * 3 * EE];   // W: bf16 1-term or 3-term split
__device__ float g_bcat[3*EE];                     // concatenated bias

// ---------------- portable PTX helpers -------
__device__ __forceinline__ uint32_t smem_u32(const void* p) {
    uint32_t a;
    asm("{ .reg .u64 t; cvta.to.shared.u64 t, %1; cvt.u32.u64 %0, t; }" : "=r"(a) : "l"(p));
    return a;
}

#define SWZ(x) ((x) ^ (((x) >> 3) & 0x70))

#define CP_ASYNC16(dst_u32, src_ptr) \
    asm volatile("cp.async.cg.shared.global [%0], [%1], 16;" \
        :: "r"(dst_u32), "l"(src_ptr) : "memory")
#define CP_COMMIT() asm volatile("cp.async.commit_group;" ::: "memory")
#define CP_WAIT1()  asm volatile("cp.async.wait_group 1;" ::: "memory")
#define CP_WAIT0()  asm volatile("cp.async.wait_group 0;" ::: "memory")

__device__ __forceinline__ void ldsm_x4(uint32_t& r0, uint32_t& r1, uint32_t& r2, uint32_t& r3,
                                        uint32_t addr) {
    asm volatile("ldmatrix.sync.aligned.m8n8.x4.shared.b16 {%0,%1,%2,%3}, [%4];"
        : "=r"(r0), "=r"(r1), "=r"(r2), "=r"(r3) : "r"(addr));
}
__device__ __forceinline__ void ldsm_x2(uint32_t& r0, uint32_t& r1, uint32_t addr) {
    asm volatile("ldmatrix.sync.aligned.m8n8.x2.shared.b16 {%0,%1}, [%2];"
        : "=r"(r0), "=r"(r1) : "r"(addr));
}
__device__ __forceinline__ void mma_bf16(float* d, const uint32_t* a, const uint32_t* b) {
    asm volatile("mma.sync.aligned.m16n8k16.row.col.f32.bf16.bf16.f32 "
        "{%0,%1,%2,%3}, {%4,%5,%6,%7}, {%8,%9}, {%0,%1,%2,%3};"
        : "+f"(d[0]), "+f"(d[1]), "+f"(d[2]), "+f"(d[3])
        : "r"(a[0]), "r"(a[1]), "r"(a[2]), "r"(a[3]), "r"(b[0]), "r"(b[1]));
}
__device__ __forceinline__ uint32_t pack_bf16x2(float x, float y) {
    __nv_bfloat162 h = __floats2bfloat162_rn(x, y);
    return *(uint32_t*)&h;
}

// ---------------- layernorm ----------------
__global__ void ln_kernel(const float* __restrict__ x, const float* __restrict__ g,
                          const float* __restrict__ b, float* __restrict__ y) {
    int row = blockIdx.x;
    int tid = threadIdx.x;
    const float4* xr = (const float4*)(x + (size_t)row * EE);
    float4 v = xr[tid];
    float s  = v.x + v.y + v.z + v.w;
    float sq = v.x*v.x + v.y*v.y + v.z*v.z + v.w*v.w;
    #pragma unroll
    for (int off = 16; off > 0; off >>= 1) {
        s  += __shfl_down_sync(0xffffffffu, s,  off);
        sq += __shfl_down_sync(0xffffffffu, sq, off);
    }
    __shared__ float rs[8], rq[8];
    __shared__ float s_mean, s_rstd;
    int lane = tid & 31, wid = tid >> 5;
    if (lane == 0) { rs[wid] = s; rq[wid] = sq; }
    __syncthreads();
    if (tid == 0) {
        float ts = 0.f, tq = 0.f;
        #pragma unroll
        for (int i = 0; i < 8; i++) { ts += rs[i]; tq += rq[i]; }
        float mean = ts * (1.0f / EE);
        float var  = tq * (1.0f / EE) - mean * mean;
        s_mean = mean;
        s_rstd = rsqrtf(var + 1e-5f);
    }
    __syncthreads();
    float mean = s_mean, rstd = s_rstd;
    const float4* gr = (const float4*)g;
    const float4* br = (const float4*)b;
    float4 gv = gr[tid], bv = br[tid];
    float4 o;
    o.x = (v.x - mean) * rstd * gv.x + bv.x;
    o.y = (v.y - mean) * rstd * gv.y + bv.y;
    o.z = (v.z - mean) * rstd * gv.z + bv.z;
    o.w = (v.w - mean) * rstd * gv.w + bv.w;
    ((float4*)(y + (size_t)row * EE))[tid] = o;
}

// ---------------- fp32 -> plain bf16 (1-term) ----------------
__global__ void conv1_kernel(const float* __restrict__ X, __nv_bfloat16* __restrict__ Y,
                             int total4) {
    int idx = blockIdx.x * blockDim.x + threadIdx.x;
    if (idx >= total4) return;
    float4 v = ((const float4*)X)[idx];
    uint2 pk;
    pk.x = pack_bf16x2(v.x, v.y);
    pk.y = pack_bf16x2(v.z, v.w);
    ((uint2*)Y)[idx] = pk;
}

// ---------------- fp32 -> 3-segment bf16 split ----------------
__global__ void split3_kernel(const float* __restrict__ X, __nv_bfloat16* __restrict__ Y,
                              int K, int total4, int border) {
    int idx = blockIdx.x * blockDim.x + threadIdx.x;
    if (idx >= total4) return;
    int kq = K >> 2;
    int r  = idx / kq;
    int k  = (idx - r * kq) << 2;
    float4 v = *(const float4*)(X + (size_t)r * K + k);
    float f[4] = {v.x, v.y, v.z, v.w};
    union { __nv_bfloat16 b[4]; uint2 u; } H, L;
    #pragma unroll
    for (int i = 0; i < 4; i++) {
        H.b[i] = __float2bfloat16(f[i]);
        L.b[i] = __float2bfloat16(f[i] - __bfloat162float(H.b[i]));
    }
    size_t base = (size_t)r * 3 * K + k;
    *(uint2*)(Y + base)         = H.u;
    *(uint2*)(Y + base + K)     = border ? H.u : L.u;
    *(uint2*)(Y + base + 2*K)   = border ? L.u : H.u;
}

// ---------------- bias concatenation ----------------
__global__ void biascat_kernel(const float* __restrict__ b0, const float* __restrict__ b1,
                               const float* __restrict__ b2, float* __restrict__ out) {
    int seg = blockIdx.x;
    const float* src = seg == 0 ? b0 : (seg == 1 ? b1 : b2);
    out[seg * 1024 + threadIdx.x] = src[threadIdx.x];
}

// ---------------- HMMA bf16 GEMM (3-stage cp.async pipeline) ----
#define GBM 128
#define GBN 128
#define GBK 64
#define AST (GBM*128)
#define GSTAGE (AST + GBN*128)      // 32768
#define GSMEM (3*GSTAGE + 1024)

template<int EPI>
__global__ void __launch_bounds__(256, 1)
gemm_mma(const __nv_bfloat16* __restrict__ A, const __nv_bfloat16* __restrict__ B,
         const float* __restrict__ bias, const float* __restrict__ R,
         float* __restrict__ C, int M, int N, int K3) {
    extern __shared__ char dyn_smem[];
    const int tid  = threadIdx.x;
    const int lane = tid & 31;
    const int wid  = tid >> 5;
    const int wm   = wid & 1;
    const int wn   = wid >> 1;
    const int bm = blockIdx.y * GBM;
    const int bn = blockIdx.x * GBN;

    uint32_t raw = smem_u32(dyn_smem);
    uint32_t sb  = (raw + 1023u) & ~1023u;

    const size_t ldb = (size_t)K3 * 2;
    const char* Abase = (const char*)(A + (size_t)bm * K3);
    const char* Bbase = (const char*)(B + (size_t)bn * K3);

    auto issue_stage = [&](int kt, int s) {
        uint32_t dst = sb + s * GSTAGE;
        const char* Ab = Abase + (size_t)kt * (GBK * 2);
        const char* Bb = Bbase + (size_t)kt * (GBK * 2);
        #pragma unroll
        for (int p = 0; p < 4; p++) {
            int g   = (p << 8) + tid;
            int row = g >> 3;
            int seg = (g & 7) << 4;
            uint32_t off = SWZ(row * 128 + seg);
            CP_ASYNC16(dst + off,       Ab + (size_t)row * ldb + seg);
            CP_ASYNC16(dst + AST + off, Bb + (size_t)row * ldb + seg);
        }
        CP_COMMIT();
    };

    float acc[4][4][4];
    #pragma unroll
    for (int i = 0; i < 4; i++)
        #pragma unroll
        for (int j = 0; j < 4; j++)
            #pragma unroll
            for (int t = 0; t < 4; t++) acc[i][j][t] = 0.f;

    const int nk = K3 / GBK;
    issue_stage(0, 0);
    issue_stage(1, 1);

    const int a_row = wm * 64 + (lane & 15);
    const int a_kb  = (lane >> 4) << 4;
    // paired B ldsm: x4 loads two adjacent n8 tiles (lanes 0-15 tile 2j, 16-31 tile 2j+1)
    const int bp_row = wn * 32 + ((lane >> 4) << 3) + (lane & 7);
    const int bp_kb  = (((lane >> 3) & 1) << 4);

    for (int kt = 0; kt < nk; kt++) {
        if (kt + 1 < nk) { CP_WAIT1(); } else { CP_WAIT0(); }
        __syncthreads();
        if (kt + 2 < nk) issue_stage(kt + 2, (kt + 2) % 3);

        uint32_t ab = sb + (kt % 3) * GSTAGE;
        uint32_t bb = ab + AST;
        #pragma unroll
        for (int kk = 0; kk < 4; kk++) {
            uint32_t af[4][4], bfr[4][2];
            #pragma unroll
            for (int i = 0; i < 4; i++)
                ldsm_x4(af[i][0], af[i][1], af[i][2], af[i][3],
                        ab + SWZ((a_row + i*16) * 128 + kk*32 + a_kb));
            #pragma unroll
            for (int j = 0; j < 2; j++)
                ldsm_x4(bfr[2*j][0], bfr[2*j][1], bfr[2*j+1][0], bfr[2*j+1][1],
                        bb + SWZ((bp_row + j*16) * 128 + kk*32 + bp_kb));
            #pragma unroll
            for (int i = 0; i < 4; i++)
                #pragma unroll
                for (int j = 0; j < 4; j++)
                    mma_bf16(acc[i][j], af[i], bfr[j]);
        }
    }

    const int er = (lane >> 2);
    const int ec = (lane & 3) << 1;
    #pragma unroll
    for (int i = 0; i < 4; i++) {
        #pragma unroll
        for (int j = 0; j < 4; j++) {
            int col = bn + wn*32 + j*8 + ec;
            float bx = bias[col], by = bias[col + 1];
            #pragma unroll
            for (int h = 0; h < 2; h++) {
                int row = bm + wm*64 + i*16 + er + h*8;
                float vx = acc[i][j][h*2 + 0] + bx;
                float vy = acc[i][j][h*2 + 1] + by;
                if (EPI == 1) {
                    const float2 rr = *(const float2*)(R + (size_t)row * N + col);
                    vx += rr.x; vy += rr.y;
                }
                if (EPI == 2) {
                    vx = 0.5f * vx * (1.0f + erff(vx * 0.70710678118654752f));
                    vy = 0.5f * vy * (1.0f + erff(vy * 0.70710678118654752f));
                }
                *(float2*)(C + (size_t)row * N + col) = make_float2(vx, vy);
            }
        }
    }
}

// ---------------- HMMA flash attention (causal always per reference) ----
// Strided operands so q/k/v can live in fused projection outputs.
__global__ void __launch_bounds__(128)
attn_mma(const float* __restrict__ Q, int ldq, const float* __restrict__ Kp, int ldk,
         const float* __restrict__ Vp, int ldv, float* __restrict__ O) {
    __shared__ __nv_bfloat16 Qs[64*64];
    __shared__ __nv_bfloat16 Ks[64*64];
    __shared__ __nv_bfloat16 Vt[64*64];   // [d][kv]

    const int b = blockIdx.y, qi = blockIdx.x;
    const int n = b >> 4, hh = b & 15;
    const int tid = threadIdx.x, lane = tid & 31, w = tid >> 5;
    const int qbase = qi * 64;
    const uint32_t qs = smem_u32(Qs), ks = smem_u32(Ks), vt = smem_u32(Vt);

    for (int i = tid; i < 64*16; i += 128) {
        int rr = i >> 4, seg = (i & 15) << 2;
        float4 v = *(const float4*)(Q + (size_t)((qbase+rr)*NN + n) * ldq + hh*HD + seg);
        uint2 pk;
        pk.x = pack_bf16x2(v.x*0.125f, v.y*0.125f);
        pk.y = pack_bf16x2(v.z*0.125f, v.w*0.125f);
        *(uint2*)((char*)Qs + SWZ(rr*128 + seg*2)) = pk;
    }

    const int r  = lane >> 2;
    const int cb = (lane & 3) << 1;

    float m0 = -1e30f, m1 = -1e30f, l0 = 0.f, l1 = 0.f;
    float oac[8][4];
    #pragma unroll
    for (int t = 0; t < 8; t++)
        #pragma unroll
        for (int e = 0; e < 4; e++) oac[t][e] = 0.f;

    for (int j = 0; j <= qi; j++) {
        __syncthreads();
        for (int i = tid; i < 64*16; i += 128) {
            int rr = i >> 4, seg = (i & 15) << 2;
            float4 kv = *(const float4*)(Kp + (size_t)((j*64+rr)*NN + n) * ldk + hh*HD + seg);
            uint2 pk;
            pk.x = pack_bf16x2(kv.x, kv.y);
            pk.y = pack_bf16x2(kv.z, kv.w);
            *(uint2*)((char*)Ks + SWZ(rr*128 + seg*2)) = pk;
            float4 vv = *(const float4*)(Vp + (size_t)((j*64+rr)*NN + n) * ldv + hh*HD + seg);
            *(__nv_bfloat16*)((char*)Vt + SWZ((seg+0)*128 + rr*2)) = __float2bfloat16(vv.x);
            *(__nv_bfloat16*)((char*)Vt + SWZ((seg+1)*128 + rr*2)) = __float2bfloat16(vv.y);
            *(__nv_bfloat16*)((char*)Vt + SWZ((seg+2)*128 + rr*2)) = __float2bfloat16(vv.z);
            *(__nv_bfloat16*)((char*)Vt + SWZ((seg+3)*128 + rr*2)) = __float2bfloat16(vv.w);
        }
        __syncthreads();

        uint32_t af[4][4];
        #pragma unroll
        for (int kk = 0; kk < 4; kk++)
            ldsm_x4(af[kk][0], af[kk][1], af[kk][2], af[kk][3],
                    qs + SWZ((w*16 + (lane & 15))*128 + kk*32 + ((lane >> 4) << 4)));

        float sac[8][4];
        #pragma unroll
        for (int t = 0; t < 8; t++) {
            sac[t][0] = sac[t][1] = sac[t][2] = sac[t][3] = 0.f;
            #pragma unroll
            for (int kk = 0; kk < 4; kk++) {
                uint32_t bfr[2];
                ldsm_x2(bfr[0], bfr[1],
                        ks + SWZ((t*8 + (lane & 7))*128 + kk*32 + (((lane >> 3) & 1) << 4)));
                mma_bf16(sac[t], af[kk], bfr);
            }
        }

        if (j == qi) {
            int grow0 = qbase + w*16 + r;
            int grow1 = grow0 + 8;
            #pragma unroll
            for (int t = 0; t < 8; t++) {
                int gc = j*64 + t*8 + cb;
                if (gc     > grow0) sac[t][0] = -10000.0f;
                if (gc + 1 > grow0) sac[t][1] = -10000.0f;
                if (gc     > grow1) sac[t][2] = -10000.0f;
                if (gc + 1 > grow1) sac[t][3] = -10000.0f;
            }
        }

        float mx0 = -1e30f, mx1 = -1e30f;
        #pragma unroll
        for (int t = 0; t < 8; t++) {
            mx0 = fmaxf(mx0, fmaxf(sac[t][0], sac[t][1]));
            mx1 = fmaxf(mx1, fmaxf(sac[t][2], sac[t][3]));
        }
        mx0 = fmaxf(mx0, __shfl_xor_sync(0xffffffffu, mx0, 1));
        mx0 = fmaxf(mx0, __shfl_xor_sync(0xffffffffu, mx0, 2));
        mx1 = fmaxf(mx1, __shfl_xor_sync(0xffffffffu, mx1, 1));
        mx1 = fmaxf(mx1, __shfl_xor_sync(0xffffffffu, mx1, 2));
        float mn0 = fmaxf(m0, mx0), mn1 = fmaxf(m1, mx1);
        float al0 = __expf(m0 - mn0), al1 = __expf(m1 - mn1);
        float ls0 = 0.f, ls1 = 0.f;
        #pragma unroll
        for (int t = 0; t < 8; t++) {
            sac[t][0] = __expf(sac[t][0] - mn0);
            sac[t][1] = __expf(sac[t][1] - mn0);
            sac[t][2] = __expf(sac[t][2] - mn1);
            sac[t][3] = __expf(sac[t][3] - mn1);
            ls0 += sac[t][0] + sac[t][1];
            ls1 += sac[t][2] + sac[t][3];
        }
        ls0 += __shfl_xor_sync(0xffffffffu, ls0, 1);
        ls0 += __shfl_xor_sync(0xffffffffu, ls0, 2);
        ls1 += __shfl_xor_sync(0xffffffffu, ls1, 1);
        ls1 += __shfl_xor_sync(0xffffffffu, ls1, 2);
        l0 = l0 * al0 + ls0;  m0 = mn0;
        l1 = l1 * al1 + ls1;  m1 = mn1;
        #pragma unroll
        for (int t = 0; t < 8; t++) {
            oac[t][0] *= al0; oac[t][1] *= al0;
            oac[t][2] *= al1; oac[t][3] *= al1;
        }

        uint32_t pf[4][4];
        #pragma unroll
        for (int kt = 0; kt < 4; kt++) {
            pf[kt][0] = pack_bf16x2(sac[2*kt][0],   sac[2*kt][1]);
            pf[kt][1] = pack_bf16x2(sac[2*kt][2],   sac[2*kt][3]);
            pf[kt][2] = pack_bf16x2(sac[2*kt+1][0], sac[2*kt+1][1]);
            pf[kt][3] = pack_bf16x2(sac[2*kt+1][2], sac[2*kt+1][3]);
        }

        #pragma unroll
        for (int td = 0; td < 8; td++) {
            #pragma unroll
            for (int kt = 0; kt < 4; kt++) {
                uint32_t bfr[2];
                ldsm_x2(bfr[0], bfr[1],
                        vt + SWZ((td*8 + (lane & 7))*128 + kt*32 + (((lane >> 3) & 1) << 4)));
                mma_bf16(oac[td], pf[kt], bfr);
            }
        }
    }

    float inv0 = 1.0f / l0, inv1 = 1.0f / l1;
    int row0 = qbase + w*16 + r;
    int row1 = row0 + 8;
    #pragma unroll
    for (int td = 0; td < 8; td++) {
        int col = td*8 + cb;
        *(float2*)(O + ((size_t)(row0*NN + n) << 10) + hh*HD + col) =
            make_float2(oac[td][0]*inv0, oac[td][1]*inv0);
        *(float2*)(O + ((size_t)(row1*NN + n) << 10) + hh*HD + col) =
            make_float2(oac[td][2]*inv1, oac[td][3]*inv1);
    }
}

// ---------------- orchestration ----------------
static void conv1(const float* X, __nv_bfloat16* Y, size_t elems) {
    int t4 = (int)(elems / 4);
    conv1_kernel<<<(t4 + 255) / 256, 256>>>(X, Y, t4);
}
static void split3(const float* X, __nv_bfloat16* Y, int rows, int K, int border) {
    int t4 = rows * K / 4;
    split3_kernel<<<(t4 + 255) / 256, 256>>>(X, Y, K, t4, border);
}
static void run_gemm(int epi, const __nv_bfloat16* A, const __nv_bfloat16* B,
                     const float* bias, const float* R, float* C,
                     int M_, int N_, int K3) {
    dim3 grid(N_ / GBN, M_ / GBM);
    if (epi == 0)      gemm_mma<0><<<grid, 256, GSMEM>>>(A, B, bias, R, C, M_, N_, K3);
    else if (epi == 1) gemm_mma<1><<<grid, 256, GSMEM>>>(A, B, bias, R, C, M_, N_, K3);
    else               gemm_mma<2><<<grid, 256, GSMEM>>>(A, B, bias, R, C, M_, N_, K3);
}

extern "C" void kernel_launch(void* const* d_in, const int* in_sizes, int n_in,
                              void* d_out, int out_size) {
    const float* x    = (const float*)d_in[0];
    const float* enc  = (const float*)d_in[1];
    const float* wq_s = (const float*)d_in[2];
    const float* bq_s = (const float*)d_in[3];
    const float* wk_s = (const float*)d_in[4];
    const float* bk_s = (const float*)d_in[5];
    const float* wv_s = (const float*)d_in[6];
    const float* bv_s = (const float*)d_in[7];
    const float* wo_s = (const float*)d_in[8];
    const float* bo_s = (const float*)d_in[9];
    const float* wq_c = (const float*)d_in[10];
    const float* bq_c = (const float*)d_in[11];
    const float* wk_c = (const float*)d_in[12];
    const float* bk_c = (const float*)d_in[13];
    const float* wv_c = (const float*)d_in[14];
    const float* bv_c = (const float*)d_in[15];
    const float* wo_c = (const float*)d_in[16];
    const float* bo_c = (const float*)d_in[17];
    const float* ln1_g = (const float*)d_in[18];
    const float* ln1_b = (const float*)d_in[19];
    const float* ln2_g = (const float*)d_in[20];
    const float* ln2_b = (const float*)d_in[21];
    const float* ln3_g = (const float*)d_in[22];
    const float* ln3_b = (const float*)d_in[23];
    const float* fc1_w = (const float*)d_in[24];
    const float* fc1_b = (const float*)d_in[25];
    const float* fc2_w = (const float*)d_in[26];
    const float* fc2_b = (const float*)d_in[27];
    float* out = (float*)d_out;

    float *p_h, *p_q, *p_attn, *p_ff, *p_bcat;
    __nv_bfloat16 *p_a3, *p_w3;
    cudaGetSymbolAddress((void**)&p_h,    g_h);
    cudaGetSymbolAddress((void**)&p_q,    g_q);
    cudaGetSymbolAddress((void**)&p_attn, g_attn);
    cudaGetSymbolAddress((void**)&p_ff,   g_ff);
    cudaGetSymbolAddress((void**)&p_a3,   g_a3);
    cudaGetSymbolAddress((void**)&p_w3,   g_w3);
    cudaGetSymbolAddress((void**)&p_bcat, g_bcat);

    cudaFuncSetAttribute(gemm_mma<0>, cudaFuncAttributeMaxDynamicSharedMemorySize, GSMEM);
    cudaFuncSetAttribute(gemm_mma<1>, cudaFuncAttributeMaxDynamicSharedMemorySize, GSMEM);
    cudaFuncSetAttribute(gemm_mma<2>, cudaFuncAttributeMaxDynamicSharedMemorySize, GSMEM);

    dim3 agrid(LL / 64, NN * HH);   // 16 x 64
    const size_t W1 = (size_t)EE * EE;   // one 1024x1024 weight

    // ---- block 1: self-attention (fused QKV, 1-term bf16) ----
    ln_kernel<<<MM, 256>>>(x, ln1_g, ln1_b, p_h);
    conv1(p_h, p_a3, (size_t)MM * EE);
    conv1(wq_s, p_w3,         W1);
    conv1(wk_s, p_w3 + W1,    W1);
    conv1(wv_s, p_w3 + 2*W1,  W1);
    biascat_kernel<<<3, 1024>>>(bq_s, bk_s, bv_s, p_bcat);
    run_gemm(0, p_a3, p_w3, p_bcat, nullptr, p_ff, MM, 3*EE, EE);
    attn_mma<<<agrid, 128>>>(p_ff, 3*EE, p_ff + EE, 3*EE, p_ff + 2*EE, 3*EE, p_attn);
    conv1(p_attn, p_a3, (size_t)MM * EE);
    conv1(wo_s, p_w3, W1);
    run_gemm(1, p_a3, p_w3, bo_s, x, out, MM, EE, EE);

    // ---- block 2: cross-attention (reference applies causal mask here too) ----
    ln_kernel<<<MM, 256>>>(out, ln2_g, ln2_b, p_h);
    conv1(p_h, p_a3, (size_t)MM * EE);
    conv1(wq_c, p_w3, W1);
    run_gemm(0, p_a3, p_w3, bq_c, nullptr, p_q, MM, EE, EE);
    conv1(enc, p_a3, (size_t)MM * EE);
    conv1(wk_c, p_w3,      W1);
    conv1(wv_c, p_w3 + W1, W1);
    biascat_kernel<<<2, 1024>>>(bk_c, bv_c, nullptr, p_bcat);
    run_gemm(0, p_a3, p_w3, p_bcat, nullptr, p_ff, MM, 2*EE, EE);
    attn_mma<<<agrid, 128>>>(p_q, EE, p_ff, 2*EE, p_ff + EE, 2*EE, p_attn);
    conv1(p_attn, p_a3, (size_t)MM * EE);
    conv1(wo_c, p_w3, W1);
    run_gemm(1, p_a3, p_w3, bo_c, out, out, MM, EE, EE);

    // ---- block 3: FFN (3-term split for accuracy) ----
    ln_kernel<<<MM, 256>>>(out, ln3_g, ln3_b, p_h);
    split3(p_h, p_a3, MM, EE, 0);
    split3(fc1_w, p_w3, FF, EE, 1);
    run_gemm(2, p_a3, p_w3, fc1_b, nullptr, p_ff, MM, FF, 3*EE);
    split3(p_ff, p_a3, MM, FF, 0);
    split3(fc2_w, p_w3, EE, FF, 1);
    run_gemm(1, p_a3, p_w3, fc2_b, out, out, MM, EE, 3*FF);
}

// round 9
// speedup vs baseline: 3.9999x; 1.0139x over previous
#include <cuda_runtime.h>
#include <cuda_bf16.h>
#include <math.h>
#include <stdint.h>

// Problem constants: L=1024, N=4, E=1024, F=4096, H=16, d=64
#define LL 1024
#define NN 4
#define EE 1024
#define FF 4096
#define HH 16
#define HD 64
#define MM (LL*NN)   // 4096 rows

// ---------------- scratch (static device allocations) ----------------
__device__ float g_q[MM*EE];                            // cross-attn q (fp32)
__device__ float g_ff[(size_t)MM*FF];                   // fused qkv/kv GEMM out (fp32)
__device__ __nv_bfloat16 g_a3[(size_t)MM * 3 * EE];     // LN splits / attn out / enc bf16
__device__ __nv_bfloat16 g_w3[(size_t)FF * 3 * EE];     // weight bf16 buffers
__device__ __nv_bfloat16 g_gelu3[(size_t)MM * 3 * FF];  // gelu 3-term split (fc2 A operand)
__device__ float g_bcat[3*EE];                          // concatenated bias

// ---------------- portable PTX helpers -------
__device__ __forceinline__ uint32_t smem_u32(const void* p) {
    uint32_t a;
    asm("{ .reg .u64 t; cvta.to.shared.u64 t, %1; cvt.u32.u64 %0, t; }" : "=r"(a) : "l"(p));
    return a;
}

#define SWZ(x) ((x) ^ (((x) >> 3) & 0x70))

#define CP_ASYNC16(dst_u32, src_ptr) \
    asm volatile("cp.async.cg.shared.global [%0], [%1], 16;" \
        :: "r"(dst_u32), "l"(src_ptr) : "memory")
#define CP_COMMIT() asm volatile("cp.async.commit_group;" ::: "memory")
#define CP_WAIT1()  asm volatile("cp.async.wait_group 1;" ::: "memory")
#define CP_WAIT0()  asm volatile("cp.async.wait_group 0;" ::: "memory")

__device__ __forceinline__ void ldsm_x4(uint32_t& r0, uint32_t& r1, uint32_t& r2, uint32_t& r3,
                                        uint32_t addr) {
    asm volatile("ldmatrix.sync.aligned.m8n8.x4.shared.b16 {%0,%1,%2,%3}, [%4];"
        : "=r"(r0), "=r"(r1), "=r"(r2), "=r"(r3) : "r"(addr));
}
__device__ __forceinline__ void ldsm_x2(uint32_t& r0, uint32_t& r1, uint32_t addr) {
    asm volatile("ldmatrix.sync.aligned.m8n8.x2.shared.b16 {%0,%1}, [%2];"
        : "=r"(r0), "=r"(r1) : "r"(addr));
}
__device__ __forceinline__ void mma_bf16(float* d, const uint32_t* a, const uint32_t* b) {
    asm volatile("mma.sync.aligned.m16n8k16.row.col.f32.bf16.bf16.f32 "
        "{%0,%1,%2,%3}, {%4,%5,%6,%7}, {%8,%9}, {%0,%1,%2,%3};"
        : "+f"(d[0]), "+f"(d[1]), "+f"(d[2]), "+f"(d[3])
        : "r"(a[0]), "r"(a[1]), "r"(a[2]), "r"(a[3]), "r"(b[0]), "r"(b[1]));
}
__device__ __forceinline__ uint32_t pack_bf16x2(float x, float y) {
    __nv_bfloat162 h = __floats2bfloat162_rn(x, y);
    return *(uint32_t*)&h;
}

// ---------------- layernorm core ----------------
__device__ __forceinline__ void ln_core(const float* __restrict__ x, int row, int tid,
                                        float4& v, float& mean, float& rstd) {
    const float4* xr = (const float4*)(x + (size_t)row * EE);
    v = xr[tid];
    float s  = v.x + v.y + v.z + v.w;
    float sq = v.x*v.x + v.y*v.y + v.z*v.z + v.w*v.w;
    #pragma unroll
    for (int off = 16; off > 0; off >>= 1) {
        s  += __shfl_down_sync(0xffffffffu, s,  off);
        sq += __shfl_down_sync(0xffffffffu, sq, off);
    }
    __shared__ float rs[8], rq[8];
    __shared__ float s_mean, s_rstd;
    int lane = tid & 31, wid = tid >> 5;
    if (lane == 0) { rs[wid] = s; rq[wid] = sq; }
    __syncthreads();
    if (tid == 0) {
        float ts = 0.f, tq = 0.f;
        #pragma unroll
        for (int i = 0; i < 8; i++) { ts += rs[i]; tq += rq[i]; }
        float mn = ts * (1.0f / EE);
        float var = tq * (1.0f / EE) - mn * mn;
        s_mean = mn;
        s_rstd = rsqrtf(var + 1e-5f);
    }
    __syncthreads();
    mean = s_mean; rstd = s_rstd;
}

// LN -> 1-term bf16 (row stride EE)
__global__ void ln_bf16_kernel(const float* __restrict__ x, const float* __restrict__ g,
                               const float* __restrict__ b, __nv_bfloat16* __restrict__ y) {
    int row = blockIdx.x, tid = threadIdx.x;
    float4 v; float mean, rstd;
    ln_core(x, row, tid, v, mean, rstd);
    float4 gv = ((const float4*)g)[tid], bv = ((const float4*)b)[tid];
    float ox = (v.x - mean) * rstd * gv.x + bv.x;
    float oy = (v.y - mean) * rstd * gv.y + bv.y;
    float oz = (v.z - mean) * rstd * gv.z + bv.z;
    float ow = (v.w - mean) * rstd * gv.w + bv.w;
    uint2 pk; pk.x = pack_bf16x2(ox, oy); pk.y = pack_bf16x2(oz, ow);
    *(uint2*)(y + (size_t)row * EE + tid * 4) = pk;
}

// LN -> 3-term split [hi | lo | hi] (row stride 3*EE)
__global__ void ln_split3_kernel(const float* __restrict__ x, const float* __restrict__ g,
                                 const float* __restrict__ b, __nv_bfloat16* __restrict__ y) {
    int row = blockIdx.x, tid = threadIdx.x;
    float4 v; float mean, rstd;
    ln_core(x, row, tid, v, mean, rstd);
    float4 gv = ((const float4*)g)[tid], bv = ((const float4*)b)[tid];
    float f[4];
    f[0] = (v.x - mean) * rstd * gv.x + bv.x;
    f[1] = (v.y - mean) * rstd * gv.y + bv.y;
    f[2] = (v.z - mean) * rstd * gv.z + bv.z;
    f[3] = (v.w - mean) * rstd * gv.w + bv.w;
    union { __nv_bfloat16 h[4]; uint2 u; } H, L;
    #pragma unroll
    for (int i = 0; i < 4; i++) {
        H.h[i] = __float2bfloat16(f[i]);
        L.h[i] = __float2bfloat16(f[i] - __bfloat162float(H.h[i]));
    }
    size_t base = (size_t)row * 3 * EE + tid * 4;
    *(uint2*)(y + base)        = H.u;
    *(uint2*)(y + base + EE)   = L.u;
    *(uint2*)(y + base + 2*EE) = H.u;
}

// fp32 -> plain bf16 (1-term)
__global__ void conv1_kernel(const float* __restrict__ X, __nv_bfloat16* __restrict__ Y,
                             int total4) {
    int idx = blockIdx.x * blockDim.x + threadIdx.x;
    if (idx >= total4) return;
    float4 v = ((const float4*)X)[idx];
    uint2 pk;
    pk.x = pack_bf16x2(v.x, v.y);
    pk.y = pack_bf16x2(v.z, v.w);
    ((uint2*)Y)[idx] = pk;
}

// weight -> 3-term split [hi | hi | lo] (row stride 3K)
__global__ void split3w_kernel(const float* __restrict__ X, __nv_bfloat16* __restrict__ Y,
                               int K, int total4) {
    int idx = blockIdx.x * blockDim.x + threadIdx.x;
    if (idx >= total4) return;
    int kq = K >> 2;
    int r  = idx / kq;
    int k  = (idx - r * kq) << 2;
    float4 v = *(const float4*)(X + (size_t)r * K + k);
    float f[4] = {v.x, v.y, v.z, v.w};
    union { __nv_bfloat16 b[4]; uint2 u; } H, L;
    #pragma unroll
    for (int i = 0; i < 4; i++) {
        H.b[i] = __float2bfloat16(f[i]);
        L.b[i] = __float2bfloat16(f[i] - __bfloat162float(H.b[i]));
    }
    size_t base = (size_t)r * 3 * K + k;
    *(uint2*)(Y + base)       = H.u;
    *(uint2*)(Y + base + K)   = H.u;
    *(uint2*)(Y + base + 2*K) = L.u;
}

// ---------------- bias concatenation ----------------
__global__ void biascat_kernel(const float* __restrict__ b0, const float* __restrict__ b1,
                               const float* __restrict__ b2, float* __restrict__ out) {
    int seg = blockIdx.x;
    const float* src = seg == 0 ? b0 : (seg == 1 ? b1 : b2);
    out[seg * 1024 + threadIdx.x] = src[threadIdx.x];
}

// ---------------- HMMA bf16 GEMM (3-stage cp.async pipeline) ----
// EPI: 0 = bias -> fp32, 1 = bias + residual -> fp32, 3 = bias + gelu -> split3 bf16
#define GBM 128
#define GBN 128
#define GBK 64
#define AST (GBM*128)
#define GSTAGE (AST + GBN*128)      // 32768
#define GSMEM (3*GSTAGE + 1024)

template<int EPI>
__global__ void __launch_bounds__(256, 1)
gemm_mma(const __nv_bfloat16* __restrict__ A, const __nv_bfloat16* __restrict__ B,
         const float* __restrict__ bias, const float* __restrict__ R,
         float* __restrict__ C, __nv_bfloat16* __restrict__ C2, int M, int N, int K3) {
    extern __shared__ char dyn_smem[];
    const int tid  = threadIdx.x;
    const int lane = tid & 31;
    const int wid  = tid >> 5;
    const int wm   = wid & 1;
    const int wn   = wid >> 1;
    const int bm = blockIdx.y * GBM;
    const int bn = blockIdx.x * GBN;

    uint32_t raw = smem_u32(dyn_smem);
    uint32_t sb  = (raw + 1023u) & ~1023u;

    const size_t ldb = (size_t)K3 * 2;
    const char* Abase = (const char*)(A + (size_t)bm * K3);
    const char* Bbase = (const char*)(B + (size_t)bn * K3);

    auto issue_stage = [&](int kt, int s) {
        uint32_t dst = sb + s * GSTAGE;
        const char* Ab = Abase + (size_t)kt * (GBK * 2);
        const char* Bb = Bbase + (size_t)kt * (GBK * 2);
        #pragma unroll
        for (int p = 0; p < 4; p++) {
            int g   = (p << 8) + tid;
            int row = g >> 3;
            int seg = (g & 7) << 4;
            uint32_t off = SWZ(row * 128 + seg);
            CP_ASYNC16(dst + off,       Ab + (size_t)row * ldb + seg);
            CP_ASYNC16(dst + AST + off, Bb + (size_t)row * ldb + seg);
        }
        CP_COMMIT();
    };

    float acc[4][4][4];
    #pragma unroll
    for (int i = 0; i < 4; i++)
        #pragma unroll
        for (int j = 0; j < 4; j++)
            #pragma unroll
            for (int t = 0; t < 4; t++) acc[i][j][t] = 0.f;

    const int nk = K3 / GBK;
    issue_stage(0, 0);
    issue_stage(1, 1);

    const int a_row = wm * 64 + (lane & 15);
    const int a_kb  = (lane >> 4) << 4;
    const int bp_row = wn * 32 + ((lane >> 4) << 3) + (lane & 7);
    const int bp_kb  = (((lane >> 3) & 1) << 4);

    for (int kt = 0; kt < nk; kt++) {
        if (kt + 1 < nk) { CP_WAIT1(); } else { CP_WAIT0(); }
        __syncthreads();
        if (kt + 2 < nk) issue_stage(kt + 2, (kt + 2) % 3);

        uint32_t ab = sb + (kt % 3) * GSTAGE;
        uint32_t bb = ab + AST;
        #pragma unroll
        for (int kk = 0; kk < 4; kk++) {
            uint32_t af[4][4], bfr[4][2];
            #pragma unroll
            for (int i = 0; i < 4; i++)
                ldsm_x4(af[i][0], af[i][1], af[i][2], af[i][3],
                        ab + SWZ((a_row + i*16) * 128 + kk*32 + a_kb));
            #pragma unroll
            for (int j = 0; j < 2; j++)
                ldsm_x4(bfr[2*j][0], bfr[2*j][1], bfr[2*j+1][0], bfr[2*j+1][1],
                        bb + SWZ((bp_row + j*16) * 128 + kk*32 + bp_kb));
            #pragma unroll
            for (int i = 0; i < 4; i++)
                #pragma unroll
                for (int j = 0; j < 4; j++)
                    mma_bf16(acc[i][j], af[i], bfr[j]);
        }
    }

    const int er = (lane >> 2);
    const int ec = (lane & 3) << 1;
    #pragma unroll
    for (int i = 0; i < 4; i++) {
        #pragma unroll
        for (int j = 0; j < 4; j++) {
            int col = bn + wn*32 + j*8 + ec;
            float bx = bias[col], by = bias[col + 1];
            #pragma unroll
            for (int h = 0; h < 2; h++) {
                int row = bm + wm*64 + i*16 + er + h*8;
                float vx = acc[i][j][h*2 + 0] + bx;
                float vy = acc[i][j][h*2 + 1] + by;
                if (EPI == 1) {
                    const float2 rr = *(const float2*)(R + (size_t)row * N + col);
                    vx += rr.x; vy += rr.y;
                    *(float2*)(C + (size_t)row * N + col) = make_float2(vx, vy);
                } else if (EPI == 3) {
                    vx = 0.5f * vx * (1.0f + erff(vx * 0.70710678118654752f));
                    vy = 0.5f * vy * (1.0f + erff(vy * 0.70710678118654752f));
                    __nv_bfloat16 hx = __float2bfloat16(vx);
                    __nv_bfloat16 hy = __float2bfloat16(vy);
                    float lx = vx - __bfloat162float(hx);
                    float ly = vy - __bfloat162float(hy);
                    uint32_t hp; { __nv_bfloat162 t2 = {hx, hy}; hp = *(uint32_t*)&t2; }
                    uint32_t lp = pack_bf16x2(lx, ly);
                    size_t base = (size_t)row * (3*(size_t)N) + col;
                    *(uint32_t*)(C2 + base)         = hp;   // hi
                    *(uint32_t*)(C2 + base + N)     = lp;   // lo
                    *(uint32_t*)(C2 + base + 2*N)   = hp;   // hi
                } else {
                    *(float2*)(C + (size_t)row * N + col) = make_float2(vx, vy);
                }
            }
        }
    }
}

// ---------------- HMMA flash attention (causal always per reference) ----
// Strided fp32 inputs; bf16 output (row stride EE) feeding the wo GEMM.
__global__ void __launch_bounds__(128)
attn_mma(const float* __restrict__ Q, int ldq, const float* __restrict__ Kp, int ldk,
         const float* __restrict__ Vp, int ldv, __nv_bfloat16* __restrict__ O) {
    __shared__ __nv_bfloat16 Qs[64*64];
    __shared__ __nv_bfloat16 Ks[64*64];
    __shared__ __nv_bfloat16 Vt[64*64];   // [d][kv]

    const int b = blockIdx.y, qi = blockIdx.x;
    const int n = b >> 4, hh = b & 15;
    const int tid = threadIdx.x, lane = tid & 31, w = tid >> 5;
    const int qbase = qi * 64;
    const uint32_t qs = smem_u32(Qs), ks = smem_u32(Ks), vt = smem_u32(Vt);

    for (int i = tid; i < 64*16; i += 128) {
        int rr = i >> 4, seg = (i & 15) << 2;
        float4 v = *(const float4*)(Q + (size_t)((qbase+rr)*NN + n) * ldq + hh*HD + seg);
        uint2 pk;
        pk.x = pack_bf16x2(v.x*0.125f, v.y*0.125f);
        pk.y = pack_bf16x2(v.z*0.125f, v.w*0.125f);
        *(uint2*)((char*)Qs + SWZ(rr*128 + seg*2)) = pk;
    }

    const int r  = lane >> 2;
    const int cb = (lane & 3) << 1;

    float m0 = -1e30f, m1 = -1e30f, l0 = 0.f, l1 = 0.f;
    float oac[8][4];
    #pragma unroll
    for (int t = 0; t < 8; t++)
        #pragma unroll
        for (int e = 0; e < 4; e++) oac[t][e] = 0.f;

    for (int j = 0; j <= qi; j++) {
        __syncthreads();
        for (int i = tid; i < 64*16; i += 128) {
            int rr = i >> 4, seg = (i & 15) << 2;
            float4 kv = *(const float4*)(Kp + (size_t)((j*64+rr)*NN + n) * ldk + hh*HD + seg);
            uint2 pk;
            pk.x = pack_bf16x2(kv.x, kv.y);
            pk.y = pack_bf16x2(kv.z, kv.w);
            *(uint2*)((char*)Ks + SWZ(rr*128 + seg*2)) = pk;
            float4 vv = *(const float4*)(Vp + (size_t)((j*64+rr)*NN + n) * ldv + hh*HD + seg);
            *(__nv_bfloat16*)((char*)Vt + SWZ((seg+0)*128 + rr*2)) = __float2bfloat16(vv.x);
            *(__nv_bfloat16*)((char*)Vt + SWZ((seg+1)*128 + rr*2)) = __float2bfloat16(vv.y);
            *(__nv_bfloat16*)((char*)Vt + SWZ((seg+2)*128 + rr*2)) = __float2bfloat16(vv.z);
            *(__nv_bfloat16*)((char*)Vt + SWZ((seg+3)*128 + rr*2)) = __float2bfloat16(vv.w);
        }
        __syncthreads();

        uint32_t af[4][4];
        #pragma unroll
        for (int kk = 0; kk < 4; kk++)
            ldsm_x4(af[kk][0], af[kk][1], af[kk][2], af[kk][3],
                    qs + SWZ((w*16 + (lane & 15))*128 + kk*32 + ((lane >> 4) << 4)));

        float sac[8][4];
        #pragma unroll
        for (int t = 0; t < 8; t++) {
            sac[t][0] = sac[t][1] = sac[t][2] = sac[t][3] = 0.f;
            #pragma unroll
            for (int kk = 0; kk < 4; kk++) {
                uint32_t bfr[2];
                ldsm_x2(bfr[0], bfr[1],
                        ks + SWZ((t*8 + (lane & 7))*128 + kk*32 + (((lane >> 3) & 1) << 4)));
                mma_bf16(sac[t], af[kk], bfr);
            }
        }

        if (j == qi) {
            int grow0 = qbase + w*16 + r;
            int grow1 = grow0 + 8;
            #pragma unroll
            for (int t = 0; t < 8; t++) {
                int gc = j*64 + t*8 + cb;
                if (gc     > grow0) sac[t][0] = -10000.0f;
                if (gc + 1 > grow0) sac[t][1] = -10000.0f;
                if (gc     > grow1) sac[t][2] = -10000.0f;
                if (gc + 1 > grow1) sac[t][3] = -10000.0f;
            }
        }

        float mx0 = -1e30f, mx1 = -1e30f;
        #pragma unroll
        for (int t = 0; t < 8; t++) {
            mx0 = fmaxf(mx0, fmaxf(sac[t][0], sac[t][1]));
            mx1 = fmaxf(mx1, fmaxf(sac[t][2], sac[t][3]));
        }
        mx0 = fmaxf(mx0, __shfl_xor_sync(0xffffffffu, mx0, 1));
        mx0 = fmaxf(mx0, __shfl_xor_sync(0xffffffffu, mx0, 2));
        mx1 = fmaxf(mx1, __shfl_xor_sync(0xffffffffu, mx1, 1));
        mx1 = fmaxf(mx1, __shfl_xor_sync(0xffffffffu, mx1, 2));
        float mn0 = fmaxf(m0, mx0), mn1 = fmaxf(m1, mx1);
        float al0 = __expf(m0 - mn0), al1 = __expf(m1 - mn1);
        float ls0 = 0.f, ls1 = 0.f;
        #pragma unroll
        for (int t = 0; t < 8; t++) {
            sac[t][0] = __expf(sac[t][0] - mn0);
            sac[t][1] = __expf(sac[t][1] - mn0);
            sac[t][2] = __expf(sac[t][2] - mn1);
            sac[t][3] = __expf(sac[t][3] - mn1);
            ls0 += sac[t][0] + sac[t][1];
            ls1 += sac[t][2] + sac[t][3];
        }
        ls0 += __shfl_xor_sync(0xffffffffu, ls0, 1);
        ls0 += __shfl_xor_sync(0xffffffffu, ls0, 2);
        ls1 += __shfl_xor_sync(0xffffffffu, ls1, 1);
        ls1 += __shfl_xor_sync(0xffffffffu, ls1, 2);
        l0 = l0 * al0 + ls0;  m0 = mn0;
        l1 = l1 * al1 + ls1;  m1 = mn1;
        #pragma unroll
        for (int t = 0; t < 8; t++) {
            oac[t][0] *= al0; oac[t][1] *= al0;
            oac[t][2] *= al1; oac[t][3] *= al1;
        }

        uint32_t pf[4][4];
        #pragma unroll
        for (int kt = 0; kt < 4; kt++) {
            pf[kt][0] = pack_bf16x2(sac[2*kt][0],   sac[2*kt][1]);
            pf[kt][1] = pack_bf16x2(sac[2*kt][2],   sac[2*kt][3]);
            pf[kt][2] = pack_bf16x2(sac[2*kt+1][0], sac[2*kt+1][1]);
            pf[kt][3] = pack_bf16x2(sac[2*kt+1][2], sac[2*kt+1][3]);
        }

        #pragma unroll
        for (int td = 0; td < 8; td++) {
            #pragma unroll
            for (int kt = 0; kt < 4; kt++) {
                uint32_t bfr[2];
                ldsm_x2(bfr[0], bfr[1],
                        vt + SWZ((td*8 + (lane & 7))*128 + kt*32 + (((lane >> 3) & 1) << 4)));
                mma_bf16(oac[td], pf[kt], bfr);
            }
        }
    }

    float inv0 = 1.0f / l0, inv1 = 1.0f / l1;
    int row0 = qbase + w*16 + r;
    int row1 = row0 + 8;
    #pragma unroll
    for (int td = 0; td < 8; td++) {
        int col = td*8 + cb;
        *(uint32_t*)(O + (size_t)(row0*NN + n) * EE + hh*HD + col) =
            pack_bf16x2(oac[td][0]*inv0, oac[td][1]*inv0);
        *(uint32_t*)(O + (size_t)(row1*NN + n) * EE + hh*HD + col) =
            pack_bf16x2(oac[td][2]*inv1, oac[td][3]*inv1);
    }
}

// ---------------- orchestration ----------------
static void conv1(const float* X, __nv_bfloat16* Y, size_t elems) {
    int t4 = (int)(elems / 4);
    conv1_kernel<<<(t4 + 255) / 256, 256>>>(X, Y, t4);
}
static void split3w(const float* X, __nv_bfloat16* Y, int rows, int K) {
    int t4 = rows * K / 4;
    split3w_kernel<<<(t4 + 255) / 256, 256>>>(X, Y, K, t4);
}
static void run_gemm(int epi, const __nv_bfloat16* A, const __nv_bfloat16* B,
                     const float* bias, const float* R, float* C, __nv_bfloat16* C2,
                     int M_, int N_, int K3) {
    dim3 grid(N_ / GBN, M_ / GBM);
    if (epi == 0)      gemm_mma<0><<<grid, 256, GSMEM>>>(A, B, bias, R, C, C2, M_, N_, K3);
    else if (epi == 1) gemm_mma<1><<<grid, 256, GSMEM>>>(A, B, bias, R, C, C2, M_, N_, K3);
    else               gemm_mma<3><<<grid, 256, GSMEM>>>(A, B, bias, R, C, C2, M_, N_, K3);
}

extern "C" void kernel_launch(void* const* d_in, const int* in_sizes, int n_in,
                              void* d_out, int out_size) {
    const float* x    = (const float*)d_in[0];
    const float* enc  = (const float*)d_in[1];
    const float* wq_s = (const float*)d_in[2];
    const float* bq_s = (const float*)d_in[3];
    const float* wk_s = (const float*)d_in[4];
    const float* bk_s = (const float*)d_in[5];
    const float* wv_s = (const float*)d_in[6];
    const float* bv_s = (const float*)d_in[7];
    const float* wo_s = (const float*)d_in[8];
    const float* bo_s = (const float*)d_in[9];
    const float* wq_c = (const float*)d_in[10];
    const float* bq_c = (const float*)d_in[11];
    const float* wk_c = (const float*)d_in[12];
    const float* bk_c = (const float*)d_in[13];
    const float* wv_c = (const float*)d_in[14];
    const float* bv_c = (const float*)d_in[15];
    const float* wo_c = (const float*)d_in[16];
    const float* bo_c = (const float*)d_in[17];
    const float* ln1_g = (const float*)d_in[18];
    const float* ln1_b = (const float*)d_in[19];
    const float* ln2_g = (const float*)d_in[20];
    const float* ln2_b = (const float*)d_in[21];
    const float* ln3_g = (const float*)d_in[22];
    const float* ln3_b = (const float*)d_in[23];
    const float* fc1_w = (const float*)d_in[24];
    const float* fc1_b = (const float*)d_in[25];
    const float* fc2_w = (const float*)d_in[26];
    const float* fc2_b = (const float*)d_in[27];
    float* out = (float*)d_out;

    float *p_q, *p_ff, *p_bcat;
    __nv_bfloat16 *p_a3, *p_w3, *p_gelu;
    cudaGetSymbolAddress((void**)&p_q,    g_q);
    cudaGetSymbolAddress((void**)&p_ff,   g_ff);
    cudaGetSymbolAddress((void**)&p_a3,   g_a3);
    cudaGetSymbolAddress((void**)&p_w3,   g_w3);
    cudaGetSymbolAddress((void**)&p_gelu, g_gelu3);
    cudaGetSymbolAddress((void**)&p_bcat, g_bcat);

    cudaFuncSetAttribute(gemm_mma<0>, cudaFuncAttributeMaxDynamicSharedMemorySize, GSMEM);
    cudaFuncSetAttribute(gemm_mma<1>, cudaFuncAttributeMaxDynamicSharedMemorySize, GSMEM);
    cudaFuncSetAttribute(gemm_mma<3>, cudaFuncAttributeMaxDynamicSharedMemorySize, GSMEM);

    dim3 agrid(LL / 64, NN * HH);   // 16 x 64
    const size_t W1 = (size_t)EE * EE;

    // ---- block 1: self-attention (fused QKV, 1-term bf16) ----
    ln_bf16_kernel<<<MM, 256>>>(x, ln1_g, ln1_b, p_a3);
    conv1(wq_s, p_w3,         W1);
    conv1(wk_s, p_w3 + W1,    W1);
    conv1(wv_s, p_w3 + 2*W1,  W1);
    biascat_kernel<<<3, 1024>>>(bq_s, bk_s, bv_s, p_bcat);
    run_gemm(0, p_a3, p_w3, p_bcat, nullptr, p_ff, nullptr, MM, 3*EE, EE);
    attn_mma<<<agrid, 128>>>(p_ff, 3*EE, p_ff + EE, 3*EE, p_ff + 2*EE, 3*EE, p_a3);
    conv1(wo_s, p_w3, W1);
    run_gemm(1, p_a3, p_w3, bo_s, x, out, nullptr, MM, EE, EE);

    // ---- block 2: cross-attention (reference applies causal mask here too) ----
    ln_bf16_kernel<<<MM, 256>>>(out, ln2_g, ln2_b, p_a3);
    conv1(wq_c, p_w3, W1);
    run_gemm(0, p_a3, p_w3, bq_c, nullptr, p_q, nullptr, MM, EE, EE);
    conv1(enc, p_a3, (size_t)MM * EE);
    conv1(wk_c, p_w3,      W1);
    conv1(wv_c, p_w3 + W1, W1);
    biascat_kernel<<<2, 1024>>>(bk_c, bv_c, nullptr, p_bcat);
    run_gemm(0, p_a3, p_w3, p_bcat, nullptr, p_ff, nullptr, MM, 2*EE, EE);
    attn_mma<<<agrid, 128>>>(p_q, EE, p_ff, 2*EE, p_ff + EE, 2*EE, p_a3);
    conv1(wo_c, p_w3, W1);
    run_gemm(1, p_a3, p_w3, bo_c, out, out, nullptr, MM, EE, EE);

    // ---- block 3: FFN (3-term split: A=[hi,lo,hi], W=[hi,hi,lo]) ----
    ln_split3_kernel<<<MM, 256>>>(out, ln3_g, ln3_b, p_a3);
    split3w(fc1_w, p_w3, FF, EE);
    run_gemm(3, p_a3, p_w3, fc1_b, nullptr, nullptr, p_gelu, MM, FF, 3*EE);
    split3w(fc2_w, p_w3, EE, FF);
    run_gemm(1, p_gelu, p_w3, fc2_b, out, out, nullptr, MM, EE, 3*FF);
}

// round 10
// speedup vs baseline: 4.6925x; 1.1732x over previous
#include <cuda_runtime.h>
#include <cuda_bf16.h>
#include <math.h>
#include <stdint.h>

// Problem constants: L=1024, N=4, E=1024, F=4096, H=16, d=64
#define LL 1024
#define NN 4
#define EE 1024
#define FF 4096
#define HH 16
#define HD 64
#define MM (LL*NN)   // 4096 rows

// ---------------- scratch (static device allocations) ----------------
__device__ float g_q[MM*EE];                            // cross-attn q (fp32)
__device__ float g_ff[(size_t)MM*FF];                   // fused qkv/kv GEMM out (fp32)
__device__ __nv_bfloat16 g_a3[(size_t)MM * 3 * EE];     // LN splits / attn out / enc bf16
__device__ __nv_bfloat16 g_w3[(size_t)FF * 3 * EE];     // weight bf16 buffers
__device__ __nv_bfloat16 g_gelu3[(size_t)MM * 3 * FF];  // gelu 3-term split (fc2 A operand)
__device__ float g_bcat[3*EE];                          // concatenated bias

// ---------------- portable PTX helpers -------
__device__ __forceinline__ uint32_t smem_u32(const void* p) {
    uint32_t a;
    asm("{ .reg .u64 t; cvta.to.shared.u64 t, %1; cvt.u32.u64 %0, t; }" : "=r"(a) : "l"(p));
    return a;
}

#define SWZ(x) ((x) ^ (((x) >> 3) & 0x70))

#define CP_ASYNC16(dst_u32, src_ptr) \
    asm volatile("cp.async.cg.shared.global [%0], [%1], 16;" \
        :: "r"(dst_u32), "l"(src_ptr) : "memory")
#define CP_COMMIT() asm volatile("cp.async.commit_group;" ::: "memory")
#define CP_WAIT1()  asm volatile("cp.async.wait_group 1;" ::: "memory")
#define CP_WAIT0()  asm volatile("cp.async.wait_group 0;" ::: "memory")

__device__ __forceinline__ void ldsm_x4(uint32_t& r0, uint32_t& r1, uint32_t& r2, uint32_t& r3,
                                        uint32_t addr) {
    asm volatile("ldmatrix.sync.aligned.m8n8.x4.shared.b16 {%0,%1,%2,%3}, [%4];"
        : "=r"(r0), "=r"(r1), "=r"(r2), "=r"(r3) : "r"(addr));
}
__device__ __forceinline__ void ldsm_x2(uint32_t& r0, uint32_t& r1, uint32_t addr) {
    asm volatile("ldmatrix.sync.aligned.m8n8.x2.shared.b16 {%0,%1}, [%2];"
        : "=r"(r0), "=r"(r1) : "r"(addr));
}
__device__ __forceinline__ void mma_bf16(float* d, const uint32_t* a, const uint32_t* b) {
    asm volatile("mma.sync.aligned.m16n8k16.row.col.f32.bf16.bf16.f32 "
        "{%0,%1,%2,%3}, {%4,%5,%6,%7}, {%8,%9}, {%0,%1,%2,%3};"
        : "+f"(d[0]), "+f"(d[1]), "+f"(d[2]), "+f"(d[3])
        : "r"(a[0]), "r"(a[1]), "r"(a[2]), "r"(a[3]), "r"(b[0]), "r"(b[1]));
}
__device__ __forceinline__ uint32_t pack_bf16x2(float x, float y) {
    __nv_bfloat162 h = __floats2bfloat162_rn(x, y);
    return *(uint32_t*)&h;
}

// ---------------- layernorm core ----------------
__device__ __forceinline__ void ln_core(const float* __restrict__ x, int row, int tid,
                                        float4& v, float& mean, float& rstd) {
    const float4* xr = (const float4*)(x + (size_t)row * EE);
    v = xr[tid];
    float s  = v.x + v.y + v.z + v.w;
    float sq = v.x*v.x + v.y*v.y + v.z*v.z + v.w*v.w;
    #pragma unroll
    for (int off = 16; off > 0; off >>= 1) {
        s  += __shfl_down_sync(0xffffffffu, s,  off);
        sq += __shfl_down_sync(0xffffffffu, sq, off);
    }
    __shared__ float rs[8], rq[8];
    __shared__ float s_mean, s_rstd;
    int lane = tid & 31, wid = tid >> 5;
    if (lane == 0) { rs[wid] = s; rq[wid] = sq; }
    __syncthreads();
    if (tid == 0) {
        float ts = 0.f, tq = 0.f;
        #pragma unroll
        for (int i = 0; i < 8; i++) { ts += rs[i]; tq += rq[i]; }
        float mn = ts * (1.0f / EE);
        float var = tq * (1.0f / EE) - mn * mn;
        s_mean = mn;
        s_rstd = rsqrtf(var + 1e-5f);
    }
    __syncthreads();
    mean = s_mean; rstd = s_rstd;
}

// LN -> 1-term bf16 (row stride EE)
__global__ void ln_bf16_kernel(const float* __restrict__ x, const float* __restrict__ g,
                               const float* __restrict__ b, __nv_bfloat16* __restrict__ y) {
    int row = blockIdx.x, tid = threadIdx.x;
    float4 v; float mean, rstd;
    ln_core(x, row, tid, v, mean, rstd);
    float4 gv = ((const float4*)g)[tid], bv = ((const float4*)b)[tid];
    float ox = (v.x - mean) * rstd * gv.x + bv.x;
    float oy = (v.y - mean) * rstd * gv.y + bv.y;
    float oz = (v.z - mean) * rstd * gv.z + bv.z;
    float ow = (v.w - mean) * rstd * gv.w + bv.w;
    uint2 pk; pk.x = pack_bf16x2(ox, oy); pk.y = pack_bf16x2(oz, ow);
    *(uint2*)(y + (size_t)row * EE + tid * 4) = pk;
}

// LN -> 3-term split [hi | lo | hi] (row stride 3*EE)
__global__ void ln_split3_kernel(const float* __restrict__ x, const float* __restrict__ g,
                                 const float* __restrict__ b, __nv_bfloat16* __restrict__ y) {
    int row = blockIdx.x, tid = threadIdx.x;
    float4 v; float mean, rstd;
    ln_core(x, row, tid, v, mean, rstd);
    float4 gv = ((const float4*)g)[tid], bv = ((const float4*)b)[tid];
    float f[4];
    f[0] = (v.x - mean) * rstd * gv.x + bv.x;
    f[1] = (v.y - mean) * rstd * gv.y + bv.y;
    f[2] = (v.z - mean) * rstd * gv.z + bv.z;
    f[3] = (v.w - mean) * rstd * gv.w + bv.w;
    union { __nv_bfloat16 h[4]; uint2 u; } H, L;
    #pragma unroll
    for (int i = 0; i < 4; i++) {
        H.h[i] = __float2bfloat16(f[i]);
        L.h[i] = __float2bfloat16(f[i] - __bfloat162float(H.h[i]));
    }
    size_t base = (size_t)row * 3 * EE + tid * 4;
    *(uint2*)(y + base)        = H.u;
    *(uint2*)(y + base + EE)   = L.u;
    *(uint2*)(y + base + 2*EE) = H.u;
}

// fp32 -> plain bf16 (1-term)
__global__ void conv1_kernel(const float* __restrict__ X, __nv_bfloat16* __restrict__ Y,
                             int total4) {
    int idx = blockIdx.x * blockDim.x + threadIdx.x;
    if (idx >= total4) return;
    float4 v = ((const float4*)X)[idx];
    uint2 pk;
    pk.x = pack_bf16x2(v.x, v.y);
    pk.y = pack_bf16x2(v.z, v.w);
    ((uint2*)Y)[idx] = pk;
}

// weight -> 3-term split [hi | hi | lo] (row stride 3K)
__global__ void split3w_kernel(const float* __restrict__ X, __nv_bfloat16* __restrict__ Y,
                               int K, int total4) {
    int idx = blockIdx.x * blockDim.x + threadIdx.x;
    if (idx >= total4) return;
    int kq = K >> 2;
    int r  = idx / kq;
    int k  = (idx - r * kq) << 2;
    float4 v = *(const float4*)(X + (size_t)r * K + k);
    float f[4] = {v.x, v.y, v.z, v.w};
    union { __nv_bfloat16 b[4]; uint2 u; } H, L;
    #pragma unroll
    for (int i = 0; i < 4; i++) {
        H.b[i] = __float2bfloat16(f[i]);
        L.b[i] = __float2bfloat16(f[i] - __bfloat162float(H.b[i]));
    }
    size_t base = (size_t)r * 3 * K + k;
    *(uint2*)(Y + base)       = H.u;
    *(uint2*)(Y + base + K)   = H.u;
    *(uint2*)(Y + base + 2*K) = L.u;
}

// ---------------- bias concatenation ----------------
__global__ void biascat_kernel(const float* __restrict__ b0, const float* __restrict__ b1,
                               const float* __restrict__ b2, float* __restrict__ out) {
    int seg = blockIdx.x;
    const float* src = seg == 0 ? b0 : (seg == 1 ? b1 : b2);
    out[seg * 1024 + threadIdx.x] = src[threadIdx.x];
}

// ---------------- HMMA bf16 GEMM (2-stage cp.async, 2 CTAs/SM) ----
// EPI: 0 = bias -> fp32, 1 = bias + residual -> fp32, 3 = bias + gelu -> split3 bf16
#define GBM 128
#define GBN 128
#define GBK 64
#define AST (GBM*128)
#define GSTAGE (AST + GBN*128)      // 32768
#define GSMEM (2*GSTAGE + 1024)     // 66560 -> 2 CTAs/SM fit in 228KB

template<int EPI>
__global__ void __launch_bounds__(256, 2)
gemm_mma(const __nv_bfloat16* __restrict__ A, const __nv_bfloat16* __restrict__ B,
         const float* __restrict__ bias, const float* __restrict__ R,
         float* __restrict__ C, __nv_bfloat16* __restrict__ C2, int M, int N, int K3) {
    extern __shared__ char dyn_smem[];
    const int tid  = threadIdx.x;
    const int lane = tid & 31;
    const int wid  = tid >> 5;
    const int wm   = wid & 1;
    const int wn   = wid >> 1;
    const int bm = blockIdx.y * GBM;
    const int bn = blockIdx.x * GBN;

    uint32_t raw = smem_u32(dyn_smem);
    uint32_t sb  = (raw + 1023u) & ~1023u;

    const size_t ldb = (size_t)K3 * 2;
    const char* Abase = (const char*)(A + (size_t)bm * K3);
    const char* Bbase = (const char*)(B + (size_t)bn * K3);

    auto issue_stage = [&](int kt, int s) {
        uint32_t dst = sb + s * GSTAGE;
        const char* Ab = Abase + (size_t)kt * (GBK * 2);
        const char* Bb = Bbase + (size_t)kt * (GBK * 2);
        #pragma unroll
        for (int p = 0; p < 4; p++) {
            int g   = (p << 8) + tid;
            int row = g >> 3;
            int seg = (g & 7) << 4;
            uint32_t off = SWZ(row * 128 + seg);
            CP_ASYNC16(dst + off,       Ab + (size_t)row * ldb + seg);
            CP_ASYNC16(dst + AST + off, Bb + (size_t)row * ldb + seg);
        }
        CP_COMMIT();
    };

    float acc[4][4][4];
    #pragma unroll
    for (int i = 0; i < 4; i++)
        #pragma unroll
        for (int j = 0; j < 4; j++)
            #pragma unroll
            for (int t = 0; t < 4; t++) acc[i][j][t] = 0.f;

    const int nk = K3 / GBK;
    issue_stage(0, 0);

    const int a_row = wm * 64 + (lane & 15);
    const int a_kb  = (lane >> 4) << 4;
    const int bp_row = wn * 32 + ((lane >> 4) << 3) + (lane & 7);
    const int bp_kb  = (((lane >> 3) & 1) << 4);

    for (int kt = 0; kt < nk; kt++) {
        int s = kt & 1;
        if (kt + 1 < nk) {
            issue_stage(kt + 1, s ^ 1);
            CP_WAIT1();
        } else {
            CP_WAIT0();
        }
        __syncthreads();

        uint32_t ab = sb + s * GSTAGE;
        uint32_t bb = ab + AST;
        #pragma unroll
        for (int kk = 0; kk < 4; kk++) {
            uint32_t af[4][4], bfr[4][2];
            #pragma unroll
            for (int i = 0; i < 4; i++)
                ldsm_x4(af[i][0], af[i][1], af[i][2], af[i][3],
                        ab + SWZ((a_row + i*16) * 128 + kk*32 + a_kb));
            #pragma unroll
            for (int j = 0; j < 2; j++)
                ldsm_x4(bfr[2*j][0], bfr[2*j][1], bfr[2*j+1][0], bfr[2*j+1][1],
                        bb + SWZ((bp_row + j*16) * 128 + kk*32 + bp_kb));
            #pragma unroll
            for (int i = 0; i < 4; i++)
                #pragma unroll
                for (int j = 0; j < 4; j++)
                    mma_bf16(acc[i][j], af[i], bfr[j]);
        }
        __syncthreads();
    }

    const int er = (lane >> 2);
    const int ec = (lane & 3) << 1;
    #pragma unroll
    for (int i = 0; i < 4; i++) {
        #pragma unroll
        for (int j = 0; j < 4; j++) {
            int col = bn + wn*32 + j*8 + ec;
            float bx = bias[col], by = bias[col + 1];
            #pragma unroll
            for (int h = 0; h < 2; h++) {
                int row = bm + wm*64 + i*16 + er + h*8;
                float vx = acc[i][j][h*2 + 0] + bx;
                float vy = acc[i][j][h*2 + 1] + by;
                if (EPI == 1) {
                    const float2 rr = *(const float2*)(R + (size_t)row * N + col);
                    vx += rr.x; vy += rr.y;
                    *(float2*)(C + (size_t)row * N + col) = make_float2(vx, vy);
                } else if (EPI == 3) {
                    vx = 0.5f * vx * (1.0f + erff(vx * 0.70710678118654752f));
                    vy = 0.5f * vy * (1.0f + erff(vy * 0.70710678118654752f));
                    __nv_bfloat16 hx = __float2bfloat16(vx);
                    __nv_bfloat16 hy = __float2bfloat16(vy);
                    float lx = vx - __bfloat162float(hx);
                    float ly = vy - __bfloat162float(hy);
                    uint32_t hp; { __nv_bfloat162 t2 = {hx, hy}; hp = *(uint32_t*)&t2; }
                    uint32_t lp = pack_bf16x2(lx, ly);
                    size_t base = (size_t)row * (3*(size_t)N) + col;
                    *(uint32_t*)(C2 + base)         = hp;   // hi
                    *(uint32_t*)(C2 + base + N)     = lp;   // lo
                    *(uint32_t*)(C2 + base + 2*N)   = hp;   // hi
                } else {
                    *(float2*)(C + (size_t)row * N + col) = make_float2(vx, vy);
                }
            }
        }
    }
}

// ---------------- HMMA flash attention (causal always per reference) ----
// Strided fp32 inputs; bf16 output (row stride EE) feeding the wo GEMM.
__global__ void __launch_bounds__(128)
attn_mma(const float* __restrict__ Q, int ldq, const float* __restrict__ Kp, int ldk,
         const float* __restrict__ Vp, int ldv, __nv_bfloat16* __restrict__ O) {
    __shared__ __nv_bfloat16 Qs[64*64];
    __shared__ __nv_bfloat16 Ks[64*64];
    __shared__ __nv_bfloat16 Vt[64*64];   // [d][kv]

    const int b = blockIdx.y, qi = blockIdx.x;
    const int n = b >> 4, hh = b & 15;
    const int tid = threadIdx.x, lane = tid & 31, w = tid >> 5;
    const int qbase = qi * 64;
    const uint32_t qs = smem_u32(Qs), ks = smem_u32(Ks), vt = smem_u32(Vt);

    for (int i = tid; i < 64*16; i += 128) {
        int rr = i >> 4, seg = (i & 15) << 2;
        float4 v = *(const float4*)(Q + (size_t)((qbase+rr)*NN + n) * ldq + hh*HD + seg);
        uint2 pk;
        pk.x = pack_bf16x2(v.x*0.125f, v.y*0.125f);
        pk.y = pack_bf16x2(v.z*0.125f, v.w*0.125f);
        *(uint2*)((char*)Qs + SWZ(rr*128 + seg*2)) = pk;
    }

    const int r  = lane >> 2;
    const int cb = (lane & 3) << 1;

    float m0 = -1e30f, m1 = -1e30f, l0 = 0.f, l1 = 0.f;
    float oac[8][4];
    #pragma unroll
    for (int t = 0; t < 8; t++)
        #pragma unroll
        for (int e = 0; e < 4; e++) oac[t][e] = 0.f;

    for (int j = 0; j <= qi; j++) {
        __syncthreads();
        for (int i = tid; i < 64*16; i += 128) {
            int rr = i >> 4, seg = (i & 15) << 2;
            float4 kv = *(const float4*)(Kp + (size_t)((j*64+rr)*NN + n) * ldk + hh*HD + seg);
            uint2 pk;
            pk.x = pack_bf16x2(kv.x, kv.y);
            pk.y = pack_bf16x2(kv.z, kv.w);
            *(uint2*)((char*)Ks + SWZ(rr*128 + seg*2)) = pk;
            float4 vv = *(const float4*)(Vp + (size_t)((j*64+rr)*NN + n) * ldv + hh*HD + seg);
            *(__nv_bfloat16*)((char*)Vt + SWZ((seg+0)*128 + rr*2)) = __float2bfloat16(vv.x);
            *(__nv_bfloat16*)((char*)Vt + SWZ((seg+1)*128 + rr*2)) = __float2bfloat16(vv.y);
            *(__nv_bfloat16*)((char*)Vt + SWZ((seg+2)*128 + rr*2)) = __float2bfloat16(vv.z);
            *(__nv_bfloat16*)((char*)Vt + SWZ((seg+3)*128 + rr*2)) = __float2bfloat16(vv.w);
        }
        __syncthreads();

        uint32_t af[4][4];
        #pragma unroll
        for (int kk = 0; kk < 4; kk++)
            ldsm_x4(af[kk][0], af[kk][1], af[kk][2], af[kk][3],
                    qs + SWZ((w*16 + (lane & 15))*128 + kk*32 + ((lane >> 4) << 4)));

        float sac[8][4];
        #pragma unroll
        for (int t = 0; t < 8; t++) {
            sac[t][0] = sac[t][1] = sac[t][2] = sac[t][3] = 0.f;
            #pragma unroll
            for (int kk = 0; kk < 4; kk++) {
                uint32_t bfr[2];
                ldsm_x2(bfr[0], bfr[1],
                        ks + SWZ((t*8 + (lane & 7))*128 + kk*32 + (((lane >> 3) & 1) << 4)));
                mma_bf16(sac[t], af[kk], bfr);
            }
        }

        if (j == qi) {
            int grow0 = qbase + w*16 + r;
            int grow1 = grow0 + 8;
            #pragma unroll
            for (int t = 0; t < 8; t++) {
                int gc = j*64 + t*8 + cb;
                if (gc     > grow0) sac[t][0] = -10000.0f;
                if (gc + 1 > grow0) sac[t][1] = -10000.0f;
                if (gc     > grow1) sac[t][2] = -10000.0f;
                if (gc + 1 > grow1) sac[t][3] = -10000.0f;
            }
        }

        float mx0 = -1e30f, mx1 = -1e30f;
        #pragma unroll
        for (int t = 0; t < 8; t++) {
            mx0 = fmaxf(mx0, fmaxf(sac[t][0], sac[t][1]));
            mx1 = fmaxf(mx1, fmaxf(sac[t][2], sac[t][3]));
        }
        mx0 = fmaxf(mx0, __shfl_xor_sync(0xffffffffu, mx0, 1));
        mx0 = fmaxf(mx0, __shfl_xor_sync(0xffffffffu, mx0, 2));
        mx1 = fmaxf(mx1, __shfl_xor_sync(0xffffffffu, mx1, 1));
        mx1 = fmaxf(mx1, __shfl_xor_sync(0xffffffffu, mx1, 2));
        float mn0 = fmaxf(m0, mx0), mn1 = fmaxf(m1, mx1);
        float al0 = __expf(m0 - mn0), al1 = __expf(m1 - mn1);
        float ls0 = 0.f, ls1 = 0.f;
        #pragma unroll
        for (int t = 0; t < 8; t++) {
            sac[t][0] = __expf(sac[t][0] - mn0);
            sac[t][1] = __expf(sac[t][1] - mn0);
            sac[t][2] = __expf(sac[t][2] - mn1);
            sac[t][3] = __expf(sac[t][3] - mn1);
            ls0 += sac[t][0] + sac[t][1];
            ls1 += sac[t][2] + sac[t][3];
        }
        ls0 += __shfl_xor_sync(0xffffffffu, ls0, 1);
        ls0 += __shfl_xor_sync(0xffffffffu, ls0, 2);
        ls1 += __shfl_xor_sync(0xffffffffu, ls1, 1);
        ls1 += __shfl_xor_sync(0xffffffffu, ls1, 2);
        l0 = l0 * al0 + ls0;  m0 = mn0;
        l1 = l1 * al1 + ls1;  m1 = mn1;
        #pragma unroll
        for (int t = 0; t < 8; t++) {
            oac[t][0] *= al0; oac[t][1] *= al0;
            oac[t][2] *= al1; oac[t][3] *= al1;
        }

        uint32_t pf[4][4];
        #pragma unroll
        for (int kt = 0; kt < 4; kt++) {
            pf[kt][0] = pack_bf16x2(sac[2*kt][0],   sac[2*kt][1]);
            pf[kt][1] = pack_bf16x2(sac[2*kt][2],   sac[2*kt][3]);
            pf[kt][2] = pack_bf16x2(sac[2*kt+1][0], sac[2*kt+1][1]);
            pf[kt][3] = pack_bf16x2(sac[2*kt+1][2], sac[2*kt+1][3]);
        }

        #pragma unroll
        for (int td = 0; td < 8; td++) {
            #pragma unroll
            for (int kt = 0; kt < 4; kt++) {
                uint32_t bfr[2];
                ldsm_x2(bfr[0], bfr[1],
                        vt + SWZ((td*8 + (lane & 7))*128 + kt*32 + (((lane >> 3) & 1) << 4)));
                mma_bf16(oac[td], pf[kt], bfr);
            }
        }
    }

    float inv0 = 1.0f / l0, inv1 = 1.0f / l1;
    int row0 = qbase + w*16 + r;
    int row1 = row0 + 8;
    #pragma unroll
    for (int td = 0; td < 8; td++) {
        int col = td*8 + cb;
        *(uint32_t*)(O + (size_t)(row0*NN + n) * EE + hh*HD + col) =
            pack_bf16x2(oac[td][0]*inv0, oac[td][1]*inv0);
        *(uint32_t*)(O + (size_t)(row1*NN + n) * EE + hh*HD + col) =
            pack_bf16x2(oac[td][2]*inv1, oac[td][3]*inv1);
    }
}

// ---------------- orchestration ----------------
static void conv1(const float* X, __nv_bfloat16* Y, size_t elems) {
    int t4 = (int)(elems / 4);
    conv1_kernel<<<(t4 + 255) / 256, 256>>>(X, Y, t4);
}
static void split3w(const float* X, __nv_bfloat16* Y, int rows, int K) {
    int t4 = rows * K / 4;
    split3w_kernel<<<(t4 + 255) / 256, 256>>>(X, Y, K, t4);
}
static void run_gemm(int epi, const __nv_bfloat16* A, const __nv_bfloat16* B,
                     const float* bias, const float* R, float* C, __nv_bfloat16* C2,
                     int M_, int N_, int K3) {
    dim3 grid(N_ / GBN, M_ / GBM);
    if (epi == 0)      gemm_mma<0><<<grid, 256, GSMEM>>>(A, B, bias, R, C, C2, M_, N_, K3);
    else if (epi == 1) gemm_mma<1><<<grid, 256, GSMEM>>>(A, B, bias, R, C, C2, M_, N_, K3);
    else               gemm_mma<3><<<grid, 256, GSMEM>>>(A, B, bias, R, C, C2, M_, N_, K3);
}

extern "C" void kernel_launch(void* const* d_in, const int* in_sizes, int n_in,
                              void* d_out, int out_size) {
    const float* x    = (const float*)d_in[0];
    const float* enc  = (const float*)d_in[1];
    const float* wq_s = (const float*)d_in[2];
    const float* bq_s = (const float*)d_in[3];
    const float* wk_s = (const float*)d_in[4];
    const float* bk_s = (const float*)d_in[5];
    const float* wv_s = (const float*)d_in[6];
    const float* bv_s = (const float*)d_in[7];
    const float* wo_s = (const float*)d_in[8];
    const float* bo_s = (const float*)d_in[9];
    const float* wq_c = (const float*)d_in[10];
    const float* bq_c = (const float*)d_in[11];
    const float* wk_c = (const float*)d_in[12];
    const float* bk_c = (const float*)d_in[13];
    const float* wv_c = (const float*)d_in[14];
    const float* bv_c = (const float*)d_in[15];
    const float* wo_c = (const float*)d_in[16];
    const float* bo_c = (const float*)d_in[17];
    const float* ln1_g = (const float*)d_in[18];
    const float* ln1_b = (const float*)d_in[19];
    const float* ln2_g = (const float*)d_in[20];
    const float* ln2_b = (const float*)d_in[21];
    const float* ln3_g = (const float*)d_in[22];
    const float* ln3_b = (const float*)d_in[23];
    const float* fc1_w = (const float*)d_in[24];
    const float* fc1_b = (const float*)d_in[25];
    const float* fc2_w = (const float*)d_in[26];
    const float* fc2_b = (const float*)d_in[27];
    float* out = (float*)d_out;

    float *p_q, *p_ff, *p_bcat;
    __nv_bfloat16 *p_a3, *p_w3, *p_gelu;
    cudaGetSymbolAddress((void**)&p_q,    g_q);
    cudaGetSymbolAddress((void**)&p_ff,   g_ff);
    cudaGetSymbolAddress((void**)&p_a3,   g_a3);
    cudaGetSymbolAddress((void**)&p_w3,   g_w3);
    cudaGetSymbolAddress((void**)&p_gelu, g_gelu3);
    cudaGetSymbolAddress((void**)&p_bcat, g_bcat);

    cudaFuncSetAttribute(gemm_mma<0>, cudaFuncAttributeMaxDynamicSharedMemorySize, GSMEM);
    cudaFuncSetAttribute(gemm_mma<1>, cudaFuncAttributeMaxDynamicSharedMemorySize, GSMEM);
    cudaFuncSetAttribute(gemm_mma<3>, cudaFuncAttributeMaxDynamicSharedMemorySize, GSMEM);

    dim3 agrid(LL / 64, NN * HH);   // 16 x 64
    const size_t W1 = (size_t)EE * EE;

    // ---- block 1: self-attention (fused QKV, 1-term bf16) ----
    ln_bf16_kernel<<<MM, 256>>>(x, ln1_g, ln1_b, p_a3);
    conv1(wq_s, p_w3,         W1);
    conv1(wk_s, p_w3 + W1,    W1);
    conv1(wv_s, p_w3 + 2*W1,  W1);
    biascat_kernel<<<3, 1024>>>(bq_s, bk_s, bv_s, p_bcat);
    run_gemm(0, p_a3, p_w3, p_bcat, nullptr, p_ff, nullptr, MM, 3*EE, EE);
    attn_mma<<<agrid, 128>>>(p_ff, 3*EE, p_ff + EE, 3*EE, p_ff + 2*EE, 3*EE, p_a3);
    conv1(wo_s, p_w3, W1);
    run_gemm(1, p_a3, p_w3, bo_s, x, out, nullptr, MM, EE, EE);

    // ---- block 2: cross-attention (reference applies causal mask here too) ----
    ln_bf16_kernel<<<MM, 256>>>(out, ln2_g, ln2_b, p_a3);
    conv1(wq_c, p_w3, W1);
    run_gemm(0, p_a3, p_w3, bq_c, nullptr, p_q, nullptr, MM, EE, EE);
    conv1(enc, p_a3, (size_t)MM * EE);
    conv1(wk_c, p_w3,      W1);
    conv1(wv_c, p_w3 + W1, W1);
    biascat_kernel<<<2, 1024>>>(bk_c, bv_c, nullptr, p_bcat);
    run_gemm(0, p_a3, p_w3, p_bcat, nullptr, p_ff, nullptr, MM, 2*EE, EE);
    attn_mma<<<agrid, 128>>>(p_q, EE, p_ff, 2*EE, p_ff + EE, 2*EE, p_a3);
    conv1(wo_c, p_w3, W1);
    run_gemm(1, p_a3, p_w3, bo_c, out, out, nullptr, MM, EE, EE);

    // ---- block 3: FFN (3-term split: A=[hi,lo,hi], W=[hi,hi,lo]) ----
    ln_split3_kernel<<<MM, 256>>>(out, ln3_g, ln3_b, p_a3);
    split3w(fc1_w, p_w3, FF, EE);
    run_gemm(3, p_a3, p_w3, fc1_b, nullptr, nullptr, p_gelu, MM, FF, 3*EE);
    split3w(fc2_w, p_w3, EE, FF);
    run_gemm(1, p_gelu, p_w3, fc2_b, out, out, nullptr, MM, EE, 3*FF);
}

// round 11
// speedup vs baseline: 5.7462x; 1.2245x over previous
#include <cuda_runtime.h>
#include <cuda_bf16.h>
#include <math.h>
#include <stdint.h>

// Problem constants: L=1024, N=4, E=1024, F=4096, H=16, d=64
#define LL 1024
#define NN 4
#define EE 1024
#define FF 4096
#define HH 16
#define HD 64
#define MM (LL*NN)   // 4096 rows

// ---------------- scratch (static device allocations) ----------------
__device__ float g_q[MM*EE];                          // cross-attn q / fc1 A (tf32 fp32)
__device__ float g_ff[(size_t)MM*FF];                 // fused qkv/kv out; gelu out (tf32 fp32)
__device__ __nv_bfloat16 g_a3[(size_t)MM * 3 * EE];   // LN bf16 / attn out / enc bf16
__device__ __nv_bfloat16 g_w3[(size_t)EE * 3 * EE];   // attn-path weight bf16
__device__ float g_wtf[2][(size_t)EE * FF];           // tf32-rounded fc weights
__device__ float g_bcat[3*EE];                        // concatenated bias

// ---------------- portable PTX helpers -------
__device__ __forceinline__ uint32_t smem_u32(const void* p) {
    uint32_t a;
    asm("{ .reg .u64 t; cvta.to.shared.u64 t, %1; cvt.u32.u64 %0, t; }" : "=r"(a) : "l"(p));
    return a;
}

#define SWZ(x) ((x) ^ (((x) >> 3) & 0x70))

#define CP_ASYNC16(dst_u32, src_ptr) \
    asm volatile("cp.async.cg.shared.global [%0], [%1], 16;" \
        :: "r"(dst_u32), "l"(src_ptr) : "memory")
#define CP_COMMIT() asm volatile("cp.async.commit_group;" ::: "memory")
#define CP_WAIT1()  asm volatile("cp.async.wait_group 1;" ::: "memory")
#define CP_WAIT0()  asm volatile("cp.async.wait_group 0;" ::: "memory")

__device__ __forceinline__ void ldsm_x4(uint32_t& r0, uint32_t& r1, uint32_t& r2, uint32_t& r3,
                                        uint32_t addr) {
    asm volatile("ldmatrix.sync.aligned.m8n8.x4.shared.b16 {%0,%1,%2,%3}, [%4];"
        : "=r"(r0), "=r"(r1), "=r"(r2), "=r"(r3) : "r"(addr));
}
__device__ __forceinline__ void ldsm_x2(uint32_t& r0, uint32_t& r1, uint32_t addr) {
    asm volatile("ldmatrix.sync.aligned.m8n8.x2.shared.b16 {%0,%1}, [%2];"
        : "=r"(r0), "=r"(r1) : "r"(addr));
}
__device__ __forceinline__ void mma_bf16(float* d, const uint32_t* a, const uint32_t* b) {
    asm volatile("mma.sync.aligned.m16n8k16.row.col.f32.bf16.bf16.f32 "
        "{%0,%1,%2,%3}, {%4,%5,%6,%7}, {%8,%9}, {%0,%1,%2,%3};"
        : "+f"(d[0]), "+f"(d[1]), "+f"(d[2]), "+f"(d[3])
        : "r"(a[0]), "r"(a[1]), "r"(a[2]), "r"(a[3]), "r"(b[0]), "r"(b[1]));
}
__device__ __forceinline__ void mma_tf32(float* d, const uint32_t* a, const uint32_t* b) {
    asm volatile("mma.sync.aligned.m16n8k8.row.col.f32.tf32.tf32.f32 "
        "{%0,%1,%2,%3}, {%4,%5,%6,%7}, {%8,%9}, {%0,%1,%2,%3};"
        : "+f"(d[0]), "+f"(d[1]), "+f"(d[2]), "+f"(d[3])
        : "r"(a[0]), "r"(a[1]), "r"(a[2]), "r"(a[3]), "r"(b[0]), "r"(b[1]));
}
__device__ __forceinline__ uint32_t pack_bf16x2(float x, float y) {
    __nv_bfloat162 h = __floats2bfloat162_rn(x, y);
    return *(uint32_t*)&h;
}
__device__ __forceinline__ float to_tf32(float x) {
    uint32_t u;
    asm("cvt.rna.tf32.f32 %0, %1;" : "=r"(u) : "f"(x));
    return __uint_as_float(u);
}

// ---------------- layernorm core ----------------
__device__ __forceinline__ void ln_core(const float* __restrict__ x, int row, int tid,
                                        float4& v, float& mean, float& rstd) {
    const float4* xr = (const float4*)(x + (size_t)row * EE);
    v = xr[tid];
    float s  = v.x + v.y + v.z + v.w;
    float sq = v.x*v.x + v.y*v.y + v.z*v.z + v.w*v.w;
    #pragma unroll
    for (int off = 16; off > 0; off >>= 1) {
        s  += __shfl_down_sync(0xffffffffu, s,  off);
        sq += __shfl_down_sync(0xffffffffu, sq, off);
    }
    __shared__ float rs[8], rq[8];
    __shared__ float s_mean, s_rstd;
    int lane = tid & 31, wid = tid >> 5;
    if (lane == 0) { rs[wid] = s; rq[wid] = sq; }
    __syncthreads();
    if (tid == 0) {
        float ts = 0.f, tq = 0.f;
        #pragma unroll
        for (int i = 0; i < 8; i++) { ts += rs[i]; tq += rq[i]; }
        float mn = ts * (1.0f / EE);
        float var = tq * (1.0f / EE) - mn * mn;
        s_mean = mn;
        s_rstd = rsqrtf(var + 1e-5f);
    }
    __syncthreads();
    mean = s_mean; rstd = s_rstd;
}

// LN -> 1-term bf16 (row stride EE)
__global__ void ln_bf16_kernel(const float* __restrict__ x, const float* __restrict__ g,
                               const float* __restrict__ b, __nv_bfloat16* __restrict__ y) {
    int row = blockIdx.x, tid = threadIdx.x;
    float4 v; float mean, rstd;
    ln_core(x, row, tid, v, mean, rstd);
    float4 gv = ((const float4*)g)[tid], bv = ((const float4*)b)[tid];
    float ox = (v.x - mean) * rstd * gv.x + bv.x;
    float oy = (v.y - mean) * rstd * gv.y + bv.y;
    float oz = (v.z - mean) * rstd * gv.z + bv.z;
    float ow = (v.w - mean) * rstd * gv.w + bv.w;
    uint2 pk; pk.x = pack_bf16x2(ox, oy); pk.y = pack_bf16x2(oz, ow);
    *(uint2*)(y + (size_t)row * EE + tid * 4) = pk;
}

// LN -> tf32-rounded fp32 (row stride EE)
__global__ void ln_tf32_kernel(const float* __restrict__ x, const float* __restrict__ g,
                               const float* __restrict__ b, float* __restrict__ y) {
    int row = blockIdx.x, tid = threadIdx.x;
    float4 v; float mean, rstd;
    ln_core(x, row, tid, v, mean, rstd);
    float4 gv = ((const float4*)g)[tid], bv = ((const float4*)b)[tid];
    float4 o;
    o.x = to_tf32((v.x - mean) * rstd * gv.x + bv.x);
    o.y = to_tf32((v.y - mean) * rstd * gv.y + bv.y);
    o.z = to_tf32((v.z - mean) * rstd * gv.z + bv.z);
    o.w = to_tf32((v.w - mean) * rstd * gv.w + bv.w);
    ((float4*)(y + (size_t)row * EE))[tid] = o;
}

// fp32 -> plain bf16 (1-term)
__global__ void conv1_kernel(const float* __restrict__ X, __nv_bfloat16* __restrict__ Y,
                             int total4) {
    int idx = blockIdx.x * blockDim.x + threadIdx.x;
    if (idx >= total4) return;
    float4 v = ((const float4*)X)[idx];
    uint2 pk;
    pk.x = pack_bf16x2(v.x, v.y);
    pk.y = pack_bf16x2(v.z, v.w);
    ((uint2*)Y)[idx] = pk;
}

// fp32 -> tf32-rounded fp32
__global__ void conv_tf32_kernel(const float* __restrict__ X, float* __restrict__ Y,
                                 int total4) {
    int idx = blockIdx.x * blockDim.x + threadIdx.x;
    if (idx >= total4) return;
    float4 v = ((const float4*)X)[idx];
    v.x = to_tf32(v.x); v.y = to_tf32(v.y); v.z = to_tf32(v.z); v.w = to_tf32(v.w);
    ((float4*)Y)[idx] = v;
}

// ---------------- bias concatenation ----------------
__global__ void biascat_kernel(const float* __restrict__ b0, const float* __restrict__ b1,
                               const float* __restrict__ b2, float* __restrict__ out) {
    int seg = blockIdx.x;
    const float* src = seg == 0 ? b0 : (seg == 1 ? b1 : b2);
    out[seg * 1024 + threadIdx.x] = src[threadIdx.x];
}

// ---------------- common tile geometry ----------------
#define GBM 128
#define GBN 128
#define AST (GBM*128)               // A stage bytes (128 rows x 128B)
#define GSTAGE (AST + GBN*128)      // 32768
#define GSMEM (2*GSTAGE + 1024)     // 2 stages -> 2 CTAs/SM

// ---------------- HMMA bf16 GEMM (attention path) ----
// EPI: 0 = bias -> fp32, 1 = bias + residual -> fp32
template<int EPI>
__global__ void __launch_bounds__(256, 2)
gemm_mma(const __nv_bfloat16* __restrict__ A, const __nv_bfloat16* __restrict__ B,
         const float* __restrict__ bias, const float* __restrict__ R,
         float* __restrict__ C, int M, int N, int K) {
    extern __shared__ char dyn_smem[];
    const int tid  = threadIdx.x;
    const int lane = tid & 31;
    const int wid  = tid >> 5;
    const int wm   = wid & 1;
    const int wn   = wid >> 1;
    const int bm = blockIdx.y * GBM;
    const int bn = blockIdx.x * GBN;

    uint32_t raw = smem_u32(dyn_smem);
    uint32_t sb  = (raw + 1023u) & ~1023u;
    char* smp = dyn_smem + (sb - raw); (void)smp;

    const size_t ldb = (size_t)K * 2;
    const char* Abase = (const char*)(A + (size_t)bm * K);
    const char* Bbase = (const char*)(B + (size_t)bn * K);

    auto issue_stage = [&](int kt, int s) {
        uint32_t dst = sb + s * GSTAGE;
        const char* Ab = Abase + (size_t)kt * 128;   // 64 bf16 = 128B
        const char* Bb = Bbase + (size_t)kt * 128;
        #pragma unroll
        for (int p = 0; p < 4; p++) {
            int g   = (p << 8) + tid;
            int row = g >> 3;
            int seg = (g & 7) << 4;
            uint32_t off = SWZ(row * 128 + seg);
            CP_ASYNC16(dst + off,       Ab + (size_t)row * ldb + seg);
            CP_ASYNC16(dst + AST + off, Bb + (size_t)row * ldb + seg);
        }
        CP_COMMIT();
    };

    float acc[4][4][4];
    #pragma unroll
    for (int i = 0; i < 4; i++)
        #pragma unroll
        for (int j = 0; j < 4; j++)
            #pragma unroll
            for (int t = 0; t < 4; t++) acc[i][j][t] = 0.f;

    const int nk = K / 64;
    issue_stage(0, 0);

    const int a_row = wm * 64 + (lane & 15);
    const int a_kb  = (lane >> 4) << 4;
    const int bp_row = wn * 32 + ((lane >> 4) << 3) + (lane & 7);
    const int bp_kb  = (((lane >> 3) & 1) << 4);

    for (int kt = 0; kt < nk; kt++) {
        int s = kt & 1;
        if (kt + 1 < nk) {
            issue_stage(kt + 1, s ^ 1);
            CP_WAIT1();
        } else {
            CP_WAIT0();
        }
        __syncthreads();

        uint32_t ab = sb + s * GSTAGE;
        uint32_t bb = ab + AST;
        #pragma unroll
        for (int kk = 0; kk < 4; kk++) {
            uint32_t af[4][4], bfr[4][2];
            #pragma unroll
            for (int i = 0; i < 4; i++)
                ldsm_x4(af[i][0], af[i][1], af[i][2], af[i][3],
                        ab + SWZ((a_row + i*16) * 128 + kk*32 + a_kb));
            #pragma unroll
            for (int j = 0; j < 2; j++)
                ldsm_x4(bfr[2*j][0], bfr[2*j][1], bfr[2*j+1][0], bfr[2*j+1][1],
                        bb + SWZ((bp_row + j*16) * 128 + kk*32 + bp_kb));
            #pragma unroll
            for (int i = 0; i < 4; i++)
                #pragma unroll
                for (int j = 0; j < 4; j++)
                    mma_bf16(acc[i][j], af[i], bfr[j]);
        }
        __syncthreads();
    }

    const int er = (lane >> 2);
    const int ec = (lane & 3) << 1;
    #pragma unroll
    for (int i = 0; i < 4; i++) {
        #pragma unroll
        for (int j = 0; j < 4; j++) {
            int col = bn + wn*32 + j*8 + ec;
            float bx = bias[col], by = bias[col + 1];
            #pragma unroll
            for (int h = 0; h < 2; h++) {
                int row = bm + wm*64 + i*16 + er + h*8;
                float vx = acc[i][j][h*2 + 0] + bx;
                float vy = acc[i][j][h*2 + 1] + by;
                if (EPI == 1) {
                    const float2 rr = *(const float2*)(R + (size_t)row * N + col);
                    vx += rr.x; vy += rr.y;
                }
                *(float2*)(C + (size_t)row * N + col) = make_float2(vx, vy);
            }
        }
    }
}

// ---------------- TF32 GEMM (FFN path) ----
// A: M x K fp32 (tf32-rounded), B: N x K fp32 (tf32-rounded).
// EPI: 1 = bias + residual -> fp32, 3 = bias + gelu -> tf32-rounded fp32
template<int EPI>
__global__ void __launch_bounds__(256, 2)
gemm_tf32(const float* __restrict__ A, const float* __restrict__ B,
          const float* __restrict__ bias, const float* __restrict__ R,
          float* __restrict__ C, int M, int N, int K) {
    extern __shared__ char dyn_smem[];
    const int tid  = threadIdx.x;
    const int lane = tid & 31;
    const int wid  = tid >> 5;
    const int wm   = wid & 1;
    const int wn   = wid >> 1;
    const int bm = blockIdx.y * GBM;
    const int bn = blockIdx.x * GBN;

    uint32_t raw = smem_u32(dyn_smem);
    uint32_t sb  = (raw + 1023u) & ~1023u;

    const size_t ldb = (size_t)K * 4;
    const char* Abase = (const char*)(A + (size_t)bm * K);
    const char* Bbase = (const char*)(B + (size_t)bn * K);

    auto issue_stage = [&](int kt, int s) {
        uint32_t dst = sb + s * GSTAGE;
        const char* Ab = Abase + (size_t)kt * 128;   // 32 fp32 = 128B
        const char* Bb = Bbase + (size_t)kt * 128;
        #pragma unroll
        for (int p = 0; p < 4; p++) {
            int g   = (p << 8) + tid;
            int row = g >> 3;
            int seg = (g & 7) << 4;
            uint32_t off = SWZ(row * 128 + seg);
            CP_ASYNC16(dst + off,       Ab + (size_t)row * ldb + seg);
            CP_ASYNC16(dst + AST + off, Bb + (size_t)row * ldb + seg);
        }
        CP_COMMIT();
    };

    float acc[4][4][4];
    #pragma unroll
    for (int i = 0; i < 4; i++)
        #pragma unroll
        for (int j = 0; j < 4; j++)
            #pragma unroll
            for (int t = 0; t < 4; t++) acc[i][j][t] = 0.f;

    const int nk = K / 32;
    issue_stage(0, 0);

    // tf32 ldmatrix lane addressing (8x4-tf32 pieces viewed as 8x8 b16):
    // A x4 pieces: a0 rows0-7/k0, a1 rows8-15/k0, a2 rows0-7/k0+4, a3 rows8-15/k0+4
    const int a_row  = wm * 64 + (lane & 7) + ((lane >> 3) & 1) * 8;
    const int a_colb = ((lane >> 4) & 1) << 4;            // 0 or 16 bytes (4 tf32)
    // B x4 pieces: (tile 2j) b0 k0 / b1 k0+4, (tile 2j+1) b0/b1
    const int b_row  = wn * 32 + (lane & 7) + ((lane >> 4) & 1) * 8;
    const int b_colb = ((lane >> 3) & 1) << 4;

    for (int kt = 0; kt < nk; kt++) {
        int s = kt & 1;
        if (kt + 1 < nk) {
            issue_stage(kt + 1, s ^ 1);
            CP_WAIT1();
        } else {
            CP_WAIT0();
        }
        __syncthreads();

        uint32_t ab = sb + s * GSTAGE;
        uint32_t bb = ab + AST;
        #pragma unroll
        for (int kk = 0; kk < 4; kk++) {     // k8 steps within 32-elem chunk
            uint32_t af[4][4], bfr[4][2];
            #pragma unroll
            for (int i = 0; i < 4; i++)
                ldsm_x4(af[i][0], af[i][1], af[i][2], af[i][3],
                        ab + SWZ((a_row + i*16) * 128 + kk*32 + a_colb));
            #pragma unroll
            for (int j = 0; j < 2; j++)
                ldsm_x4(bfr[2*j][0], bfr[2*j][1], bfr[2*j+1][0], bfr[2*j+1][1],
                        bb + SWZ((b_row + j*16) * 128 + kk*32 + b_colb));
            #pragma unroll
            for (int i = 0; i < 4; i++)
                #pragma unroll
                for (int j = 0; j < 4; j++)
                    mma_tf32(acc[i][j], af[i], bfr[j]);
        }
        __syncthreads();
    }

    const int er = (lane >> 2);
    const int ec = (lane & 3) << 1;
    #pragma unroll
    for (int i = 0; i < 4; i++) {
        #pragma unroll
        for (int j = 0; j < 4; j++) {
            int col = bn + wn*32 + j*8 + ec;
            float bx = bias[col], by = bias[col + 1];
            #pragma unroll
            for (int h = 0; h < 2; h++) {
                int row = bm + wm*64 + i*16 + er + h*8;
                float vx = acc[i][j][h*2 + 0] + bx;
                float vy = acc[i][j][h*2 + 1] + by;
                if (EPI == 1) {
                    const float2 rr = *(const float2*)(R + (size_t)row * N + col);
                    vx += rr.x; vy += rr.y;
                } else if (EPI == 3) {
                    vx = to_tf32(0.5f * vx * (1.0f + erff(vx * 0.70710678118654752f)));
                    vy = to_tf32(0.5f * vy * (1.0f + erff(vy * 0.70710678118654752f)));
                }
                *(float2*)(C + (size_t)row * N + col) = make_float2(vx, vy);
            }
        }
    }
}

// ---------------- HMMA flash attention (causal always per reference) ----
__global__ void __launch_bounds__(128)
attn_mma(const float* __restrict__ Q, int ldq, const float* __restrict__ Kp, int ldk,
         const float* __restrict__ Vp, int ldv, __nv_bfloat16* __restrict__ O) {
    __shared__ __nv_bfloat16 Qs[64*64];
    __shared__ __nv_bfloat16 Ks[64*64];
    __shared__ __nv_bfloat16 Vt[64*64];   // [d][kv]

    const int b = blockIdx.y, qi = blockIdx.x;
    const int n = b >> 4, hh = b & 15;
    const int tid = threadIdx.x, lane = tid & 31, w = tid >> 5;
    const int qbase = qi * 64;
    const uint32_t qs = smem_u32(Qs), ks = smem_u32(Ks), vt = smem_u32(Vt);

    for (int i = tid; i < 64*16; i += 128) {
        int rr = i >> 4, seg = (i & 15) << 2;
        float4 v = *(const float4*)(Q + (size_t)((qbase+rr)*NN + n) * ldq + hh*HD + seg);
        uint2 pk;
        pk.x = pack_bf16x2(v.x*0.125f, v.y*0.125f);
        pk.y = pack_bf16x2(v.z*0.125f, v.w*0.125f);
        *(uint2*)((char*)Qs + SWZ(rr*128 + seg*2)) = pk;
    }

    const int r  = lane >> 2;
    const int cb = (lane & 3) << 1;

    float m0 = -1e30f, m1 = -1e30f, l0 = 0.f, l1 = 0.f;
    float oac[8][4];
    #pragma unroll
    for (int t = 0; t < 8; t++)
        #pragma unroll
        for (int e = 0; e < 4; e++) oac[t][e] = 0.f;

    for (int j = 0; j <= qi; j++) {
        __syncthreads();
        for (int i = tid; i < 64*16; i += 128) {
            int rr = i >> 4, seg = (i & 15) << 2;
            float4 kv = *(const float4*)(Kp + (size_t)((j*64+rr)*NN + n) * ldk + hh*HD + seg);
            uint2 pk;
            pk.x = pack_bf16x2(kv.x, kv.y);
            pk.y = pack_bf16x2(kv.z, kv.w);
            *(uint2*)((char*)Ks + SWZ(rr*128 + seg*2)) = pk;
            float4 vv = *(const float4*)(Vp + (size_t)((j*64+rr)*NN + n) * ldv + hh*HD + seg);
            *(__nv_bfloat16*)((char*)Vt + SWZ((seg+0)*128 + rr*2)) = __float2bfloat16(vv.x);
            *(__nv_bfloat16*)((char*)Vt + SWZ((seg+1)*128 + rr*2)) = __float2bfloat16(vv.y);
            *(__nv_bfloat16*)((char*)Vt + SWZ((seg+2)*128 + rr*2)) = __float2bfloat16(vv.z);
            *(__nv_bfloat16*)((char*)Vt + SWZ((seg+3)*128 + rr*2)) = __float2bfloat16(vv.w);
        }
        __syncthreads();

        uint32_t af[4][4];
        #pragma unroll
        for (int kk = 0; kk < 4; kk++)
            ldsm_x4(af[kk][0], af[kk][1], af[kk][2], af[kk][3],
                    qs + SWZ((w*16 + (lane & 15))*128 + kk*32 + ((lane >> 4) << 4)));

        float sac[8][4];
        #pragma unroll
        for (int t = 0; t < 8; t++) {
            sac[t][0] = sac[t][1] = sac[t][2] = sac[t][3] = 0.f;
            #pragma unroll
            for (int kk = 0; kk < 4; kk++) {
                uint32_t bfr[2];
                ldsm_x2(bfr[0], bfr[1],
                        ks + SWZ((t*8 + (lane & 7))*128 + kk*32 + (((lane >> 3) & 1) << 4)));
                mma_bf16(sac[t], af[kk], bfr);
            }
        }

        if (j == qi) {
            int grow0 = qbase + w*16 + r;
            int grow1 = grow0 + 8;
            #pragma unroll
            for (int t = 0; t < 8; t++) {
                int gc = j*64 + t*8 + cb;
                if (gc     > grow0) sac[t][0] = -10000.0f;
                if (gc + 1 > grow0) sac[t][1] = -10000.0f;
                if (gc     > grow1) sac[t][2] = -10000.0f;
                if (gc + 1 > grow1) sac[t][3] = -10000.0f;
            }
        }

        float mx0 = -1e30f, mx1 = -1e30f;
        #pragma unroll
        for (int t = 0; t < 8; t++) {
            mx0 = fmaxf(mx0, fmaxf(sac[t][0], sac[t][1]));
            mx1 = fmaxf(mx1, fmaxf(sac[t][2], sac[t][3]));
        }
        mx0 = fmaxf(mx0, __shfl_xor_sync(0xffffffffu, mx0, 1));
        mx0 = fmaxf(mx0, __shfl_xor_sync(0xffffffffu, mx0, 2));
        mx1 = fmaxf(mx1, __shfl_xor_sync(0xffffffffu, mx1, 1));
        mx1 = fmaxf(mx1, __shfl_xor_sync(0xffffffffu, mx1, 2));
        float mn0 = fmaxf(m0, mx0), mn1 = fmaxf(m1, mx1);
        float al0 = __expf(m0 - mn0), al1 = __expf(m1 - mn1);
        float ls0 = 0.f, ls1 = 0.f;
        #pragma unroll
        for (int t = 0; t < 8; t++) {
            sac[t][0] = __expf(sac[t][0] - mn0);
            sac[t][1] = __expf(sac[t][1] - mn0);
            sac[t][2] = __expf(sac[t][2] - mn1);
            sac[t][3] = __expf(sac[t][3] - mn1);
            ls0 += sac[t][0] + sac[t][1];
            ls1 += sac[t][2] + sac[t][3];
        }
        ls0 += __shfl_xor_sync(0xffffffffu, ls0, 1);
        ls0 += __shfl_xor_sync(0xffffffffu, ls0, 2);
        ls1 += __shfl_xor_sync(0xffffffffu, ls1, 1);
        ls1 += __shfl_xor_sync(0xffffffffu, ls1, 2);
        l0 = l0 * al0 + ls0;  m0 = mn0;
        l1 = l1 * al1 + ls1;  m1 = mn1;
        #pragma unroll
        for (int t = 0; t < 8; t++) {
            oac[t][0] *= al0; oac[t][1] *= al0;
            oac[t][2] *= al1; oac[t][3] *= al1;
        }

        uint32_t pf[4][4];
        #pragma unroll
        for (int kt = 0; kt < 4; kt++) {
            pf[kt][0] = pack_bf16x2(sac[2*kt][0],   sac[2*kt][1]);
            pf[kt][1] = pack_bf16x2(sac[2*kt][2],   sac[2*kt][3]);
            pf[kt][2] = pack_bf16x2(sac[2*kt+1][0], sac[2*kt+1][1]);
            pf[kt][3] = pack_bf16x2(sac[2*kt+1][2], sac[2*kt+1][3]);
        }

        #pragma unroll
        for (int td = 0; td < 8; td++) {
            #pragma unroll
            for (int kt = 0; kt < 4; kt++) {
                uint32_t bfr[2];
                ldsm_x2(bfr[0], bfr[1],
                        vt + SWZ((td*8 + (lane & 7))*128 + kt*32 + (((lane >> 3) & 1) << 4)));
                mma_bf16(oac[td], pf[kt], bfr);
            }
        }
    }

    float inv0 = 1.0f / l0, inv1 = 1.0f / l1;
    int row0 = qbase + w*16 + r;
    int row1 = row0 + 8;
    #pragma unroll
    for (int td = 0; td < 8; td++) {
        int col = td*8 + cb;
        *(uint32_t*)(O + (size_t)(row0*NN + n) * EE + hh*HD + col) =
            pack_bf16x2(oac[td][0]*inv0, oac[td][1]*inv0);
        *(uint32_t*)(O + (size_t)(row1*NN + n) * EE + hh*HD + col) =
            pack_bf16x2(oac[td][2]*inv1, oac[td][3]*inv1);
    }
}

// ---------------- orchestration ----------------
static void conv1(const float* X, __nv_bfloat16* Y, size_t elems) {
    int t4 = (int)(elems / 4);
    conv1_kernel<<<(t4 + 255) / 256, 256>>>(X, Y, t4);
}
static void convtf(const float* X, float* Y, size_t elems) {
    int t4 = (int)(elems / 4);
    conv_tf32_kernel<<<(t4 + 255) / 256, 256>>>(X, Y, t4);
}
static void run_gemm(int epi, const __nv_bfloat16* A, const __nv_bfloat16* B,
                     const float* bias, const float* R, float* C,
                     int M_, int N_, int K_) {
    dim3 grid(N_ / GBN, M_ / GBM);
    if (epi == 0) gemm_mma<0><<<grid, 256, GSMEM>>>(A, B, bias, R, C, M_, N_, K_);
    else          gemm_mma<1><<<grid, 256, GSMEM>>>(A, B, bias, R, C, M_, N_, K_);
}
static void run_gemm_tf(int epi, const float* A, const float* B,
                        const float* bias, const float* R, float* C,
                        int M_, int N_, int K_) {
    dim3 grid(N_ / GBN, M_ / GBM);
    if (epi == 1) gemm_tf32<1><<<grid, 256, GSMEM>>>(A, B, bias, R, C, M_, N_, K_);
    else          gemm_tf32<3><<<grid, 256, GSMEM>>>(A, B, bias, R, C, M_, N_, K_);
}

extern "C" void kernel_launch(void* const* d_in, const int* in_sizes, int n_in,
                              void* d_out, int out_size) {
    const float* x    = (const float*)d_in[0];
    const float* enc  = (const float*)d_in[1];
    const float* wq_s = (const float*)d_in[2];
    const float* bq_s = (const float*)d_in[3];
    const float* wk_s = (const float*)d_in[4];
    const float* bk_s = (const float*)d_in[5];
    const float* wv_s = (const float*)d_in[6];
    const float* bv_s = (const float*)d_in[7];
    const float* wo_s = (const float*)d_in[8];
    const float* bo_s = (const float*)d_in[9];
    const float* wq_c = (const float*)d_in[10];
    const float* bq_c = (const float*)d_in[11];
    const float* wk_c = (const float*)d_in[12];
    const float* bk_c = (const float*)d_in[13];
    const float* wv_c = (const float*)d_in[14];
    const float* bv_c = (const float*)d_in[15];
    const float* wo_c = (const float*)d_in[16];
    const float* bo_c = (const float*)d_in[17];
    const float* ln1_g = (const float*)d_in[18];
    const float* ln1_b = (const float*)d_in[19];
    const float* ln2_g = (const float*)d_in[20];
    const float* ln2_b = (const float*)d_in[21];
    const float* ln3_g = (const float*)d_in[22];
    const float* ln3_b = (const float*)d_in[23];
    const float* fc1_w = (const float*)d_in[24];
    const float* fc1_b = (const float*)d_in[25];
    const float* fc2_w = (const float*)d_in[26];
    const float* fc2_b = (const float*)d_in[27];
    float* out = (float*)d_out;

    float *p_q, *p_ff, *p_bcat, *p_wtf0, *p_wtf1;
    __nv_bfloat16 *p_a3, *p_w3;
    cudaGetSymbolAddress((void**)&p_q,    g_q);
    cudaGetSymbolAddress((void**)&p_ff,   g_ff);
    cudaGetSymbolAddress((void**)&p_a3,   g_a3);
    cudaGetSymbolAddress((void**)&p_w3,   g_w3);
    cudaGetSymbolAddress((void**)&p_wtf0, g_wtf);
    p_wtf1 = p_wtf0 + (size_t)EE * FF;
    cudaGetSymbolAddress((void**)&p_bcat, g_bcat);

    cudaFuncSetAttribute(gemm_mma<0>,  cudaFuncAttributeMaxDynamicSharedMemorySize, GSMEM);
    cudaFuncSetAttribute(gemm_mma<1>,  cudaFuncAttributeMaxDynamicSharedMemorySize, GSMEM);
    cudaFuncSetAttribute(gemm_tf32<1>, cudaFuncAttributeMaxDynamicSharedMemorySize, GSMEM);
    cudaFuncSetAttribute(gemm_tf32<3>, cudaFuncAttributeMaxDynamicSharedMemorySize, GSMEM);

    dim3 agrid(LL / 64, NN * HH);   // 16 x 64
    const size_t W1 = (size_t)EE * EE;

    // ---- block 1: self-attention (fused QKV, 1-term bf16) ----
    ln_bf16_kernel<<<MM, 256>>>(x, ln1_g, ln1_b, p_a3);
    conv1(wq_s, p_w3,         W1);
    conv1(wk_s, p_w3 + W1,    W1);
    conv1(wv_s, p_w3 + 2*W1,  W1);
    biascat_kernel<<<3, 1024>>>(bq_s, bk_s, bv_s, p_bcat);
    run_gemm(0, p_a3, p_w3, p_bcat, nullptr, p_ff, MM, 3*EE, EE);
    attn_mma<<<agrid, 128>>>(p_ff, 3*EE, p_ff + EE, 3*EE, p_ff + 2*EE, 3*EE, p_a3);
    conv1(wo_s, p_w3, W1);
    run_gemm(1, p_a3, p_w3, bo_s, x, out, MM, EE, EE);

    // ---- block 2: cross-attention (reference applies causal mask here too) ----
    ln_bf16_kernel<<<MM, 256>>>(out, ln2_g, ln2_b, p_a3);
    conv1(wq_c, p_w3, W1);
    run_gemm(0, p_a3, p_w3, bq_c, nullptr, p_q, MM, EE, EE);
    conv1(enc, p_a3, (size_t)MM * EE);
    conv1(wk_c, p_w3,      W1);
    conv1(wv_c, p_w3 + W1, W1);
    biascat_kernel<<<2, 1024>>>(bk_c, bv_c, nullptr, p_bcat);
    run_gemm(0, p_a3, p_w3, p_bcat, nullptr, p_ff, MM, 2*EE, EE);
    attn_mma<<<agrid, 128>>>(p_q, EE, p_ff, 2*EE, p_ff + EE, 2*EE, p_a3);
    conv1(wo_c, p_w3, W1);
    run_gemm(1, p_a3, p_w3, bo_c, out, out, MM, EE, EE);

    // ---- block 3: FFN (1-term TF32) ----
    ln_tf32_kernel<<<MM, 256>>>(out, ln3_g, ln3_b, p_q);
    convtf(fc1_w, p_wtf0, (size_t)FF * EE);
    run_gemm_tf(3, p_q, p_wtf0, fc1_b, nullptr, p_ff, MM, FF, EE);
    convtf(fc2_w, p_wtf1, (size_t)EE * FF);
    run_gemm_tf(1, p_ff, p_wtf1, fc2_b, out, out, MM, EE, FF);
}

// round 12
// speedup vs baseline: 5.7491x; 1.0005x over previous
#include <cuda_runtime.h>
#include <cuda_bf16.h>
#include <math.h>
#include <stdint.h>

// Problem constants: L=1024, N=4, E=1024, F=4096, H=16, d=64
#define LL 1024
#define NN 4
#define EE 1024
#define FF 4096
#define HH 16
#define HD 64
#define MM (LL*NN)   // 4096 rows

// ---------------- scratch (static device allocations) ----------------
__device__ float g_tf[MM*EE];                         // LN3 tf32 out
__device__ float g_ff[(size_t)MM*FF];                 // fc1 gelu out (tf32 fp32)
__device__ __nv_bfloat16 g_a3[(size_t)MM * 3 * EE];   // LN bf16 / attn out / enc bf16
__device__ __nv_bfloat16 g_qkv[(size_t)MM * 3 * EE];  // fused qkv / kv bf16 outputs
__device__ __nv_bfloat16 g_qc[(size_t)MM * EE];       // cross-attn q bf16
__device__ __nv_bfloat16 g_w3[(size_t)EE * 3 * EE];   // attn-path weight bf16
__device__ float g_wtf[2][(size_t)EE * FF];           // tf32-rounded fc weights
__device__ float g_bcat[3*EE];                        // concatenated bias

// ---------------- portable PTX helpers -------
__device__ __forceinline__ uint32_t smem_u32(const void* p) {
    uint32_t a;
    asm("{ .reg .u64 t; cvta.to.shared.u64 t, %1; cvt.u32.u64 %0, t; }" : "=r"(a) : "l"(p));
    return a;
}

#define SWZ(x) ((x) ^ (((x) >> 3) & 0x70))

#define CP_ASYNC16(dst_u32, src_ptr) \
    asm volatile("cp.async.cg.shared.global [%0], [%1], 16;" \
        :: "r"(dst_u32), "l"(src_ptr) : "memory")
#define CP_COMMIT() asm volatile("cp.async.commit_group;" ::: "memory")
#define CP_WAIT1()  asm volatile("cp.async.wait_group 1;" ::: "memory")
#define CP_WAIT0()  asm volatile("cp.async.wait_group 0;" ::: "memory")

__device__ __forceinline__ void ldsm_x4(uint32_t& r0, uint32_t& r1, uint32_t& r2, uint32_t& r3,
                                        uint32_t addr) {
    asm volatile("ldmatrix.sync.aligned.m8n8.x4.shared.b16 {%0,%1,%2,%3}, [%4];"
        : "=r"(r0), "=r"(r1), "=r"(r2), "=r"(r3) : "r"(addr));
}
__device__ __forceinline__ void ldsm_x2(uint32_t& r0, uint32_t& r1, uint32_t addr) {
    asm volatile("ldmatrix.sync.aligned.m8n8.x2.shared.b16 {%0,%1}, [%2];"
        : "=r"(r0), "=r"(r1) : "r"(addr));
}
__device__ __forceinline__ void mma_bf16(float* d, const uint32_t* a, const uint32_t* b) {
    asm volatile("mma.sync.aligned.m16n8k16.row.col.f32.bf16.bf16.f32 "
        "{%0,%1,%2,%3}, {%4,%5,%6,%7}, {%8,%9}, {%0,%1,%2,%3};"
        : "+f"(d[0]), "+f"(d[1]), "+f"(d[2]), "+f"(d[3])
        : "r"(a[0]), "r"(a[1]), "r"(a[2]), "r"(a[3]), "r"(b[0]), "r"(b[1]));
}
__device__ __forceinline__ void mma_tf32(float* d, const uint32_t* a, const uint32_t* b) {
    asm volatile("mma.sync.aligned.m16n8k8.row.col.f32.tf32.tf32.f32 "
        "{%0,%1,%2,%3}, {%4,%5,%6,%7}, {%8,%9}, {%0,%1,%2,%3};"
        : "+f"(d[0]), "+f"(d[1]), "+f"(d[2]), "+f"(d[3])
        : "r"(a[0]), "r"(a[1]), "r"(a[2]), "r"(a[3]), "r"(b[0]), "r"(b[1]));
}
__device__ __forceinline__ uint32_t pack_bf16x2(float x, float y) {
    __nv_bfloat162 h = __floats2bfloat162_rn(x, y);
    return *(uint32_t*)&h;
}
__device__ __forceinline__ float to_tf32(float x) {
    uint32_t u;
    asm("cvt.rna.tf32.f32 %0, %1;" : "=r"(u) : "f"(x));
    return __uint_as_float(u);
}

// ---------------- layernorm core ----------------
__device__ __forceinline__ void ln_core(const float* __restrict__ x, int row, int tid,
                                        float4& v, float& mean, float& rstd) {
    const float4* xr = (const float4*)(x + (size_t)row * EE);
    v = xr[tid];
    float s  = v.x + v.y + v.z + v.w;
    float sq = v.x*v.x + v.y*v.y + v.z*v.z + v.w*v.w;
    #pragma unroll
    for (int off = 16; off > 0; off >>= 1) {
        s  += __shfl_down_sync(0xffffffffu, s,  off);
        sq += __shfl_down_sync(0xffffffffu, sq, off);
    }
    __shared__ float rs[8], rq[8];
    __shared__ float s_mean, s_rstd;
    int lane = tid & 31, wid = tid >> 5;
    if (lane == 0) { rs[wid] = s; rq[wid] = sq; }
    __syncthreads();
    if (tid == 0) {
        float ts = 0.f, tq = 0.f;
        #pragma unroll
        for (int i = 0; i < 8; i++) { ts += rs[i]; tq += rq[i]; }
        float mn = ts * (1.0f / EE);
        float var = tq * (1.0f / EE) - mn * mn;
        s_mean = mn;
        s_rstd = rsqrtf(var + 1e-5f);
    }
    __syncthreads();
    mean = s_mean; rstd = s_rstd;
}

// LN -> 1-term bf16 (row stride EE)
__global__ void ln_bf16_kernel(const float* __restrict__ x, const float* __restrict__ g,
                               const float* __restrict__ b, __nv_bfloat16* __restrict__ y) {
    int row = blockIdx.x, tid = threadIdx.x;
    float4 v; float mean, rstd;
    ln_core(x, row, tid, v, mean, rstd);
    float4 gv = ((const float4*)g)[tid], bv = ((const float4*)b)[tid];
    float ox = (v.x - mean) * rstd * gv.x + bv.x;
    float oy = (v.y - mean) * rstd * gv.y + bv.y;
    float oz = (v.z - mean) * rstd * gv.z + bv.z;
    float ow = (v.w - mean) * rstd * gv.w + bv.w;
    uint2 pk; pk.x = pack_bf16x2(ox, oy); pk.y = pack_bf16x2(oz, ow);
    *(uint2*)(y + (size_t)row * EE + tid * 4) = pk;
}

// LN -> tf32-rounded fp32 (row stride EE)
__global__ void ln_tf32_kernel(const float* __restrict__ x, const float* __restrict__ g,
                               const float* __restrict__ b, float* __restrict__ y) {
    int row = blockIdx.x, tid = threadIdx.x;
    float4 v; float mean, rstd;
    ln_core(x, row, tid, v, mean, rstd);
    float4 gv = ((const float4*)g)[tid], bv = ((const float4*)b)[tid];
    float4 o;
    o.x = to_tf32((v.x - mean) * rstd * gv.x + bv.x);
    o.y = to_tf32((v.y - mean) * rstd * gv.y + bv.y);
    o.z = to_tf32((v.z - mean) * rstd * gv.z + bv.z);
    o.w = to_tf32((v.w - mean) * rstd * gv.w + bv.w);
    ((float4*)(y + (size_t)row * EE))[tid] = o;
}

// fp32 -> plain bf16 (1-term)
__global__ void conv1_kernel(const float* __restrict__ X, __nv_bfloat16* __restrict__ Y,
                             int total4) {
    int idx = blockIdx.x * blockDim.x + threadIdx.x;
    if (idx >= total4) return;
    float4 v = ((const float4*)X)[idx];
    uint2 pk;
    pk.x = pack_bf16x2(v.x, v.y);
    pk.y = pack_bf16x2(v.z, v.w);
    ((uint2*)Y)[idx] = pk;
}

// fp32 -> tf32-rounded fp32
__global__ void conv_tf32_kernel(const float* __restrict__ X, float* __restrict__ Y,
                                 int total4) {
    int idx = blockIdx.x * blockDim.x + threadIdx.x;
    if (idx >= total4) return;
    float4 v = ((const float4*)X)[idx];
    v.x = to_tf32(v.x); v.y = to_tf32(v.y); v.z = to_tf32(v.z); v.w = to_tf32(v.w);
    ((float4*)Y)[idx] = v;
}

// ---------------- bias concatenation ----------------
__global__ void biascat_kernel(const float* __restrict__ b0, const float* __restrict__ b1,
                               const float* __restrict__ b2, float* __restrict__ out) {
    int seg = blockIdx.x;
    const float* src = seg == 0 ? b0 : (seg == 1 ? b1 : b2);
    out[seg * 1024 + threadIdx.x] = src[threadIdx.x];
}

// ---------------- common tile geometry ----------------
#define GBM 128
#define GBN 128
#define AST (GBM*128)               // A stage bytes (128 rows x 128B)
#define GSTAGE (AST + GBN*128)      // 32768
#define GSMEM (3*GSTAGE + 1024)     // 3 stages, single barrier; 2 CTAs/SM (194KB < 228KB)

// ---------------- HMMA bf16 GEMM (attention path) ----
// EPI: 0 = bias -> fp32, 1 = bias + residual -> fp32,
//      4 = bias, x0.125 on cols < qcols, -> bf16 (qkv path)
template<int EPI>
__global__ void __launch_bounds__(256, 2)
gemm_mma(const __nv_bfloat16* __restrict__ A, const __nv_bfloat16* __restrict__ B,
         const float* __restrict__ bias, const float* __restrict__ R,
         float* __restrict__ C, __nv_bfloat16* __restrict__ C2, int qcols,
         int M, int N, int K) {
    extern __shared__ char dyn_smem[];
    const int tid  = threadIdx.x;
    const int lane = tid & 31;
    const int wid  = tid >> 5;
    const int wm   = wid & 1;
    const int wn   = wid >> 1;
    const int bm = blockIdx.y * GBM;
    const int bn = blockIdx.x * GBN;

    uint32_t raw = smem_u32(dyn_smem);
    uint32_t sb  = (raw + 1023u) & ~1023u;

    const size_t ldb = (size_t)K * 2;
    const char* Abase = (const char*)(A + (size_t)bm * K);
    const char* Bbase = (const char*)(B + (size_t)bn * K);

    auto issue_stage = [&](int kt, int s) {
        uint32_t dst = sb + s * GSTAGE;
        const char* Ab = Abase + (size_t)kt * 128;   // 64 bf16 = 128B
        const char* Bb = Bbase + (size_t)kt * 128;
        #pragma unroll
        for (int p = 0; p < 4; p++) {
            int g   = (p << 8) + tid;
            int row = g >> 3;
            int seg = (g & 7) << 4;
            uint32_t off = SWZ(row * 128 + seg);
            CP_ASYNC16(dst + off,       Ab + (size_t)row * ldb + seg);
            CP_ASYNC16(dst + AST + off, Bb + (size_t)row * ldb + seg);
        }
        CP_COMMIT();
    };

    float acc[4][4][4];
    #pragma unroll
    for (int i = 0; i < 4; i++)
        #pragma unroll
        for (int j = 0; j < 4; j++)
            #pragma unroll
            for (int t = 0; t < 4; t++) acc[i][j][t] = 0.f;

    const int nk = K / 64;
    issue_stage(0, 0);
    issue_stage(1, 1);

    const int a_row = wm * 64 + (lane & 15);
    const int a_kb  = (lane >> 4) << 4;
    const int bp_row = wn * 32 + ((lane >> 4) << 3) + (lane & 7);
    const int bp_kb  = (((lane >> 3) & 1) << 4);

    for (int kt = 0; kt < nk; kt++) {
        if (kt + 1 < nk) { CP_WAIT1(); } else { CP_WAIT0(); }
        __syncthreads();
        if (kt + 2 < nk) issue_stage(kt + 2, (kt + 2) % 3);

        uint32_t ab = sb + (kt % 3) * GSTAGE;
        uint32_t bb = ab + AST;
        #pragma unroll
        for (int kk = 0; kk < 4; kk++) {
            uint32_t af[4][4], bfr[4][2];
            #pragma unroll
            for (int i = 0; i < 4; i++)
                ldsm_x4(af[i][0], af[i][1], af[i][2], af[i][3],
                        ab + SWZ((a_row + i*16) * 128 + kk*32 + a_kb));
            #pragma unroll
            for (int j = 0; j < 2; j++)
                ldsm_x4(bfr[2*j][0], bfr[2*j][1], bfr[2*j+1][0], bfr[2*j+1][1],
                        bb + SWZ((bp_row + j*16) * 128 + kk*32 + bp_kb));
            #pragma unroll
            for (int i = 0; i < 4; i++)
                #pragma unroll
                for (int j = 0; j < 4; j++)
                    mma_bf16(acc[i][j], af[i], bfr[j]);
        }
    }

    const int er = (lane >> 2);
    const int ec = (lane & 3) << 1;
    #pragma unroll
    for (int i = 0; i < 4; i++) {
        #pragma unroll
        for (int j = 0; j < 4; j++) {
            int col = bn + wn*32 + j*8 + ec;
            float bx = bias[col], by = bias[col + 1];
            float sc = (EPI == 4 && col < qcols) ? 0.125f : 1.0f;
            #pragma unroll
            for (int h = 0; h < 2; h++) {
                int row = bm + wm*64 + i*16 + er + h*8;
                float vx = acc[i][j][h*2 + 0] + bx;
                float vy = acc[i][j][h*2 + 1] + by;
                if (EPI == 1) {
                    const float2 rr = *(const float2*)(R + (size_t)row * N + col);
                    vx += rr.x; vy += rr.y;
                }
                if (EPI == 4) {
                    *(uint32_t*)(C2 + (size_t)row * N + col) = pack_bf16x2(vx * sc, vy * sc);
                } else {
                    *(float2*)(C + (size_t)row * N + col) = make_float2(vx, vy);
                }
            }
        }
    }
}

// ---------------- TF32 GEMM (FFN path) ----
// EPI: 1 = bias + residual -> fp32, 3 = bias + gelu -> tf32-rounded fp32
template<int EPI>
__global__ void __launch_bounds__(256, 2)
gemm_tf32(const float* __restrict__ A, const float* __restrict__ B,
          const float* __restrict__ bias, const float* __restrict__ R,
          float* __restrict__ C, int M, int N, int K) {
    extern __shared__ char dyn_smem[];
    const int tid  = threadIdx.x;
    const int lane = tid & 31;
    const int wid  = tid >> 5;
    const int wm   = wid & 1;
    const int wn   = wid >> 1;
    const int bm = blockIdx.y * GBM;
    const int bn = blockIdx.x * GBN;

    uint32_t raw = smem_u32(dyn_smem);
    uint32_t sb  = (raw + 1023u) & ~1023u;

    const size_t ldb = (size_t)K * 4;
    const char* Abase = (const char*)(A + (size_t)bm * K);
    const char* Bbase = (const char*)(B + (size_t)bn * K);

    auto issue_stage = [&](int kt, int s) {
        uint32_t dst = sb + s * GSTAGE;
        const char* Ab = Abase + (size_t)kt * 128;   // 32 fp32 = 128B
        const char* Bb = Bbase + (size_t)kt * 128;
        #pragma unroll
        for (int p = 0; p < 4; p++) {
            int g   = (p << 8) + tid;
            int row = g >> 3;
            int seg = (g & 7) << 4;
            uint32_t off = SWZ(row * 128 + seg);
            CP_ASYNC16(dst + off,       Ab + (size_t)row * ldb + seg);
            CP_ASYNC16(dst + AST + off, Bb + (size_t)row * ldb + seg);
        }
        CP_COMMIT();
    };

    float acc[4][4][4];
    #pragma unroll
    for (int i = 0; i < 4; i++)
        #pragma unroll
        for (int j = 0; j < 4; j++)
            #pragma unroll
            for (int t = 0; t < 4; t++) acc[i][j][t] = 0.f;

    const int nk = K / 32;
    issue_stage(0, 0);
    issue_stage(1, 1);

    const int a_row  = wm * 64 + (lane & 7) + ((lane >> 3) & 1) * 8;
    const int a_colb = ((lane >> 4) & 1) << 4;
    const int b_row  = wn * 32 + (lane & 7) + ((lane >> 4) & 1) * 8;
    const int b_colb = ((lane >> 3) & 1) << 4;

    for (int kt = 0; kt < nk; kt++) {
        if (kt + 1 < nk) { CP_WAIT1(); } else { CP_WAIT0(); }
        __syncthreads();
        if (kt + 2 < nk) issue_stage(kt + 2, (kt + 2) % 3);

        uint32_t ab = sb + (kt % 3) * GSTAGE;
        uint32_t bb = ab + AST;
        #pragma unroll
        for (int kk = 0; kk < 4; kk++) {
            uint32_t af[4][4], bfr[4][2];
            #pragma unroll
            for (int i = 0; i < 4; i++)
                ldsm_x4(af[i][0], af[i][1], af[i][2], af[i][3],
                        ab + SWZ((a_row + i*16) * 128 + kk*32 + a_colb));
            #pragma unroll
            for (int j = 0; j < 2; j++)
                ldsm_x4(bfr[2*j][0], bfr[2*j][1], bfr[2*j+1][0], bfr[2*j+1][1],
                        bb + SWZ((b_row + j*16) * 128 + kk*32 + b_colb));
            #pragma unroll
            for (int i = 0; i < 4; i++)
                #pragma unroll
                for (int j = 0; j < 4; j++)
                    mma_tf32(acc[i][j], af[i], bfr[j]);
        }
    }

    const int er = (lane >> 2);
    const int ec = (lane & 3) << 1;
    #pragma unroll
    for (int i = 0; i < 4; i++) {
        #pragma unroll
        for (int j = 0; j < 4; j++) {
            int col = bn + wn*32 + j*8 + ec;
            float bx = bias[col], by = bias[col + 1];
            #pragma unroll
            for (int h = 0; h < 2; h++) {
                int row = bm + wm*64 + i*16 + er + h*8;
                float vx = acc[i][j][h*2 + 0] + bx;
                float vy = acc[i][j][h*2 + 1] + by;
                if (EPI == 1) {
                    const float2 rr = *(const float2*)(R + (size_t)row * N + col);
                    vx += rr.x; vy += rr.y;
                } else if (EPI == 3) {
                    vx = to_tf32(0.5f * vx * (1.0f + erff(vx * 0.70710678118654752f)));
                    vy = to_tf32(0.5f * vy * (1.0f + erff(vy * 0.70710678118654752f)));
                }
                *(float2*)(C + (size_t)row * N + col) = make_float2(vx, vy);
            }
        }
    }
}

// ---------------- HMMA flash attention (causal always per reference) ----
// bf16 inputs (Q pre-scaled by 0.125); bf16 output (row stride EE).
__global__ void __launch_bounds__(128)
attn_mma(const __nv_bfloat16* __restrict__ Q, int ldq,
         const __nv_bfloat16* __restrict__ Kp, int ldk,
         const __nv_bfloat16* __restrict__ Vp, int ldv,
         __nv_bfloat16* __restrict__ O) {
    __shared__ __nv_bfloat16 Qs[64*64];
    __shared__ __nv_bfloat16 Ks[64*64];
    __shared__ __nv_bfloat16 Vt[64*64];   // [d][kv]

    const int b = blockIdx.y, qi = blockIdx.x;
    const int n = b >> 4, hh = b & 15;
    const int tid = threadIdx.x, lane = tid & 31, w = tid >> 5;
    const int qbase = qi * 64;
    const uint32_t qs = smem_u32(Qs), ks = smem_u32(Ks), vt = smem_u32(Vt);

    // Q tile: direct swizzled copy (already bf16, scaled)
    for (int i = tid; i < 512; i += 128) {
        int rr = i >> 3, sb8 = (i & 7) << 4;
        *(uint4*)((char*)Qs + SWZ(rr*128 + sb8)) =
            *(const uint4*)((const char*)(Q + (size_t)((qbase+rr)*NN + n) * ldq + hh*HD) + sb8);
    }

    const int r  = lane >> 2;
    const int cb = (lane & 3) << 1;

    float m0 = -1e30f, m1 = -1e30f, l0 = 0.f, l1 = 0.f;
    float oac[8][4];
    #pragma unroll
    for (int t = 0; t < 8; t++)
        #pragma unroll
        for (int e = 0; e < 4; e++) oac[t][e] = 0.f;

    for (int j = 0; j <= qi; j++) {
        __syncthreads();
        for (int i = tid; i < 512; i += 128) {
            int rr = i >> 3, sb8 = (i & 7) << 4;
            const char* kb = (const char*)(Kp + (size_t)((j*64+rr)*NN + n) * ldk + hh*HD);
            *(uint4*)((char*)Ks + SWZ(rr*128 + sb8)) = *(const uint4*)(kb + sb8);
            const char* vb = (const char*)(Vp + (size_t)((j*64+rr)*NN + n) * ldv + hh*HD);
            uint4 vv = *(const uint4*)(vb + sb8);
            const __nv_bfloat16* ve = (const __nv_bfloat16*)&vv;
            int c0 = (i & 7) << 3;
            #pragma unroll
            for (int e = 0; e < 8; e++)
                *(__nv_bfloat16*)((char*)Vt + SWZ((c0+e)*128 + rr*2)) = ve[e];
        }
        __syncthreads();

        uint32_t af[4][4];
        #pragma unroll
        for (int kk = 0; kk < 4; kk++)
            ldsm_x4(af[kk][0], af[kk][1], af[kk][2], af[kk][3],
                    qs + SWZ((w*16 + (lane & 15))*128 + kk*32 + ((lane >> 4) << 4)));

        float sac[8][4];
        #pragma unroll
        for (int t = 0; t < 8; t++) {
            sac[t][0] = sac[t][1] = sac[t][2] = sac[t][3] = 0.f;
            #pragma unroll
            for (int kk = 0; kk < 4; kk++) {
                uint32_t bfr[2];
                ldsm_x2(bfr[0], bfr[1],
                        ks + SWZ((t*8 + (lane & 7))*128 + kk*32 + (((lane >> 3) & 1) << 4)));
                mma_bf16(sac[t], af[kk], bfr);
            }
        }

        if (j == qi) {
            int grow0 = qbase + w*16 + r;
            int grow1 = grow0 + 8;
            #pragma unroll
            for (int t = 0; t < 8; t++) {
                int gc = j*64 + t*8 + cb;
                if (gc     > grow0) sac[t][0] = -10000.0f;
                if (gc + 1 > grow0) sac[t][1] = -10000.0f;
                if (gc     > grow1) sac[t][2] = -10000.0f;
                if (gc + 1 > grow1) sac[t][3] = -10000.0f;
            }
        }

        float mx0 = -1e30f, mx1 = -1e30f;
        #pragma unroll
        for (int t = 0; t < 8; t++) {
            mx0 = fmaxf(mx0, fmaxf(sac[t][0], sac[t][1]));
            mx1 = fmaxf(mx1, fmaxf(sac[t][2], sac[t][3]));
        }
        mx0 = fmaxf(mx0, __shfl_xor_sync(0xffffffffu, mx0, 1));
        mx0 = fmaxf(mx0, __shfl_xor_sync(0xffffffffu, mx0, 2));
        mx1 = fmaxf(mx1, __shfl_xor_sync(0xffffffffu, mx1, 1));
        mx1 = fmaxf(mx1, __shfl_xor_sync(0xffffffffu, mx1, 2));
        float mn0 = fmaxf(m0, mx0), mn1 = fmaxf(m1, mx1);
        float al0 = __expf(m0 - mn0), al1 = __expf(m1 - mn1);
        float ls0 = 0.f, ls1 = 0.f;
        #pragma unroll
        for (int t = 0; t < 8; t++) {
            sac[t][0] = __expf(sac[t][0] - mn0);
            sac[t][1] = __expf(sac[t][1] - mn0);
            sac[t][2] = __expf(sac[t][2] - mn1);
            sac[t][3] = __expf(sac[t][3] - mn1);
            ls0 += sac[t][0] + sac[t][1];
            ls1 += sac[t][2] + sac[t][3];
        }
        ls0 += __shfl_xor_sync(0xffffffffu, ls0, 1);
        ls0 += __shfl_xor_sync(0xffffffffu, ls0, 2);
        ls1 += __shfl_xor_sync(0xffffffffu, ls1, 1);
        ls1 += __shfl_xor_sync(0xffffffffu, ls1, 2);
        l0 = l0 * al0 + ls0;  m0 = mn0;
        l1 = l1 * al1 + ls1;  m1 = mn1;
        #pragma unroll
        for (int t = 0; t < 8; t++) {
            oac[t][0] *= al0; oac[t][1] *= al0;
            oac[t][2] *= al1; oac[t][3] *= al1;
        }

        uint32_t pf[4][4];
        #pragma unroll
        for (int kt = 0; kt < 4; kt++) {
            pf[kt][0] = pack_bf16x2(sac[2*kt][0],   sac[2*kt][1]);
            pf[kt][1] = pack_bf16x2(sac[2*kt][2],   sac[2*kt][3]);
            pf[kt][2] = pack_bf16x2(sac[2*kt+1][0], sac[2*kt+1][1]);
            pf[kt][3] = pack_bf16x2(sac[2*kt+1][2], sac[2*kt+1][3]);
        }

        #pragma unroll
        for (int td = 0; td < 8; td++) {
            #pragma unroll
            for (int kt = 0; kt < 4; kt++) {
                uint32_t bfr[2];
                ldsm_x2(bfr[0], bfr[1],
                        vt + SWZ((td*8 + (lane & 7))*128 + kt*32 + (((lane >> 3) & 1) << 4)));
                mma_bf16(oac[td], pf[kt], bfr);
            }
        }
    }

    float inv0 = 1.0f / l0, inv1 = 1.0f / l1;
    int row0 = qbase + w*16 + r;
    int row1 = row0 + 8;
    #pragma unroll
    for (int td = 0; td < 8; td++) {
        int col = td*8 + cb;
        *(uint32_t*)(O + (size_t)(row0*NN + n) * EE + hh*HD + col) =
            pack_bf16x2(oac[td][0]*inv0, oac[td][1]*inv0);
        *(uint32_t*)(O + (size_t)(row1*NN + n) * EE + hh*HD + col) =
            pack_bf16x2(oac[td][2]*inv1, oac[td][3]*inv1);
    }
}

// ---------------- orchestration ----------------
static void conv1(const float* X, __nv_bfloat16* Y, size_t elems) {
    int t4 = (int)(elems / 4);
    conv1_kernel<<<(t4 + 255) / 256, 256>>>(X, Y, t4);
}
static void convtf(const float* X, float* Y, size_t elems) {
    int t4 = (int)(elems / 4);
    conv_tf32_kernel<<<(t4 + 255) / 256, 256>>>(X, Y, t4);
}
static void run_gemm(int epi, const __nv_bfloat16* A, const __nv_bfloat16* B,
                     const float* bias, const float* R, float* C, __nv_bfloat16* C2,
                     int qcols, int M_, int N_, int K_) {
    dim3 grid(N_ / GBN, M_ / GBM);
    if (epi == 0)      gemm_mma<0><<<grid, 256, GSMEM>>>(A, B, bias, R, C, C2, qcols, M_, N_, K_);
    else if (epi == 1) gemm_mma<1><<<grid, 256, GSMEM>>>(A, B, bias, R, C, C2, qcols, M_, N_, K_);
    else               gemm_mma<4><<<grid, 256, GSMEM>>>(A, B, bias, R, C, C2, qcols, M_, N_, K_);
}
static void run_gemm_tf(int epi, const float* A, const float* B,
                        const float* bias, const float* R, float* C,
                        int M_, int N_, int K_) {
    dim3 grid(N_ / GBN, M_ / GBM);
    if (epi == 1) gemm_tf32<1><<<grid, 256, GSMEM>>>(A, B, bias, R, C, M_, N_, K_);
    else          gemm_tf32<3><<<grid, 256, GSMEM>>>(A, B, bias, R, C, M_, N_, K_);
}

extern "C" void kernel_launch(void* const* d_in, const int* in_sizes, int n_in,
                              void* d_out, int out_size) {
    const float* x    = (const float*)d_in[0];
    const float* enc  = (const float*)d_in[1];
    const float* wq_s = (const float*)d_in[2];
    const float* bq_s = (const float*)d_in[3];
    const float* wk_s = (const float*)d_in[4];
    const float* bk_s = (const float*)d_in[5];
    const float* wv_s = (const float*)d_in[6];
    const float* bv_s = (const float*)d_in[7];
    const float* wo_s = (const float*)d_in[8];
    const float* bo_s = (const float*)d_in[9];
    const float* wq_c = (const float*)d_in[10];
    const float* bq_c = (const float*)d_in[11];
    const float* wk_c = (const float*)d_in[12];
    const float* bk_c = (const float*)d_in[13];
    const float* wv_c = (const float*)d_in[14];
    const float* bv_c = (const float*)d_in[15];
    const float* wo_c = (const float*)d_in[16];
    const float* bo_c = (const float*)d_in[17];
    const float* ln1_g = (const float*)d_in[18];
    const float* ln1_b = (const float*)d_in[19];
    const float* ln2_g = (const float*)d_in[20];
    const float* ln2_b = (const float*)d_in[21];
    const float* ln3_g = (const float*)d_in[22];
    const float* ln3_b = (const float*)d_in[23];
    const float* fc1_w = (const float*)d_in[24];
    const float* fc1_b = (const float*)d_in[25];
    const float* fc2_w = (const float*)d_in[26];
    const float* fc2_b = (const float*)d_in[27];
    float* out = (float*)d_out;

    float *p_tf, *p_ff, *p_bcat, *p_wtf0, *p_wtf1;
    __nv_bfloat16 *p_a3, *p_w3, *p_qkv, *p_qc;
    cudaGetSymbolAddress((void**)&p_tf,   g_tf);
    cudaGetSymbolAddress((void**)&p_ff,   g_ff);
    cudaGetSymbolAddress((void**)&p_a3,   g_a3);
    cudaGetSymbolAddress((void**)&p_qkv,  g_qkv);
    cudaGetSymbolAddress((void**)&p_qc,   g_qc);
    cudaGetSymbolAddress((void**)&p_w3,   g_w3);
    cudaGetSymbolAddress((void**)&p_wtf0, g_wtf);
    p_wtf1 = p_wtf0 + (size_t)EE * FF;
    cudaGetSymbolAddress((void**)&p_bcat, g_bcat);

    cudaFuncSetAttribute(gemm_mma<0>,  cudaFuncAttributeMaxDynamicSharedMemorySize, GSMEM);
    cudaFuncSetAttribute(gemm_mma<1>,  cudaFuncAttributeMaxDynamicSharedMemorySize, GSMEM);
    cudaFuncSetAttribute(gemm_mma<4>,  cudaFuncAttributeMaxDynamicSharedMemorySize, GSMEM);
    cudaFuncSetAttribute(gemm_tf32<1>, cudaFuncAttributeMaxDynamicSharedMemorySize, GSMEM);
    cudaFuncSetAttribute(gemm_tf32<3>, cudaFuncAttributeMaxDynamicSharedMemorySize, GSMEM);

    dim3 agrid(LL / 64, NN * HH);   // 16 x 64
    const size_t W1 = (size_t)EE * EE;

    // ---- block 1: self-attention (fused QKV -> bf16 with q pre-scaled) ----
    ln_bf16_kernel<<<MM, 256>>>(x, ln1_g, ln1_b, p_a3);
    conv1(wq_s, p_w3,         W1);
    conv1(wk_s, p_w3 + W1,    W1);
    conv1(wv_s, p_w3 + 2*W1,  W1);
    biascat_kernel<<<3, 1024>>>(bq_s, bk_s, bv_s, p_bcat);
    run_gemm(4, p_a3, p_w3, p_bcat, nullptr, nullptr, p_qkv, EE, MM, 3*EE, EE);
    attn_mma<<<agrid, 128>>>(p_qkv, 3*EE, p_qkv + EE, 3*EE, p_qkv + 2*EE, 3*EE, p_a3);
    conv1(wo_s, p_w3, W1);
    run_gemm(1, p_a3, p_w3, bo_s, x, out, nullptr, 0, MM, EE, EE);

    // ---- block 2: cross-attention (reference applies causal mask here too) ----
    ln_bf16_kernel<<<MM, 256>>>(out, ln2_g, ln2_b, p_a3);
    conv1(wq_c, p_w3, W1);
    run_gemm(4, p_a3, p_w3, bq_c, nullptr, nullptr, p_qc, EE, MM, EE, EE);
    conv1(enc, p_a3, (size_t)MM * EE);
    conv1(wk_c, p_w3,      W1);
    conv1(wv_c, p_w3 + W1, W1);
    biascat_kernel<<<2, 1024>>>(bk_c, bv_c, nullptr, p_bcat);
    run_gemm(4, p_a3, p_w3, p_bcat, nullptr, nullptr, p_qkv, 0, MM, 2*EE, EE);
    attn_mma<<<agrid, 128>>>(p_qc, EE, p_qkv, 2*EE, p_qkv + EE, 2*EE, p_a3);
    conv1(wo_c, p_w3, W1);
    run_gemm(1, p_a3, p_w3, bo_c, out, out, nullptr, 0, MM, EE, EE);

    // ---- block 3: FFN (1-term TF32) ----
    ln_tf32_kernel<<<MM, 256>>>(out, ln3_g, ln3_b, p_tf);
    convtf(fc1_w, p_wtf0, (size_t)FF * EE);
    run_gemm_tf(3, p_tf, p_wtf0, fc1_b, nullptr, p_ff, MM, FF, EE);
    convtf(fc2_w, p_wtf1, (size_t)EE * FF);
    run_gemm_tf(1, p_ff, p_wtf1, fc2_b, out, out, MM, EE, FF);
}

// round 13
// speedup vs baseline: 6.1526x; 1.0702x over previous
#include <cuda_runtime.h>
#include <cuda_bf16.h>
#include <math.h>
#include <stdint.h>

// Problem constants: L=1024, N=4, E=1024, F=4096, H=16, d=64
#define LL 1024
#define NN 4
#define EE 1024
#define FF 4096
#define HH 16
#define HD 64
#define MM (LL*NN)   // 4096 rows

// ---------------- scratch (static device allocations) ----------------
__device__ float g_tf[MM*EE];                         // LN3 tf32 out
__device__ float g_ff[(size_t)MM*FF];                 // fc1 gelu out (tf32 fp32)
__device__ __nv_bfloat16 g_a3[(size_t)MM * 3 * EE];   // LN bf16 / attn out / enc bf16
__device__ __nv_bfloat16 g_qkv[(size_t)MM * 3 * EE];  // fused qkv / kv bf16 outputs
__device__ __nv_bfloat16 g_qc[(size_t)MM * EE];       // cross-attn q bf16
__device__ __nv_bfloat16 g_w3[(size_t)EE * 3 * EE];   // attn-path weight bf16
__device__ float g_bcat[3*EE];                        // concatenated bias

// ---------------- portable PTX helpers -------
__device__ __forceinline__ uint32_t smem_u32(const void* p) {
    uint32_t a;
    asm("{ .reg .u64 t; cvta.to.shared.u64 t, %1; cvt.u32.u64 %0, t; }" : "=r"(a) : "l"(p));
    return a;
}

#define SWZ(x) ((x) ^ (((x) >> 3) & 0x70))

#define CP_ASYNC16(dst_u32, src_ptr) \
    asm volatile("cp.async.cg.shared.global [%0], [%1], 16;" \
        :: "r"(dst_u32), "l"(src_ptr) : "memory")
#define CP_COMMIT() asm volatile("cp.async.commit_group;" ::: "memory")
#define CP_WAIT1()  asm volatile("cp.async.wait_group 1;" ::: "memory")
#define CP_WAIT0()  asm volatile("cp.async.wait_group 0;" ::: "memory")

__device__ __forceinline__ void ldsm_x4(uint32_t& r0, uint32_t& r1, uint32_t& r2, uint32_t& r3,
                                        uint32_t addr) {
    asm volatile("ldmatrix.sync.aligned.m8n8.x4.shared.b16 {%0,%1,%2,%3}, [%4];"
        : "=r"(r0), "=r"(r1), "=r"(r2), "=r"(r3) : "r"(addr));
}
__device__ __forceinline__ void ldsm_x2(uint32_t& r0, uint32_t& r1, uint32_t addr) {
    asm volatile("ldmatrix.sync.aligned.m8n8.x2.shared.b16 {%0,%1}, [%2];"
        : "=r"(r0), "=r"(r1) : "r"(addr));
}
__device__ __forceinline__ void mma_bf16(float* d, const uint32_t* a, const uint32_t* b) {
    asm volatile("mma.sync.aligned.m16n8k16.row.col.f32.bf16.bf16.f32 "
        "{%0,%1,%2,%3}, {%4,%5,%6,%7}, {%8,%9}, {%0,%1,%2,%3};"
        : "+f"(d[0]), "+f"(d[1]), "+f"(d[2]), "+f"(d[3])
        : "r"(a[0]), "r"(a[1]), "r"(a[2]), "r"(a[3]), "r"(b[0]), "r"(b[1]));
}
__device__ __forceinline__ void mma_tf32(float* d, const uint32_t* a, const uint32_t* b) {
    asm volatile("mma.sync.aligned.m16n8k8.row.col.f32.tf32.tf32.f32 "
        "{%0,%1,%2,%3}, {%4,%5,%6,%7}, {%8,%9}, {%0,%1,%2,%3};"
        : "+f"(d[0]), "+f"(d[1]), "+f"(d[2]), "+f"(d[3])
        : "r"(a[0]), "r"(a[1]), "r"(a[2]), "r"(a[3]), "r"(b[0]), "r"(b[1]));
}
__device__ __forceinline__ uint32_t pack_bf16x2(float x, float y) {
    __nv_bfloat162 h = __floats2bfloat162_rn(x, y);
    return *(uint32_t*)&h;
}
__device__ __forceinline__ float to_tf32(float x) {
    uint32_t u;
    asm("cvt.rna.tf32.f32 %0, %1;" : "=r"(u) : "f"(x));
    return __uint_as_float(u);
}

// ---------------- layernorm core ----------------
__device__ __forceinline__ void ln_core(const float* __restrict__ x, int row, int tid,
                                        float4& v, float& mean, float& rstd) {
    const float4* xr = (const float4*)(x + (size_t)row * EE);
    v = xr[tid];
    float s  = v.x + v.y + v.z + v.w;
    float sq = v.x*v.x + v.y*v.y + v.z*v.z + v.w*v.w;
    #pragma unroll
    for (int off = 16; off > 0; off >>= 1) {
        s  += __shfl_down_sync(0xffffffffu, s,  off);
        sq += __shfl_down_sync(0xffffffffu, sq, off);
    }
    __shared__ float rs[8], rq[8];
    __shared__ float s_mean, s_rstd;
    int lane = tid & 31, wid = tid >> 5;
    if (lane == 0) { rs[wid] = s; rq[wid] = sq; }
    __syncthreads();
    if (tid == 0) {
        float ts = 0.f, tq = 0.f;
        #pragma unroll
        for (int i = 0; i < 8; i++) { ts += rs[i]; tq += rq[i]; }
        float mn = ts * (1.0f / EE);
        float var = tq * (1.0f / EE) - mn * mn;
        s_mean = mn;
        s_rstd = rsqrtf(var + 1e-5f);
    }
    __syncthreads();
    mean = s_mean; rstd = s_rstd;
}

// LN -> 1-term bf16 (row stride EE)
__global__ void ln_bf16_kernel(const float* __restrict__ x, const float* __restrict__ g,
                               const float* __restrict__ b, __nv_bfloat16* __restrict__ y) {
    int row = blockIdx.x, tid = threadIdx.x;
    float4 v; float mean, rstd;
    ln_core(x, row, tid, v, mean, rstd);
    float4 gv = ((const float4*)g)[tid], bv = ((const float4*)b)[tid];
    float ox = (v.x - mean) * rstd * gv.x + bv.x;
    float oy = (v.y - mean) * rstd * gv.y + bv.y;
    float oz = (v.z - mean) * rstd * gv.z + bv.z;
    float ow = (v.w - mean) * rstd * gv.w + bv.w;
    uint2 pk; pk.x = pack_bf16x2(ox, oy); pk.y = pack_bf16x2(oz, ow);
    *(uint2*)(y + (size_t)row * EE + tid * 4) = pk;
}

// LN -> tf32-rounded fp32 (row stride EE)
__global__ void ln_tf32_kernel(const float* __restrict__ x, const float* __restrict__ g,
                               const float* __restrict__ b, float* __restrict__ y) {
    int row = blockIdx.x, tid = threadIdx.x;
    float4 v; float mean, rstd;
    ln_core(x, row, tid, v, mean, rstd);
    float4 gv = ((const float4*)g)[tid], bv = ((const float4*)b)[tid];
    float4 o;
    o.x = to_tf32((v.x - mean) * rstd * gv.x + bv.x);
    o.y = to_tf32((v.y - mean) * rstd * gv.y + bv.y);
    o.z = to_tf32((v.z - mean) * rstd * gv.z + bv.z);
    o.w = to_tf32((v.w - mean) * rstd * gv.w + bv.w);
    ((float4*)(y + (size_t)row * EE))[tid] = o;
}

// fp32 -> plain bf16 (1-term)
__global__ void conv1_kernel(const float* __restrict__ X, __nv_bfloat16* __restrict__ Y,
                             int total4) {
    int idx = blockIdx.x * blockDim.x + threadIdx.x;
    if (idx >= total4) return;
    float4 v = ((const float4*)X)[idx];
    uint2 pk;
    pk.x = pack_bf16x2(v.x, v.y);
    pk.y = pack_bf16x2(v.z, v.w);
    ((uint2*)Y)[idx] = pk;
}

// up to 3 fp32 sources -> contiguous bf16 segments (batched weight convert)
__global__ void conv3_kernel(const float* __restrict__ s0, const float* __restrict__ s1,
                             const float* __restrict__ s2, __nv_bfloat16* __restrict__ Y,
                             int per4) {
    int idx = blockIdx.x * blockDim.x + threadIdx.x;
    if (idx >= per4) return;
    int seg = blockIdx.y;
    const float* S = seg == 0 ? s0 : (seg == 1 ? s1 : s2);
    float4 v = ((const float4*)S)[idx];
    uint2 pk;
    pk.x = pack_bf16x2(v.x, v.y);
    pk.y = pack_bf16x2(v.z, v.w);
    ((uint2*)(Y + (size_t)seg * per4 * 4))[idx] = pk;
}

// ---------------- bias concatenation ----------------
__global__ void biascat_kernel(const float* __restrict__ b0, const float* __restrict__ b1,
                               const float* __restrict__ b2, float* __restrict__ out) {
    int seg = blockIdx.x;
    const float* src = seg == 0 ? b0 : (seg == 1 ? b1 : b2);
    out[seg * 1024 + threadIdx.x] = src[threadIdx.x];
}

// ---------------- common tile geometry ----------------
#define GBM 128
#define GBN 128
#define AST (GBM*128)               // A stage bytes (128 rows x 128B)
#define GSTAGE (AST + GBN*128)      // 32768
#define GSMEM (3*GSTAGE + 1024)     // 3 stages; 2 CTAs/SM

// ---------------- HMMA bf16 GEMM (attention path) ----
// EPI: 1 = bias + residual -> fp32, 4 = bias, x0.125 on cols < qcols -> bf16
template<int EPI>
__global__ void __launch_bounds__(256, 2)
gemm_mma(const __nv_bfloat16* __restrict__ A, const __nv_bfloat16* __restrict__ B,
         const float* __restrict__ bias, const float* __restrict__ R,
         float* __restrict__ C, __nv_bfloat16* __restrict__ C2, int qcols,
         int M, int N, int K) {
    extern __shared__ char dyn_smem[];
    const int tid  = threadIdx.x;
    const int lane = tid & 31;
    const int wid  = tid >> 5;
    const int wm   = wid & 1;
    const int wn   = wid >> 1;
    const int bm = blockIdx.y * GBM;
    const int bn = blockIdx.x * GBN;

    uint32_t raw = smem_u32(dyn_smem);
    uint32_t sb  = (raw + 1023u) & ~1023u;

    const size_t ldb = (size_t)K * 2;
    const char* Abase = (const char*)(A + (size_t)bm * K);
    const char* Bbase = (const char*)(B + (size_t)bn * K);

    auto issue_stage = [&](int kt, int s) {
        uint32_t dst = sb + s * GSTAGE;
        const char* Ab = Abase + (size_t)kt * 128;   // 64 bf16 = 128B
        const char* Bb = Bbase + (size_t)kt * 128;
        #pragma unroll
        for (int p = 0; p < 4; p++) {
            int g   = (p << 8) + tid;
            int row = g >> 3;
            int seg = (g & 7) << 4;
            uint32_t off = SWZ(row * 128 + seg);
            CP_ASYNC16(dst + off,       Ab + (size_t)row * ldb + seg);
            CP_ASYNC16(dst + AST + off, Bb + (size_t)row * ldb + seg);
        }
        CP_COMMIT();
    };

    float acc[4][4][4];
    #pragma unroll
    for (int i = 0; i < 4; i++)
        #pragma unroll
        for (int j = 0; j < 4; j++)
            #pragma unroll
            for (int t = 0; t < 4; t++) acc[i][j][t] = 0.f;

    const int nk = K / 64;
    issue_stage(0, 0);
    issue_stage(1, 1);

    const int a_row = wm * 64 + (lane & 15);
    const int a_kb  = (lane >> 4) << 4;
    const int bp_row = wn * 32 + ((lane >> 4) << 3) + (lane & 7);
    const int bp_kb  = (((lane >> 3) & 1) << 4);

    for (int kt = 0; kt < nk; kt++) {
        if (kt + 1 < nk) { CP_WAIT1(); } else { CP_WAIT0(); }
        __syncthreads();
        if (kt + 2 < nk) issue_stage(kt + 2, (kt + 2) % 3);

        uint32_t ab = sb + (kt % 3) * GSTAGE;
        uint32_t bb = ab + AST;
        #pragma unroll
        for (int kk = 0; kk < 4; kk++) {
            uint32_t af[4][4], bfr[4][2];
            #pragma unroll
            for (int i = 0; i < 4; i++)
                ldsm_x4(af[i][0], af[i][1], af[i][2], af[i][3],
                        ab + SWZ((a_row + i*16) * 128 + kk*32 + a_kb));
            #pragma unroll
            for (int j = 0; j < 2; j++)
                ldsm_x4(bfr[2*j][0], bfr[2*j][1], bfr[2*j+1][0], bfr[2*j+1][1],
                        bb + SWZ((bp_row + j*16) * 128 + kk*32 + bp_kb));
            #pragma unroll
            for (int i = 0; i < 4; i++)
                #pragma unroll
                for (int j = 0; j < 4; j++)
                    mma_bf16(acc[i][j], af[i], bfr[j]);
        }
    }

    const int er = (lane >> 2);
    const int ec = (lane & 3) << 1;
    #pragma unroll
    for (int i = 0; i < 4; i++) {
        #pragma unroll
        for (int j = 0; j < 4; j++) {
            int col = bn + wn*32 + j*8 + ec;
            float bx = bias[col], by = bias[col + 1];
            float sc = (EPI == 4 && col < qcols) ? 0.125f : 1.0f;
            #pragma unroll
            for (int h = 0; h < 2; h++) {
                int row = bm + wm*64 + i*16 + er + h*8;
                float vx = acc[i][j][h*2 + 0] + bx;
                float vy = acc[i][j][h*2 + 1] + by;
                if (EPI == 1) {
                    const float2 rr = *(const float2*)(R + (size_t)row * N + col);
                    vx += rr.x; vy += rr.y;
                }
                if (EPI == 4) {
                    *(uint32_t*)(C2 + (size_t)row * N + col) = pack_bf16x2(vx * sc, vy * sc);
                } else {
                    *(float2*)(C + (size_t)row * N + col) = make_float2(vx, vy);
                }
            }
        }
    }
}

// ---------------- TF32 GEMM (FFN path) ----
// B = RAW fp32 weights (HW truncates to tf32 in the mma; no pre-round pass).
// EPI: 1 = bias + residual -> fp32, 3 = bias + gelu -> tf32-rounded fp32
template<int EPI>
__global__ void __launch_bounds__(256, 2)
gemm_tf32(const float* __restrict__ A, const float* __restrict__ B,
          const float* __restrict__ bias, const float* __restrict__ R,
          float* __restrict__ C, int M, int N, int K) {
    extern __shared__ char dyn_smem[];
    const int tid  = threadIdx.x;
    const int lane = tid & 31;
    const int wid  = tid >> 5;
    const int wm   = wid & 1;
    const int wn   = wid >> 1;
    const int bm = blockIdx.y * GBM;
    const int bn = blockIdx.x * GBN;

    uint32_t raw = smem_u32(dyn_smem);
    uint32_t sb  = (raw + 1023u) & ~1023u;

    const size_t ldb = (size_t)K * 4;
    const char* Abase = (const char*)(A + (size_t)bm * K);
    const char* Bbase = (const char*)(B + (size_t)bn * K);

    auto issue_stage = [&](int kt, int s) {
        uint32_t dst = sb + s * GSTAGE;
        const char* Ab = Abase + (size_t)kt * 128;   // 32 fp32 = 128B
        const char* Bb = Bbase + (size_t)kt * 128;
        #pragma unroll
        for (int p = 0; p < 4; p++) {
            int g   = (p << 8) + tid;
            int row = g >> 3;
            int seg = (g & 7) << 4;
            uint32_t off = SWZ(row * 128 + seg);
            CP_ASYNC16(dst + off,       Ab + (size_t)row * ldb + seg);
            CP_ASYNC16(dst + AST + off, Bb + (size_t)row * ldb + seg);
        }
        CP_COMMIT();
    };

    float acc[4][4][4];
    #pragma unroll
    for (int i = 0; i < 4; i++)
        #pragma unroll
        for (int j = 0; j < 4; j++)
            #pragma unroll
            for (int t = 0; t < 4; t++) acc[i][j][t] = 0.f;

    const int nk = K / 32;
    issue_stage(0, 0);
    issue_stage(1, 1);

    const int a_row  = wm * 64 + (lane & 7) + ((lane >> 3) & 1) * 8;
    const int a_colb = ((lane >> 4) & 1) << 4;
    const int b_row  = wn * 32 + (lane & 7) + ((lane >> 4) & 1) * 8;
    const int b_colb = ((lane >> 3) & 1) << 4;

    for (int kt = 0; kt < nk; kt++) {
        if (kt + 1 < nk) { CP_WAIT1(); } else { CP_WAIT0(); }
        __syncthreads();
        if (kt + 2 < nk) issue_stage(kt + 2, (kt + 2) % 3);

        uint32_t ab = sb + (kt % 3) * GSTAGE;
        uint32_t bb = ab + AST;
        #pragma unroll
        for (int kk = 0; kk < 4; kk++) {
            uint32_t af[4][4], bfr[4][2];
            #pragma unroll
            for (int i = 0; i < 4; i++)
                ldsm_x4(af[i][0], af[i][1], af[i][2], af[i][3],
                        ab + SWZ((a_row + i*16) * 128 + kk*32 + a_colb));
            #pragma unroll
            for (int j = 0; j < 2; j++)
                ldsm_x4(bfr[2*j][0], bfr[2*j][1], bfr[2*j+1][0], bfr[2*j+1][1],
                        bb + SWZ((b_row + j*16) * 128 + kk*32 + b_colb));
            #pragma unroll
            for (int i = 0; i < 4; i++)
                #pragma unroll
                for (int j = 0; j < 4; j++)
                    mma_tf32(acc[i][j], af[i], bfr[j]);
        }
    }

    const int er = (lane >> 2);
    const int ec = (lane & 3) << 1;
    #pragma unroll
    for (int i = 0; i < 4; i++) {
        #pragma unroll
        for (int j = 0; j < 4; j++) {
            int col = bn + wn*32 + j*8 + ec;
            float bx = bias[col], by = bias[col + 1];
            #pragma unroll
            for (int h = 0; h < 2; h++) {
                int row = bm + wm*64 + i*16 + er + h*8;
                float vx = acc[i][j][h*2 + 0] + bx;
                float vy = acc[i][j][h*2 + 1] + by;
                if (EPI == 1) {
                    const float2 rr = *(const float2*)(R + (size_t)row * N + col);
                    vx += rr.x; vy += rr.y;
                } else if (EPI == 3) {
                    vx = to_tf32(0.5f * vx * (1.0f + erff(vx * 0.70710678118654752f)));
                    vy = to_tf32(0.5f * vy * (1.0f + erff(vy * 0.70710678118654752f)));
                }
                *(float2*)(C + (size_t)row * N + col) = make_float2(vx, vy);
            }
        }
    }
}

// ---------------- HMMA flash attention (causal always per reference) ----
// 256 threads, 128-row q-tile (8 warps x 16 rows), 64-row kv-tiles.
// bf16 inputs (Q pre-scaled by 0.125); bf16 output (row stride EE).
__global__ void __launch_bounds__(256)
attn_mma(const __nv_bfloat16* __restrict__ Q, int ldq,
         const __nv_bfloat16* __restrict__ Kp, int ldk,
         const __nv_bfloat16* __restrict__ Vp, int ldv,
         __nv_bfloat16* __restrict__ O) {
    __shared__ __nv_bfloat16 Qs[128*64];
    __shared__ __nv_bfloat16 Ks[64*64];
    __shared__ __nv_bfloat16 Vt[64*64];   // [d][kv]

    const int b = blockIdx.y, qi = blockIdx.x;
    const int n = b >> 4, hh = b & 15;
    const int tid = threadIdx.x, lane = tid & 31, w = tid >> 5;   // w: 0..7
    const int qbase = qi * 128;
    const uint32_t qs = smem_u32(Qs), ks = smem_u32(Ks), vt = smem_u32(Vt);

    // Q tile: direct swizzled copy (already bf16, scaled). 128 rows x 8 uint4.
    for (int i = tid; i < 1024; i += 256) {
        int rr = i >> 3, sb8 = (i & 7) << 4;
        *(uint4*)((char*)Qs + SWZ(rr*128 + sb8)) =
            *(const uint4*)((const char*)(Q + (size_t)((qbase+rr)*NN + n) * ldq + hh*HD) + sb8);
    }

    const int r  = lane >> 2;
    const int cb = (lane & 3) << 1;

    float m0 = -1e30f, m1 = -1e30f, l0 = 0.f, l1 = 0.f;
    float oac[8][4];
    #pragma unroll
    for (int t = 0; t < 8; t++)
        #pragma unroll
        for (int e = 0; e < 4; e++) oac[t][e] = 0.f;

    const int jmax = 2*qi + 1;
    for (int j = 0; j <= jmax; j++) {
        __syncthreads();
        for (int i = tid; i < 512; i += 256) {
            int rr = i >> 3, sb8 = (i & 7) << 4;
            const char* kb = (const char*)(Kp + (size_t)((j*64+rr)*NN + n) * ldk + hh*HD);
            *(uint4*)((char*)Ks + SWZ(rr*128 + sb8)) = *(const uint4*)(kb + sb8);
            const char* vb = (const char*)(Vp + (size_t)((j*64+rr)*NN + n) * ldv + hh*HD);
            uint4 vv = *(const uint4*)(vb + sb8);
            const __nv_bfloat16* ve = (const __nv_bfloat16*)&vv;
            int c0 = (i & 7) << 3;
            #pragma unroll
            for (int e = 0; e < 8; e++)
                *(__nv_bfloat16*)((char*)Vt + SWZ((c0+e)*128 + rr*2)) = ve[e];
        }
        __syncthreads();

        uint32_t af[4][4];
        #pragma unroll
        for (int kk = 0; kk < 4; kk++)
            ldsm_x4(af[kk][0], af[kk][1], af[kk][2], af[kk][3],
                    qs + SWZ((w*16 + (lane & 15))*128 + kk*32 + ((lane >> 4) << 4)));

        float sac[8][4];
        #pragma unroll
        for (int t = 0; t < 8; t++) {
            sac[t][0] = sac[t][1] = sac[t][2] = sac[t][3] = 0.f;
            #pragma unroll
            for (int kk = 0; kk < 4; kk++) {
                uint32_t bfr[2];
                ldsm_x2(bfr[0], bfr[1],
                        ks + SWZ((t*8 + (lane & 7))*128 + kk*32 + (((lane >> 3) & 1) << 4)));
                mma_bf16(sac[t], af[kk], bfr);
            }
        }

        if (j >= 2*qi) {   // tiles overlapping/above the diagonal band of this q-tile
            int grow0 = qbase + w*16 + r;
            int grow1 = grow0 + 8;
            #pragma unroll
            for (int t = 0; t < 8; t++) {
                int gc = j*64 + t*8 + cb;
                if (gc     > grow0) sac[t][0] = -10000.0f;
                if (gc + 1 > grow0) sac[t][1] = -10000.0f;
                if (gc     > grow1) sac[t][2] = -10000.0f;
                if (gc + 1 > grow1) sac[t][3] = -10000.0f;
            }
        }

        float mx0 = -1e30f, mx1 = -1e30f;
        #pragma unroll
        for (int t = 0; t < 8; t++) {
            mx0 = fmaxf(mx0, fmaxf(sac[t][0], sac[t][1]));
            mx1 = fmaxf(mx1, fmaxf(sac[t][2], sac[t][3]));
        }
        mx0 = fmaxf(mx0, __shfl_xor_sync(0xffffffffu, mx0, 1));
        mx0 = fmaxf(mx0, __shfl_xor_sync(0xffffffffu, mx0, 2));
        mx1 = fmaxf(mx1, __shfl_xor_sync(0xffffffffu, mx1, 1));
        mx1 = fmaxf(mx1, __shfl_xor_sync(0xffffffffu, mx1, 2));
        float mn0 = fmaxf(m0, mx0), mn1 = fmaxf(m1, mx1);
        float al0 = __expf(m0 - mn0), al1 = __expf(m1 - mn1);
        float ls0 = 0.f, ls1 = 0.f;
        #pragma unroll
        for (int t = 0; t < 8; t++) {
            sac[t][0] = __expf(sac[t][0] - mn0);
            sac[t][1] = __expf(sac[t][1] - mn0);
            sac[t][2] = __expf(sac[t][2] - mn1);
            sac[t][3] = __expf(sac[t][3] - mn1);
            ls0 += sac[t][0] + sac[t][1];
            ls1 += sac[t][2] + sac[t][3];
        }
        ls0 += __shfl_xor_sync(0xffffffffu, ls0, 1);
        ls0 += __shfl_xor_sync(0xffffffffu, ls0, 2);
        ls1 += __shfl_xor_sync(0xffffffffu, ls1, 1);
        ls1 += __shfl_xor_sync(0xffffffffu, ls1, 2);
        l0 = l0 * al0 + ls0;  m0 = mn0;
        l1 = l1 * al1 + ls1;  m1 = mn1;
        #pragma unroll
        for (int t = 0; t < 8; t++) {
            oac[t][0] *= al0; oac[t][1] *= al0;
            oac[t][2] *= al1; oac[t][3] *= al1;
        }

        uint32_t pf[4][4];
        #pragma unroll
        for (int kt = 0; kt < 4; kt++) {
            pf[kt][0] = pack_bf16x2(sac[2*kt][0],   sac[2*kt][1]);
            pf[kt][1] = pack_bf16x2(sac[2*kt][2],   sac[2*kt][3]);
            pf[kt][2] = pack_bf16x2(sac[2*kt+1][0], sac[2*kt+1][1]);
            pf[kt][3] = pack_bf16x2(sac[2*kt+1][2], sac[2*kt+1][3]);
        }

        #pragma unroll
        for (int td = 0; td < 8; td++) {
            #pragma unroll
            for (int kt = 0; kt < 4; kt++) {
                uint32_t bfr[2];
                ldsm_x2(bfr[0], bfr[1],
                        vt + SWZ((td*8 + (lane & 7))*128 + kt*32 + (((lane >> 3) & 1) << 4)));
                mma_bf16(oac[td], pf[kt], bfr);
            }
        }
    }

    float inv0 = 1.0f / l0, inv1 = 1.0f / l1;
    int row0 = qbase + w*16 + r;
    int row1 = row0 + 8;
    #pragma unroll
    for (int td = 0; td < 8; td++) {
        int col = td*8 + cb;
        *(uint32_t*)(O + (size_t)(row0*NN + n) * EE + hh*HD + col) =
            pack_bf16x2(oac[td][0]*inv0, oac[td][1]*inv0);
        *(uint32_t*)(O + (size_t)(row1*NN + n) * EE + hh*HD + col) =
            pack_bf16x2(oac[td][2]*inv1, oac[td][3]*inv1);
    }
}

// ---------------- orchestration ----------------
static void conv1(const float* X, __nv_bfloat16* Y, size_t elems) {
    int t4 = (int)(elems / 4);
    conv1_kernel<<<(t4 + 255) / 256, 256>>>(X, Y, t4);
}
static void conv_batch(const float* s0, const float* s1, const float* s2,
                       __nv_bfloat16* Y, int per_elems, int nseg) {
    int p4 = per_elems / 4;
    dim3 grid((p4 + 255) / 256, nseg);
    conv3_kernel<<<grid, 256>>>(s0, s1, s2, Y, p4);
}
static void run_gemm(int epi, const __nv_bfloat16* A, const __nv_bfloat16* B,
                     const float* bias, const float* R, float* C, __nv_bfloat16* C2,
                     int qcols, int M_, int N_, int K_) {
    dim3 grid(N_ / GBN, M_ / GBM);
    if (epi == 1) gemm_mma<1><<<grid, 256, GSMEM>>>(A, B, bias, R, C, C2, qcols, M_, N_, K_);
    else          gemm_mma<4><<<grid, 256, GSMEM>>>(A, B, bias, R, C, C2, qcols, M_, N_, K_);
}
static void run_gemm_tf(int epi, const float* A, const float* B,
                        const float* bias, const float* R, float* C,
                        int M_, int N_, int K_) {
    dim3 grid(N_ / GBN, M_ / GBM);
    if (epi == 1) gemm_tf32<1><<<grid, 256, GSMEM>>>(A, B, bias, R, C, M_, N_, K_);
    else          gemm_tf32<3><<<grid, 256, GSMEM>>>(A, B, bias, R, C, M_, N_, K_);
}

extern "C" void kernel_launch(void* const* d_in, const int* in_sizes, int n_in,
                              void* d_out, int out_size) {
    const float* x    = (const float*)d_in[0];
    const float* enc  = (const float*)d_in[1];
    const float* wq_s = (const float*)d_in[2];
    const float* bq_s = (const float*)d_in[3];
    const float* wk_s = (const float*)d_in[4];
    const float* bk_s = (const float*)d_in[5];
    const float* wv_s = (const float*)d_in[6];
    const float* bv_s = (const float*)d_in[7];
    const float* wo_s = (const float*)d_in[8];
    const float* bo_s = (const float*)d_in[9];
    const float* wq_c = (const float*)d_in[10];
    const float* bq_c = (const float*)d_in[11];
    const float* wk_c = (const float*)d_in[12];
    const float* bk_c = (const float*)d_in[13];
    const float* wv_c = (const float*)d_in[14];
    const float* bv_c = (const float*)d_in[15];
    const float* wo_c = (const float*)d_in[16];
    const float* bo_c = (const float*)d_in[17];
    const float* ln1_g = (const float*)d_in[18];
    const float* ln1_b = (const float*)d_in[19];
    const float* ln2_g = (const float*)d_in[20];
    const float* ln2_b = (const float*)d_in[21];
    const float* ln3_g = (const float*)d_in[22];
    const float* ln3_b = (const float*)d_in[23];
    const float* fc1_w = (const float*)d_in[24];
    const float* fc1_b = (const float*)d_in[25];
    const float* fc2_w = (const float*)d_in[26];
    const float* fc2_b = (const float*)d_in[27];
    float* out = (float*)d_out;

    float *p_tf, *p_ff, *p_bcat;
    __nv_bfloat16 *p_a3, *p_w3, *p_qkv, *p_qc;
    cudaGetSymbolAddress((void**)&p_tf,   g_tf);
    cudaGetSymbolAddress((void**)&p_ff,   g_ff);
    cudaGetSymbolAddress((void**)&p_a3,   g_a3);
    cudaGetSymbolAddress((void**)&p_qkv,  g_qkv);
    cudaGetSymbolAddress((void**)&p_qc,   g_qc);
    cudaGetSymbolAddress((void**)&p_w3,   g_w3);
    cudaGetSymbolAddress((void**)&p_bcat, g_bcat);

    cudaFuncSetAttribute(gemm_mma<1>,  cudaFuncAttributeMaxDynamicSharedMemorySize, GSMEM);
    cudaFuncSetAttribute(gemm_mma<4>,  cudaFuncAttributeMaxDynamicSharedMemorySize, GSMEM);
    cudaFuncSetAttribute(gemm_tf32<1>, cudaFuncAttributeMaxDynamicSharedMemorySize, GSMEM);
    cudaFuncSetAttribute(gemm_tf32<3>, cudaFuncAttributeMaxDynamicSharedMemorySize, GSMEM);

    dim3 agrid(LL / 128, NN * HH);   // 8 x 64
    const size_t W1 = (size_t)EE * EE;

    // ---- block 1: self-attention (fused QKV -> bf16 with q pre-scaled) ----
    ln_bf16_kernel<<<MM, 256>>>(x, ln1_g, ln1_b, p_a3);
    conv_batch(wq_s, wk_s, wv_s, p_w3, (int)W1, 3);
    biascat_kernel<<<3, 1024>>>(bq_s, bk_s, bv_s, p_bcat);
    run_gemm(4, p_a3, p_w3, p_bcat, nullptr, nullptr, p_qkv, EE, MM, 3*EE, EE);
    attn_mma<<<agrid, 256>>>(p_qkv, 3*EE, p_qkv + EE, 3*EE, p_qkv + 2*EE, 3*EE, p_a3);
    conv1(wo_s, p_w3, W1);
    run_gemm(1, p_a3, p_w3, bo_s, x, out, nullptr, 0, MM, EE, EE);

    // ---- block 2: cross-attention (reference applies causal mask here too) ----
    ln_bf16_kernel<<<MM, 256>>>(out, ln2_g, ln2_b, p_a3);
    conv1(wq_c, p_w3, W1);
    run_gemm(4, p_a3, p_w3, bq_c, nullptr, nullptr, p_qc, EE, MM, EE, EE);
    conv1(enc, p_a3, (size_t)MM * EE);
    conv_batch(wk_c, wv_c, nullptr, p_w3, (int)W1, 2);
    biascat_kernel<<<2, 1024>>>(bk_c, bv_c, nullptr, p_bcat);
    run_gemm(4, p_a3, p_w3, p_bcat, nullptr, nullptr, p_qkv, 0, MM, 2*EE, EE);
    attn_mma<<<agrid, 256>>>(p_qc, EE, p_qkv, 2*EE, p_qkv + EE, 2*EE, p_a3);
    conv1(wo_c, p_w3, W1);
    run_gemm(1, p_a3, p_w3, bo_c, out, out, nullptr, 0, MM, EE, EE);

    // ---- block 3: FFN (1-term TF32; raw fp32 weights, HW truncation) ----
    ln_tf32_kernel<<<MM, 256>>>(out, ln3_g, ln3_b, p_tf);
    run_gemm_tf(3, p_tf, fc1_w, fc1_b, nullptr, p_ff, MM, FF, EE);
    run_gemm_tf(1, p_ff, fc2_w, fc2_b, out, out, MM, EE, FF);
}